// round 3
// baseline (speedup 1.0000x reference)
#include <cuda_runtime.h>
#include <cstdint>
#include <math.h>

// Problem constants
#define BB 64
#define TT 4096
#define DD 256
#define HH 341
#define BT (BB*TT)
#define NEGV (-1e9f)

// Scratch (static __device__ allowed; no cudaMalloc)
__device__ float g_scores[BT];
__device__ float g_tv[BB];

// ---------------------------------------------------------------------------
// Kernel A: fused  emb*attn -> LayerNorm -> GEMM(256x341) -> GELU -> dot(W2)
// One block = 64 consecutive tokens. 256 threads.
// smem: xsT[256][68] (transposed normalized tile) + ws[256][32] (W1 chunk)
// ---------------------------------------------------------------------------
#define XP 68
#define SMEM_A ((256*XP + 256*32)*4)

__global__ __launch_bounds__(256, 2)
void kernelA(const float* __restrict__ emb, const float* __restrict__ attn,
             const float* __restrict__ gamma, const float* __restrict__ beta,
             const float* __restrict__ W1, const float* __restrict__ b1,
             const float* __restrict__ W2, const float* __restrict__ b2)
{
    extern __shared__ float smA[];
    float* xsT = smA;                 // [256][XP]
    float* ws  = smA + 256*XP;        // [256][32]
    __shared__ float attn_sm[64], mu_sm[64], rstd_sm[64], scores_sm[64];

    const int tid = threadIdx.x;
    const int base64 = blockIdx.x * 64;

    if (tid < 64) { attn_sm[tid] = attn[base64 + tid]; scores_sm[tid] = 0.f; }
    __syncthreads();

    // load emb tile (token-major) into transposed smem, multiply by attn
    {
        const float4* emb4 = (const float4*)(emb + (size_t)base64 * DD);
        for (int v = tid; v < 64*64; v += 256) {
            int m = v & 63;              // token within tile
            int q = v >> 6;              // float4 index within row (0..63)
            float4 e = emb4[m*64 + q];
            float a = attn_sm[m];
            int d0 = q * 4;
            xsT[(d0+0)*XP + m] = e.x * a;
            xsT[(d0+1)*XP + m] = e.y * a;
            xsT[(d0+2)*XP + m] = e.z * a;
            xsT[(d0+3)*XP + m] = e.w * a;
        }
    }
    __syncthreads();

    // LayerNorm stats: 4 threads per token
    {
        int m = tid >> 2, q = tid & 3;
        float s = 0.f, s2 = 0.f;
        for (int i = 0; i < 64; i++) {
            float v = xsT[(q*64 + i)*XP + m];
            s += v; s2 += v*v;
        }
        s  += __shfl_xor_sync(0xffffffffu, s, 1);
        s  += __shfl_xor_sync(0xffffffffu, s, 2);
        s2 += __shfl_xor_sync(0xffffffffu, s2, 1);
        s2 += __shfl_xor_sync(0xffffffffu, s2, 2);
        if (q == 0) {
            float muv = s * (1.f/256.f);
            float var = s2 * (1.f/256.f) - muv*muv;
            mu_sm[m] = muv;
            rstd_sm[m] = rsqrtf(var + 1e-5f);
        }
    }
    __syncthreads();

    // normalize in place (+ gamma/beta)
    for (int v = tid; v < 64*256; v += 256) {
        int m = v & 63;
        int d = v >> 6;
        float val = xsT[d*XP + m];
        xsT[d*XP + m] = (val - mu_sm[m]) * rstd_sm[m] * gamma[d] + beta[d];
    }

    const int ty = tid >> 4;        // 0..15
    const int tx = tid & 15;        // 0..15
    const int m0 = ty << 2;         // 4 rows
    const int n0 = tx << 1;         // 2 cols

    const int nchunks = (HH + 31) / 32;   // 11
    for (int c = 0; c < nchunks; c++) {
        const int h0 = c * 32;
        __syncthreads();
        // load W1 chunk [256][32]
        for (int v = tid; v < 256*32; v += 256) {
            int d = v >> 5, j = v & 31;
            int h = h0 + j;
            ws[d*32 + j] = (h < HH) ? W1[d*HH + h] : 0.f;
        }
        __syncthreads();

        float acc00=0.f,acc01=0.f,acc10=0.f,acc11=0.f,
              acc20=0.f,acc21=0.f,acc30=0.f,acc31=0.f;
        const float* xp = xsT + m0;
        const float* wp = ws + n0;
#pragma unroll 8
        for (int k = 0; k < 256; k++) {
            float4 xv = *(const float4*)(xp + k*XP);
            float2 wv = *(const float2*)(wp + k*32);
            acc00 = fmaf(xv.x, wv.x, acc00);
            acc01 = fmaf(xv.x, wv.y, acc01);
            acc10 = fmaf(xv.y, wv.x, acc10);
            acc11 = fmaf(xv.y, wv.y, acc11);
            acc20 = fmaf(xv.z, wv.x, acc20);
            acc21 = fmaf(xv.z, wv.y, acc21);
            acc30 = fmaf(xv.w, wv.x, acc30);
            acc31 = fmaf(xv.w, wv.y, acc31);
        }

        // epilogue: bias + exact gelu + * W2, partial per row
        float part0=0.f, part1=0.f, part2=0.f, part3=0.f;
        {
            int h = h0 + n0;
            if (h < HH) {
                float b1v = b1[h], w2v = W2[h];
                float v0 = acc00 + b1v, v1 = acc10 + b1v, v2 = acc20 + b1v, v3 = acc30 + b1v;
                part0 += 0.5f*v0*(1.f + erff(v0*0.70710678118654752f)) * w2v;
                part1 += 0.5f*v1*(1.f + erff(v1*0.70710678118654752f)) * w2v;
                part2 += 0.5f*v2*(1.f + erff(v2*0.70710678118654752f)) * w2v;
                part3 += 0.5f*v3*(1.f + erff(v3*0.70710678118654752f)) * w2v;
            }
            h = h0 + n0 + 1;
            if (h < HH) {
                float b1v = b1[h], w2v = W2[h];
                float v0 = acc01 + b1v, v1 = acc11 + b1v, v2 = acc21 + b1v, v3 = acc31 + b1v;
                part0 += 0.5f*v0*(1.f + erff(v0*0.70710678118654752f)) * w2v;
                part1 += 0.5f*v1*(1.f + erff(v1*0.70710678118654752f)) * w2v;
                part2 += 0.5f*v2*(1.f + erff(v2*0.70710678118654752f)) * w2v;
                part3 += 0.5f*v3*(1.f + erff(v3*0.70710678118654752f)) * w2v;
            }
        }
        for (int o = 8; o >= 1; o >>= 1) {
            part0 += __shfl_xor_sync(0xffffffffu, part0, o);
            part1 += __shfl_xor_sync(0xffffffffu, part1, o);
            part2 += __shfl_xor_sync(0xffffffffu, part2, o);
            part3 += __shfl_xor_sync(0xffffffffu, part3, o);
        }
        if (tx == 0) {
            scores_sm[m0+0] += part0;
            scores_sm[m0+1] += part1;
            scores_sm[m0+2] += part2;
            scores_sm[m0+3] += part3;
        }
    }
    __syncthreads();
    if (tid < 64) {
        float sc = scores_sm[tid] + b2[0];
        if (attn_sm[tid] == 0.f) sc = NEGV;
        g_scores[base64 + tid] = sc;
    }
}

// ---------------------------------------------------------------------------
// Threefry-2x32-20, JAX "partitionable" scheme (default in modern JAX):
//   per-element i: bind(k1, k2, ctr_hi=0, ctr_lo=i); 32-bit draw = out0 ^ out1
// ---------------------------------------------------------------------------
__device__ __forceinline__ uint32_t rotl32(uint32_t x, int r) { return (x << r) | (x >> (32 - r)); }
__device__ __forceinline__ void tf_r4(uint32_t& x0, uint32_t& x1, int a, int b, int c, int d) {
    x0 += x1; x1 = rotl32(x1, a); x1 ^= x0;
    x0 += x1; x1 = rotl32(x1, b); x1 ^= x0;
    x0 += x1; x1 = rotl32(x1, c); x1 ^= x0;
    x0 += x1; x1 = rotl32(x1, d); x1 ^= x0;
}
__device__ __forceinline__ uint32_t jax_bits(uint32_t i) {
    const uint32_t k0 = 0u, k1 = 42u;
    const uint32_t k2 = k0 ^ k1 ^ 0x1BD11BDAu;
    uint32_t x0 = 0u + k0;   // counter hi word = 0 (indices < 2^32)
    uint32_t x1 = i  + k1;   // counter lo word = linear element index
    tf_r4(x0, x1, 13, 15, 26, 6);   x0 += k1; x1 += k2 + 1u;
    tf_r4(x0, x1, 17, 29, 16, 24);  x0 += k2; x1 += k0 + 2u;
    tf_r4(x0, x1, 13, 15, 26, 6);   x0 += k0; x1 += k1 + 3u;
    tf_r4(x0, x1, 17, 29, 16, 24);  x0 += k1; x1 += k2 + 4u;
    tf_r4(x0, x1, 13, 15, 26, 6);   x0 += k2; x1 += k0 + 5u;
    return x0 ^ x1;          // 32-bit draw in the partitionable path
}

// descending bitonic sort of 4096 floats in smem
__device__ void bitonic_desc(float* a, int tid, int nthr) {
    for (int k = 2; k <= 4096; k <<= 1) {
        for (int j = k >> 1; j > 0; j >>= 1) {
            __syncthreads();
            for (int i = tid; i < 4096; i += nthr) {
                int ixj = i ^ j;
                if (ixj > i) {
                    float x = a[i], y = a[ixj];
                    bool up = ((i & k) == 0);
                    if (up ? (x < y) : (x > y)) { a[i] = y; a[ixj] = x; }
                }
            }
        }
    }
    __syncthreads();
}

// ---------------------------------------------------------------------------
// Kernel B: per-row entmax1.5 (sort-based) + gumbel top-k mask + TV row term
// grid = 64 rows, 1024 threads
// ---------------------------------------------------------------------------
#define SMEM_B (5*4096*4)

__global__ __launch_bounds__(1024, 1)
void kernelB(const float* __restrict__ attn, float* __restrict__ out)
{
    extern __shared__ float sm[];
    float* s_scores = sm;            // 4096 (masked scores)
    float* s_attn   = sm + 4096;
    float* s_a      = sm + 8192;     // sort workspace
    float* s_cum    = sm + 12288;    // cumsum / later pert
    float* s_cum2   = sm + 16384;    // cumsum of squares
    __shared__ float red[32], red2[32];
    __shared__ float sh_mx, sh_teff, sh_tau;
    __shared__ int sh_support;

    const int row = blockIdx.x;
    const int tid = threadIdx.x;
    const int lane = tid & 31, wid = tid >> 5;

    // load + t_eff + row max
    float tf_ = 0.f, mx = -3.402823466e38f;
    for (int t = tid; t < TT; t += 1024) {
        float s = g_scores[row*TT + t];
        float a = attn[row*TT + t];
        s_scores[t] = s; s_attn[t] = a;
        tf_ += a; mx = fmaxf(mx, s);
    }
    for (int o = 16; o; o >>= 1) {
        tf_ += __shfl_xor_sync(0xffffffffu, tf_, o);
        mx = fmaxf(mx, __shfl_xor_sync(0xffffffffu, mx, o));
    }
    if (lane == 0) { red[wid] = tf_; red2[wid] = mx; }
    __syncthreads();
    if (tid == 0) {
        float a = 0.f, b = -3.402823466e38f;
        for (int w = 0; w < 32; w++) { a += red[w]; b = fmaxf(b, red2[w]); }
        sh_teff = a; sh_mx = b;
        sh_support = 0;
    }
    __syncthreads();
    mx = sh_mx;

    // x = (scores - max)/2; sort descending
    for (int t = tid; t < TT; t += 1024) s_a[t] = (s_scores[t] - mx) * 0.5f;
    bitonic_desc(s_a, tid, 1024);

    // block scans of sorted values and their squares (blocked: 4 per thread)
    const int p0 = tid * 4;
    float v0 = s_a[p0+0], v1 = s_a[p0+1], v2 = s_a[p0+2], v3 = s_a[p0+3];
    float c0 = v0, c1 = c0 + v1, c2 = c1 + v2, c3 = c2 + v3;
    float d0 = v0*v0, d1 = d0 + v1*v1, d2 = d1 + v2*v2, d3 = d2 + v3*v3;
    float s = c3, s2 = d3;
    const float tot = c3, tot2 = d3;
    for (int o = 1; o < 32; o <<= 1) {
        float n  = __shfl_up_sync(0xffffffffu, s, o);
        float n2 = __shfl_up_sync(0xffffffffu, s2, o);
        if (lane >= o) { s += n; s2 += n2; }
    }
    if (lane == 31) { red[wid] = s; red2[wid] = s2; }
    __syncthreads();
    if (wid == 0) {
        float w = red[lane], w2 = red2[lane];
        for (int o = 1; o < 32; o <<= 1) {
            float n  = __shfl_up_sync(0xffffffffu, w, o);
            float n2 = __shfl_up_sync(0xffffffffu, w2, o);
            if (lane >= o) { w += n; w2 += n2; }
        }
        red[lane] = w; red2[lane] = w2;
    }
    __syncthreads();
    float base  = (wid ? red[wid-1]  : 0.f) + (s  - tot);
    float base2 = (wid ? red2[wid-1] : 0.f) + (s2 - tot2);
    s_cum[p0+0] = base + c0;  s_cum[p0+1] = base + c1;
    s_cum[p0+2] = base + c2;  s_cum[p0+3] = base + c3;
    s_cum2[p0+0] = base2 + d0; s_cum2[p0+1] = base2 + d1;
    s_cum2[p0+2] = base2 + d2; s_cum2[p0+3] = base2 + d3;
    __syncthreads();

    // support count
    int cnt = 0;
#pragma unroll
    for (int j = 0; j < 4; j++) {
        int p = p0 + j;
        float rho = (float)(p + 1);
        float mean = s_cum[p] / rho;
        float msq  = s_cum2[p] / rho;
        float ssv  = rho * (msq - mean*mean);
        float delta = (1.f - ssv) / rho;
        float tau = mean - sqrtf(fmaxf(delta, 0.f));
        cnt += (tau <= s_a[p]) ? 1 : 0;
    }
    for (int o = 16; o; o >>= 1) cnt += __shfl_xor_sync(0xffffffffu, cnt, o);
    if (lane == 0) atomicAdd(&sh_support, cnt);
    __syncthreads();
    if (tid == 0) {
        int p = sh_support - 1;
        float rho = (float)(p + 1);
        float mean = s_cum[p] / rho;
        float msq  = s_cum2[p] / rho;
        float ssv  = rho * (msq - mean*mean);
        float delta = (1.f - ssv) / rho;
        sh_tau = mean - sqrtf(fmaxf(delta, 0.f));
    }
    __syncthreads();
    const float taustar = sh_tau;

    // z output
    for (int t = tid; t < TT; t += 1024) {
        float x = (s_scores[t] - mx) * 0.5f;
        float dd = fmaxf(x - taustar, 0.f);
        out[row*TT + t] = dd*dd*s_attn[t];
    }
    __syncthreads();   // s_cum/s_a safe to reuse

    // gumbel-perturbed scores (NaN-safe: ref's jnp.sort pushes NaN to the
    // bottom of the descending order, so map NaN -> -inf for the sort copy)
    for (int t = tid; t < TT; t += 1024) {
        uint32_t lin = (uint32_t)(row*TT + t);
        uint32_t bits = jax_bits(lin);
        float u = __uint_as_float((bits >> 9) | 0x3f800000u) - 1.0f;
        u = fmaxf(u, 0.f);
        float gum = -logf(-logf(u + 1e-6f) + 1e-6f);
        float pert = s_scores[t] * s_attn[t] + gum;
        s_cum[t] = pert;                       // raw pert (NaN>=thr is false, matches ref h=0)
        s_a[t] = (pert != pert) ? __int_as_float(0xff800000) : pert;
    }
    bitonic_desc(s_a, tid, 1024);

    const float teff = sh_teff;
    float kf = rintf(0.3f * teff);
    kf = fminf(fmaxf(kf, 1.f), fmaxf(teff, 1.f));
    const int ki = (int)kf;
    const float thr = s_a[ki - 1];

    // g output + TV accumulation
    float num = 0.f, den = 0.f;
    for (int t = tid; t < TT; t += 1024) {
        float a0 = s_attn[t];
        float gv = (s_cum[t] >= thr) ? a0 : 0.f;
        out[BT + row*TT + t] = gv;
        if (t < TT - 1) {
            float a1 = s_attn[t+1];
            float gv1 = (s_cum[t+1] >= thr) ? a1 : 0.f;
            float valid = a0 * a1;
            num += fabsf(gv1 - gv) * valid;
            den += valid;
        }
    }
    for (int o = 16; o; o >>= 1) {
        num += __shfl_xor_sync(0xffffffffu, num, o);
        den += __shfl_xor_sync(0xffffffffu, den, o);
    }
    if (lane == 0) { red[wid] = num; red2[wid] = den; }
    __syncthreads();
    if (tid == 0) {
        float a = 0.f, b = 0.f;
        for (int w = 0; w < 32; w++) { a += red[w]; b += red2[w]; }
        g_tv[row] = a / fmaxf(b, 1.f);
    }
}

// ---------------------------------------------------------------------------
// Kernel C: reg = 0.1 * mean(tv)
// ---------------------------------------------------------------------------
__global__ void kernelC(float* __restrict__ out)
{
    __shared__ float r[64];
    r[threadIdx.x] = g_tv[threadIdx.x];
    __syncthreads();
    if (threadIdx.x == 0) {
        float s = 0.f;
        for (int i = 0; i < 64; i++) s += r[i];
        out[2*BT] = 0.1f * (s / 64.f);
    }
}

extern "C" void kernel_launch(void* const* d_in, const int* in_sizes, int n_in,
                              void* d_out, int out_size)
{
    const float* emb   = (const float*)d_in[0];
    const float* attn  = (const float*)d_in[1];
    const float* gamma = (const float*)d_in[2];
    const float* beta  = (const float*)d_in[3];
    const float* W1    = (const float*)d_in[4];
    const float* b1    = (const float*)d_in[5];
    const float* W2    = (const float*)d_in[6];
    const float* b2    = (const float*)d_in[7];
    float* out = (float*)d_out;

    cudaFuncSetAttribute(kernelA, cudaFuncAttributeMaxDynamicSharedMemorySize, SMEM_A);
    cudaFuncSetAttribute(kernelB, cudaFuncAttributeMaxDynamicSharedMemorySize, SMEM_B);

    kernelA<<<BT/64, 256, SMEM_A>>>(emb, attn, gamma, beta, W1, b1, W2, b2);
    kernelB<<<BB, 1024, SMEM_B>>>(attn, out);
    kernelC<<<1, 64>>>(out);
}

// round 4
// speedup vs baseline: 1.0044x; 1.0044x over previous
#include <cuda_runtime.h>
#include <cstdint>
#include <math.h>

// Problem constants
#define BB 64
#define TT 4096
#define DD 256
#define HH 341
#define BT (BB*TT)
#define NEGV (-1e9f)

// Scratch (static __device__ allowed; no cudaMalloc)
__device__ float g_scores[BT];
__device__ float g_tv[BB];

// ---------------------------------------------------------------------------
// Kernel A: fused  emb*attn -> LayerNorm -> GEMM(256x341) -> GELU -> dot(W2)
// One block = 64 consecutive tokens, 256 threads.
// Register tile 4m x 4n, W1 chunks of 64 cols split into two k-halves of 128
// (smem: xsT[256][68] = 69.6KB + ws[128][64] = 32KB -> 2 blocks/SM).
// ---------------------------------------------------------------------------
#define XP 68
#define SMEM_A ((256*XP + 128*64)*4)

__global__ __launch_bounds__(256, 2)
void kernelA(const float* __restrict__ emb, const float* __restrict__ attn,
             const float* __restrict__ gamma, const float* __restrict__ beta,
             const float* __restrict__ W1, const float* __restrict__ b1,
             const float* __restrict__ W2, const float* __restrict__ b2)
{
    extern __shared__ float smA[];
    float* xsT = smA;                 // [256][XP]
    float* ws  = smA + 256*XP;        // [128][64]
    __shared__ float attn_sm[64], mu_sm[64], rstd_sm[64], scores_sm[64];

    const int tid = threadIdx.x;
    const int base64 = blockIdx.x * 64;

    if (tid < 64) { attn_sm[tid] = attn[base64 + tid]; scores_sm[tid] = 0.f; }
    __syncthreads();

    // load emb tile (token-major) into transposed smem, multiply by attn
    {
        const float4* emb4 = (const float4*)(emb + (size_t)base64 * DD);
        for (int v = tid; v < 64*64; v += 256) {
            int m = v & 63;              // token within tile
            int q = v >> 6;              // float4 index within row (0..63)
            float4 e = emb4[m*64 + q];
            float a = attn_sm[m];
            int d0 = q * 4;
            xsT[(d0+0)*XP + m] = e.x * a;
            xsT[(d0+1)*XP + m] = e.y * a;
            xsT[(d0+2)*XP + m] = e.z * a;
            xsT[(d0+3)*XP + m] = e.w * a;
        }
    }
    __syncthreads();

    // LayerNorm stats: 4 threads per token
    {
        int m = tid >> 2, q = tid & 3;
        float s = 0.f, s2 = 0.f;
        for (int i = 0; i < 64; i++) {
            float v = xsT[(q*64 + i)*XP + m];
            s += v; s2 += v*v;
        }
        s  += __shfl_xor_sync(0xffffffffu, s, 1);
        s  += __shfl_xor_sync(0xffffffffu, s, 2);
        s2 += __shfl_xor_sync(0xffffffffu, s2, 1);
        s2 += __shfl_xor_sync(0xffffffffu, s2, 2);
        if (q == 0) {
            float muv = s * (1.f/256.f);
            float var = s2 * (1.f/256.f) - muv*muv;
            mu_sm[m] = muv;
            rstd_sm[m] = rsqrtf(var + 1e-5f);
        }
    }
    __syncthreads();

    // normalize in place (+ gamma/beta)
    for (int v = tid; v < 64*256; v += 256) {
        int m = v & 63;
        int d = v >> 6;
        float val = xsT[d*XP + m];
        xsT[d*XP + m] = (val - mu_sm[m]) * rstd_sm[m] * gamma[d] + beta[d];
    }

    const int ty = tid >> 4;        // 0..15 -> 4 m-rows each
    const int tx = tid & 15;        // 0..15 -> 4 n-cols each
    const int m0 = ty << 2;
    const int n0 = tx << 2;

    const int nchunks = 6;          // 6*64 = 384 >= 341
    for (int c = 0; c < nchunks; c++) {
        const int h0 = c * 64;

        float acc[4][4];
#pragma unroll
        for (int i = 0; i < 4; i++)
#pragma unroll
            for (int j = 0; j < 4; j++) acc[i][j] = 0.f;

        for (int kb = 0; kb < 2; kb++) {
            __syncthreads();
            // load W1 half-chunk [128][64]
            for (int v = tid; v < 128*64; v += 256) {
                int d = v >> 6, j = v & 63;
                int h = h0 + j;
                ws[v] = (h < HH) ? W1[(kb*128 + d)*HH + h] : 0.f;
            }
            __syncthreads();

            const float* xp = xsT + kb*128*XP + m0;
            const float* wp = ws + n0;
#pragma unroll 8
            for (int k = 0; k < 128; k++) {
                float4 xv = *(const float4*)(xp + k*XP);
                float4 wv = *(const float4*)(wp + k*64);
                acc[0][0] = fmaf(xv.x, wv.x, acc[0][0]);
                acc[0][1] = fmaf(xv.x, wv.y, acc[0][1]);
                acc[0][2] = fmaf(xv.x, wv.z, acc[0][2]);
                acc[0][3] = fmaf(xv.x, wv.w, acc[0][3]);
                acc[1][0] = fmaf(xv.y, wv.x, acc[1][0]);
                acc[1][1] = fmaf(xv.y, wv.y, acc[1][1]);
                acc[1][2] = fmaf(xv.y, wv.z, acc[1][2]);
                acc[1][3] = fmaf(xv.y, wv.w, acc[1][3]);
                acc[2][0] = fmaf(xv.z, wv.x, acc[2][0]);
                acc[2][1] = fmaf(xv.z, wv.y, acc[2][1]);
                acc[2][2] = fmaf(xv.z, wv.z, acc[2][2]);
                acc[2][3] = fmaf(xv.z, wv.w, acc[2][3]);
                acc[3][0] = fmaf(xv.w, wv.x, acc[3][0]);
                acc[3][1] = fmaf(xv.w, wv.y, acc[3][1]);
                acc[3][2] = fmaf(xv.w, wv.z, acc[3][2]);
                acc[3][3] = fmaf(xv.w, wv.w, acc[3][3]);
            }
        }

        // epilogue: bias + exact gelu + * W2, partial per row
        float part[4] = {0.f, 0.f, 0.f, 0.f};
#pragma unroll
        for (int j = 0; j < 4; j++) {
            int h = h0 + n0 + j;
            if (h < HH) {
                float b1v = b1[h], w2v = W2[h];
#pragma unroll
                for (int i = 0; i < 4; i++) {
                    float v = acc[i][j] + b1v;
                    part[i] += 0.5f*v*(1.f + erff(v*0.70710678118654752f)) * w2v;
                }
            }
        }
#pragma unroll
        for (int o = 8; o >= 1; o >>= 1) {
            part[0] += __shfl_xor_sync(0xffffffffu, part[0], o);
            part[1] += __shfl_xor_sync(0xffffffffu, part[1], o);
            part[2] += __shfl_xor_sync(0xffffffffu, part[2], o);
            part[3] += __shfl_xor_sync(0xffffffffu, part[3], o);
        }
        if (tx == 0) {
            scores_sm[m0+0] += part[0];
            scores_sm[m0+1] += part[1];
            scores_sm[m0+2] += part[2];
            scores_sm[m0+3] += part[3];
        }
    }
    __syncthreads();
    if (tid < 64) {
        float sc = scores_sm[tid] + b2[0];
        if (attn_sm[tid] == 0.f) sc = NEGV;
        g_scores[base64 + tid] = sc;
    }
}

// ---------------------------------------------------------------------------
// Threefry-2x32-20, JAX "partitionable" scheme (default in modern JAX):
//   per-element i: bind(k1, k2, ctr_hi=0, ctr_lo=i); 32-bit draw = out0 ^ out1
// ---------------------------------------------------------------------------
__device__ __forceinline__ uint32_t rotl32(uint32_t x, int r) { return (x << r) | (x >> (32 - r)); }
__device__ __forceinline__ void tf_r4(uint32_t& x0, uint32_t& x1, int a, int b, int c, int d) {
    x0 += x1; x1 = rotl32(x1, a); x1 ^= x0;
    x0 += x1; x1 = rotl32(x1, b); x1 ^= x0;
    x0 += x1; x1 = rotl32(x1, c); x1 ^= x0;
    x0 += x1; x1 = rotl32(x1, d); x1 ^= x0;
}
__device__ __forceinline__ uint32_t jax_bits(uint32_t i) {
    const uint32_t k0 = 0u, k1 = 42u;
    const uint32_t k2 = k0 ^ k1 ^ 0x1BD11BDAu;
    uint32_t x0 = 0u + k0;   // counter hi word = 0 (indices < 2^32)
    uint32_t x1 = i  + k1;   // counter lo word = linear element index
    tf_r4(x0, x1, 13, 15, 26, 6);   x0 += k1; x1 += k2 + 1u;
    tf_r4(x0, x1, 17, 29, 16, 24);  x0 += k2; x1 += k0 + 2u;
    tf_r4(x0, x1, 13, 15, 26, 6);   x0 += k0; x1 += k1 + 3u;
    tf_r4(x0, x1, 17, 29, 16, 24);  x0 += k1; x1 += k2 + 4u;
    tf_r4(x0, x1, 13, 15, 26, 6);   x0 += k2; x1 += k0 + 5u;
    return x0 ^ x1;          // 32-bit draw in the partitionable path
}

// descending bitonic sort of 4096 floats in smem
__device__ void bitonic_desc(float* a, int tid, int nthr) {
    for (int k = 2; k <= 4096; k <<= 1) {
        for (int j = k >> 1; j > 0; j >>= 1) {
            __syncthreads();
            for (int i = tid; i < 4096; i += nthr) {
                int ixj = i ^ j;
                if (ixj > i) {
                    float x = a[i], y = a[ixj];
                    bool up = ((i & k) == 0);
                    if (up ? (x < y) : (x > y)) { a[i] = y; a[ixj] = x; }
                }
            }
        }
    }
    __syncthreads();
}

// ---------------------------------------------------------------------------
// Kernel B: per-row entmax1.5 (sort-based) + gumbel top-k mask + TV row term
// grid = 64 rows, 1024 threads
// ---------------------------------------------------------------------------
#define SMEM_B (5*4096*4)

__global__ __launch_bounds__(1024, 1)
void kernelB(const float* __restrict__ attn, float* __restrict__ out)
{
    extern __shared__ float sm[];
    float* s_scores = sm;            // 4096 (masked scores)
    float* s_attn   = sm + 4096;
    float* s_a      = sm + 8192;     // sort workspace
    float* s_cum    = sm + 12288;    // cumsum / later pert
    float* s_cum2   = sm + 16384;    // cumsum of squares
    __shared__ float red[32], red2[32];
    __shared__ float sh_mx, sh_teff, sh_tau;
    __shared__ int sh_support;

    const int row = blockIdx.x;
    const int tid = threadIdx.x;
    const int lane = tid & 31, wid = tid >> 5;

    // load + t_eff + row max
    float tf_ = 0.f, mx = -3.402823466e38f;
    for (int t = tid; t < TT; t += 1024) {
        float s = g_scores[row*TT + t];
        float a = attn[row*TT + t];
        s_scores[t] = s; s_attn[t] = a;
        tf_ += a; mx = fmaxf(mx, s);
    }
    for (int o = 16; o; o >>= 1) {
        tf_ += __shfl_xor_sync(0xffffffffu, tf_, o);
        mx = fmaxf(mx, __shfl_xor_sync(0xffffffffu, mx, o));
    }
    if (lane == 0) { red[wid] = tf_; red2[wid] = mx; }
    __syncthreads();
    if (tid == 0) {
        float a = 0.f, b = -3.402823466e38f;
        for (int w = 0; w < 32; w++) { a += red[w]; b = fmaxf(b, red2[w]); }
        sh_teff = a; sh_mx = b;
        sh_support = 0;
    }
    __syncthreads();
    mx = sh_mx;

    // x = (scores - max)/2; sort descending
    for (int t = tid; t < TT; t += 1024) s_a[t] = (s_scores[t] - mx) * 0.5f;
    bitonic_desc(s_a, tid, 1024);

    // block scans of sorted values and their squares (blocked: 4 per thread)
    const int p0 = tid * 4;
    float v0 = s_a[p0+0], v1 = s_a[p0+1], v2 = s_a[p0+2], v3 = s_a[p0+3];
    float c0 = v0, c1 = c0 + v1, c2 = c1 + v2, c3 = c2 + v3;
    float d0 = v0*v0, d1 = d0 + v1*v1, d2 = d1 + v2*v2, d3 = d2 + v3*v3;
    float s = c3, s2 = d3;
    const float tot = c3, tot2 = d3;
    for (int o = 1; o < 32; o <<= 1) {
        float n  = __shfl_up_sync(0xffffffffu, s, o);
        float n2 = __shfl_up_sync(0xffffffffu, s2, o);
        if (lane >= o) { s += n; s2 += n2; }
    }
    if (lane == 31) { red[wid] = s; red2[wid] = s2; }
    __syncthreads();
    if (wid == 0) {
        float w = red[lane], w2 = red2[lane];
        for (int o = 1; o < 32; o <<= 1) {
            float n  = __shfl_up_sync(0xffffffffu, w, o);
            float n2 = __shfl_up_sync(0xffffffffu, w2, o);
            if (lane >= o) { w += n; w2 += n2; }
        }
        red[lane] = w; red2[lane] = w2;
    }
    __syncthreads();
    float base  = (wid ? red[wid-1]  : 0.f) + (s  - tot);
    float base2 = (wid ? red2[wid-1] : 0.f) + (s2 - tot2);
    s_cum[p0+0] = base + c0;  s_cum[p0+1] = base + c1;
    s_cum[p0+2] = base + c2;  s_cum[p0+3] = base + c3;
    s_cum2[p0+0] = base2 + d0; s_cum2[p0+1] = base2 + d1;
    s_cum2[p0+2] = base2 + d2; s_cum2[p0+3] = base2 + d3;
    __syncthreads();

    // support count
    int cnt = 0;
#pragma unroll
    for (int j = 0; j < 4; j++) {
        int p = p0 + j;
        float rho = (float)(p + 1);
        float mean = s_cum[p] / rho;
        float msq  = s_cum2[p] / rho;
        float ssv  = rho * (msq - mean*mean);
        float delta = (1.f - ssv) / rho;
        float tau = mean - sqrtf(fmaxf(delta, 0.f));
        cnt += (tau <= s_a[p]) ? 1 : 0;
    }
    for (int o = 16; o; o >>= 1) cnt += __shfl_xor_sync(0xffffffffu, cnt, o);
    if (lane == 0) atomicAdd(&sh_support, cnt);
    __syncthreads();
    if (tid == 0) {
        int p = sh_support - 1;
        float rho = (float)(p + 1);
        float mean = s_cum[p] / rho;
        float msq  = s_cum2[p] / rho;
        float ssv  = rho * (msq - mean*mean);
        float delta = (1.f - ssv) / rho;
        sh_tau = mean - sqrtf(fmaxf(delta, 0.f));
    }
    __syncthreads();
    const float taustar = sh_tau;

    // z output
    for (int t = tid; t < TT; t += 1024) {
        float x = (s_scores[t] - mx) * 0.5f;
        float dd = fmaxf(x - taustar, 0.f);
        out[row*TT + t] = dd*dd*s_attn[t];
    }
    __syncthreads();   // s_cum/s_a safe to reuse

    // gumbel-perturbed scores (NaN-safe: ref's jnp.sort pushes NaN to the
    // bottom of the descending order, so map NaN -> -inf for the sort copy)
    for (int t = tid; t < TT; t += 1024) {
        uint32_t lin = (uint32_t)(row*TT + t);
        uint32_t bits = jax_bits(lin);
        float u = __uint_as_float((bits >> 9) | 0x3f800000u) - 1.0f;
        u = fmaxf(u, 0.f);
        float gum = -logf(-logf(u + 1e-6f) + 1e-6f);
        float pert = s_scores[t] * s_attn[t] + gum;
        s_cum[t] = pert;                       // raw pert (NaN>=thr is false, matches ref h=0)
        s_a[t] = (pert != pert) ? __int_as_float(0xff800000) : pert;
    }
    bitonic_desc(s_a, tid, 1024);

    const float teff = sh_teff;
    float kf = rintf(0.3f * teff);
    kf = fminf(fmaxf(kf, 1.f), fmaxf(teff, 1.f));
    const int ki = (int)kf;
    const float thr = s_a[ki - 1];

    // g output + TV accumulation
    float num = 0.f, den = 0.f;
    for (int t = tid; t < TT; t += 1024) {
        float a0 = s_attn[t];
        float gv = (s_cum[t] >= thr) ? a0 : 0.f;
        out[BT + row*TT + t] = gv;
        if (t < TT - 1) {
            float a1 = s_attn[t+1];
            float gv1 = (s_cum[t+1] >= thr) ? a1 : 0.f;
            float valid = a0 * a1;
            num += fabsf(gv1 - gv) * valid;
            den += valid;
        }
    }
    for (int o = 16; o; o >>= 1) {
        num += __shfl_xor_sync(0xffffffffu, num, o);
        den += __shfl_xor_sync(0xffffffffu, den, o);
    }
    if (lane == 0) { red[wid] = num; red2[wid] = den; }
    __syncthreads();
    if (tid == 0) {
        float a = 0.f, b = 0.f;
        for (int w = 0; w < 32; w++) { a += red[w]; b += red2[w]; }
        g_tv[row] = a / fmaxf(b, 1.f);
    }
}

// ---------------------------------------------------------------------------
// Kernel C: reg = 0.1 * mean(tv)
// ---------------------------------------------------------------------------
__global__ void kernelC(float* __restrict__ out)
{
    __shared__ float r[64];
    r[threadIdx.x] = g_tv[threadIdx.x];
    __syncthreads();
    if (threadIdx.x == 0) {
        float s = 0.f;
        for (int i = 0; i < 64; i++) s += r[i];
        out[2*BT] = 0.1f * (s / 64.f);
    }
}

extern "C" void kernel_launch(void* const* d_in, const int* in_sizes, int n_in,
                              void* d_out, int out_size)
{
    const float* emb   = (const float*)d_in[0];
    const float* attn  = (const float*)d_in[1];
    const float* gamma = (const float*)d_in[2];
    const float* beta  = (const float*)d_in[3];
    const float* W1    = (const float*)d_in[4];
    const float* b1    = (const float*)d_in[5];
    const float* W2    = (const float*)d_in[6];
    const float* b2    = (const float*)d_in[7];
    float* out = (float*)d_out;

    cudaFuncSetAttribute(kernelA, cudaFuncAttributeMaxDynamicSharedMemorySize, SMEM_A);
    cudaFuncSetAttribute(kernelB, cudaFuncAttributeMaxDynamicSharedMemorySize, SMEM_B);

    kernelA<<<BT/64, 256, SMEM_A>>>(emb, attn, gamma, beta, W1, b1, W2, b2);
    kernelB<<<BB, 1024, SMEM_B>>>(attn, out);
    kernelC<<<1, 64>>>(out);
}

// round 5
// speedup vs baseline: 1.7774x; 1.7696x over previous
#include <cuda_runtime.h>
#include <cstdint>
#include <math.h>

// Problem constants
#define BB 64
#define TT 4096
#define DD 256
#define HH 341
#define BT (BB*TT)
#define NEGV (-1e9f)

// Scratch (static __device__ allowed; no cudaMalloc)
__device__ float g_scores[BT];
__device__ float g_tv[BB];

// ---------------------------------------------------------------------------
// Kernel A: fused  emb*attn -> LayerNorm -> GEMM(256x341) -> GELU -> dot(W2)
// One block = 64 consecutive tokens, 256 threads.
// EARLY EXIT: attn is a prefix mask per row; fully-masked tiles (~37.5% of
// all tiles) skip the entire LN+GEMM pipeline and just write NEG.
// Register tile 4m x 4n, W1 chunks of 64 cols split into two k-halves of 128.
// ---------------------------------------------------------------------------
#define XP 68
#define SMEM_A ((256*XP + 128*64)*4)

__global__ __launch_bounds__(256, 2)
void kernelA(const float* __restrict__ emb, const float* __restrict__ attn,
             const float* __restrict__ gamma, const float* __restrict__ beta,
             const float* __restrict__ W1, const float* __restrict__ b1,
             const float* __restrict__ W2, const float* __restrict__ b2)
{
    extern __shared__ float smA[];
    float* xsT = smA;                 // [256][XP]
    float* ws  = smA + 256*XP;        // [128][64]
    __shared__ float attn_sm[64], mu_sm[64], rstd_sm[64], scores_sm[64];
    __shared__ int sh_any;

    const int tid = threadIdx.x;
    const int base64 = blockIdx.x * 64;

    if (tid == 0) sh_any = 0;
    __syncthreads();
    if (tid < 64) {
        float a = attn[base64 + tid];
        attn_sm[tid] = a;
        scores_sm[tid] = 0.f;
        if (a != 0.f) sh_any = 1;     // benign race
    }
    __syncthreads();

    // Fully-masked tile: scores are NEG regardless of the MLP. Skip everything.
    if (!sh_any) {
        if (tid < 64) g_scores[base64 + tid] = NEGV;
        return;
    }

    // load emb tile (token-major) into transposed smem, multiply by attn
    {
        const float4* emb4 = (const float4*)(emb + (size_t)base64 * DD);
        for (int v = tid; v < 64*64; v += 256) {
            int m = v & 63;              // token within tile
            int q = v >> 6;              // float4 index within row (0..63)
            float4 e = emb4[m*64 + q];
            float a = attn_sm[m];
            int d0 = q * 4;
            xsT[(d0+0)*XP + m] = e.x * a;
            xsT[(d0+1)*XP + m] = e.y * a;
            xsT[(d0+2)*XP + m] = e.z * a;
            xsT[(d0+3)*XP + m] = e.w * a;
        }
    }
    __syncthreads();

    // LayerNorm stats: 4 threads per token
    {
        int m = tid >> 2, q = tid & 3;
        float s = 0.f, s2 = 0.f;
        for (int i = 0; i < 64; i++) {
            float v = xsT[(q*64 + i)*XP + m];
            s += v; s2 += v*v;
        }
        s  += __shfl_xor_sync(0xffffffffu, s, 1);
        s  += __shfl_xor_sync(0xffffffffu, s, 2);
        s2 += __shfl_xor_sync(0xffffffffu, s2, 1);
        s2 += __shfl_xor_sync(0xffffffffu, s2, 2);
        if (q == 0) {
            float muv = s * (1.f/256.f);
            float var = s2 * (1.f/256.f) - muv*muv;
            mu_sm[m] = muv;
            rstd_sm[m] = rsqrtf(var + 1e-5f);
        }
    }
    __syncthreads();

    // normalize in place (+ gamma/beta)
    for (int v = tid; v < 64*256; v += 256) {
        int m = v & 63;
        int d = v >> 6;
        float val = xsT[d*XP + m];
        xsT[d*XP + m] = (val - mu_sm[m]) * rstd_sm[m] * gamma[d] + beta[d];
    }

    const int ty = tid >> 4;        // 0..15 -> 4 m-rows each
    const int tx = tid & 15;        // 0..15 -> 4 n-cols each
    const int m0 = ty << 2;
    const int n0 = tx << 2;

    const int nchunks = 6;          // 6*64 = 384 >= 341
    for (int c = 0; c < nchunks; c++) {
        const int h0 = c * 64;

        float acc[4][4];
#pragma unroll
        for (int i = 0; i < 4; i++)
#pragma unroll
            for (int j = 0; j < 4; j++) acc[i][j] = 0.f;

        for (int kb = 0; kb < 2; kb++) {
            __syncthreads();
            // load W1 half-chunk [128][64]
            for (int v = tid; v < 128*64; v += 256) {
                int d = v >> 6, j = v & 63;
                int h = h0 + j;
                ws[v] = (h < HH) ? W1[(kb*128 + d)*HH + h] : 0.f;
            }
            __syncthreads();

            const float* xp = xsT + kb*128*XP + m0;
            const float* wp = ws + n0;
#pragma unroll 16
            for (int k = 0; k < 128; k++) {
                float4 xv = *(const float4*)(xp + k*XP);
                float4 wv = *(const float4*)(wp + k*64);
                acc[0][0] = fmaf(xv.x, wv.x, acc[0][0]);
                acc[0][1] = fmaf(xv.x, wv.y, acc[0][1]);
                acc[0][2] = fmaf(xv.x, wv.z, acc[0][2]);
                acc[0][3] = fmaf(xv.x, wv.w, acc[0][3]);
                acc[1][0] = fmaf(xv.y, wv.x, acc[1][0]);
                acc[1][1] = fmaf(xv.y, wv.y, acc[1][1]);
                acc[1][2] = fmaf(xv.y, wv.z, acc[1][2]);
                acc[1][3] = fmaf(xv.y, wv.w, acc[1][3]);
                acc[2][0] = fmaf(xv.z, wv.x, acc[2][0]);
                acc[2][1] = fmaf(xv.z, wv.y, acc[2][1]);
                acc[2][2] = fmaf(xv.z, wv.z, acc[2][2]);
                acc[2][3] = fmaf(xv.z, wv.w, acc[2][3]);
                acc[3][0] = fmaf(xv.w, wv.x, acc[3][0]);
                acc[3][1] = fmaf(xv.w, wv.y, acc[3][1]);
                acc[3][2] = fmaf(xv.w, wv.z, acc[3][2]);
                acc[3][3] = fmaf(xv.w, wv.w, acc[3][3]);
            }
        }

        // epilogue: bias + exact gelu + * W2, partial per row
        float part[4] = {0.f, 0.f, 0.f, 0.f};
#pragma unroll
        for (int j = 0; j < 4; j++) {
            int h = h0 + n0 + j;
            if (h < HH) {
                float b1v = b1[h], w2v = W2[h];
#pragma unroll
                for (int i = 0; i < 4; i++) {
                    float v = acc[i][j] + b1v;
                    part[i] += 0.5f*v*(1.f + erff(v*0.70710678118654752f)) * w2v;
                }
            }
        }
#pragma unroll
        for (int o = 8; o >= 1; o >>= 1) {
            part[0] += __shfl_xor_sync(0xffffffffu, part[0], o);
            part[1] += __shfl_xor_sync(0xffffffffu, part[1], o);
            part[2] += __shfl_xor_sync(0xffffffffu, part[2], o);
            part[3] += __shfl_xor_sync(0xffffffffu, part[3], o);
        }
        if (tx == 0) {
            scores_sm[m0+0] += part[0];
            scores_sm[m0+1] += part[1];
            scores_sm[m0+2] += part[2];
            scores_sm[m0+3] += part[3];
        }
    }
    __syncthreads();
    if (tid < 64) {
        float sc = scores_sm[tid] + b2[0];
        if (attn_sm[tid] == 0.f) sc = NEGV;
        g_scores[base64 + tid] = sc;
    }
}

// ---------------------------------------------------------------------------
// Threefry-2x32-20, JAX "partitionable" scheme (default in modern JAX):
//   per-element i: bind(k1, k2, ctr_hi=0, ctr_lo=i); 32-bit draw = out0 ^ out1
// ---------------------------------------------------------------------------
__device__ __forceinline__ uint32_t rotl32(uint32_t x, int r) { return (x << r) | (x >> (32 - r)); }
__device__ __forceinline__ void tf_r4(uint32_t& x0, uint32_t& x1, int a, int b, int c, int d) {
    x0 += x1; x1 = rotl32(x1, a); x1 ^= x0;
    x0 += x1; x1 = rotl32(x1, b); x1 ^= x0;
    x0 += x1; x1 = rotl32(x1, c); x1 ^= x0;
    x0 += x1; x1 = rotl32(x1, d); x1 ^= x0;
}
__device__ __forceinline__ uint32_t jax_bits(uint32_t i) {
    const uint32_t k0 = 0u, k1 = 42u;
    const uint32_t k2 = k0 ^ k1 ^ 0x1BD11BDAu;
    uint32_t x0 = 0u + k0;   // counter hi word = 0 (indices < 2^32)
    uint32_t x1 = i  + k1;   // counter lo word = linear element index
    tf_r4(x0, x1, 13, 15, 26, 6);   x0 += k1; x1 += k2 + 1u;
    tf_r4(x0, x1, 17, 29, 16, 24);  x0 += k2; x1 += k0 + 2u;
    tf_r4(x0, x1, 13, 15, 26, 6);   x0 += k0; x1 += k1 + 3u;
    tf_r4(x0, x1, 17, 29, 16, 24);  x0 += k1; x1 += k2 + 4u;
    tf_r4(x0, x1, 13, 15, 26, 6);   x0 += k2; x1 += k0 + 5u;
    return x0 ^ x1;          // 32-bit draw in the partitionable path
}

// descending bitonic sort of 4096 floats in smem
__device__ void bitonic_desc(float* a, int tid, int nthr) {
    for (int k = 2; k <= 4096; k <<= 1) {
        for (int j = k >> 1; j > 0; j >>= 1) {
            __syncthreads();
            for (int i = tid; i < 4096; i += nthr) {
                int ixj = i ^ j;
                if (ixj > i) {
                    float x = a[i], y = a[ixj];
                    bool up = ((i & k) == 0);
                    if (up ? (x < y) : (x > y)) { a[i] = y; a[ixj] = x; }
                }
            }
        }
    }
    __syncthreads();
}

// ---------------------------------------------------------------------------
// Kernel B: per-row entmax1.5 (sort-based) + gumbel top-k mask + TV row term
// grid = 64 rows, 1024 threads
// ---------------------------------------------------------------------------
#define SMEM_B (5*4096*4)

__global__ __launch_bounds__(1024, 1)
void kernelB(const float* __restrict__ attn, float* __restrict__ out)
{
    extern __shared__ float sm[];
    float* s_scores = sm;            // 4096 (masked scores)
    float* s_attn   = sm + 4096;
    float* s_a      = sm + 8192;     // sort workspace
    float* s_cum    = sm + 12288;    // cumsum / later pert
    float* s_cum2   = sm + 16384;    // cumsum of squares
    __shared__ float red[32], red2[32];
    __shared__ float sh_mx, sh_teff, sh_tau;
    __shared__ int sh_support;

    const int row = blockIdx.x;
    const int tid = threadIdx.x;
    const int lane = tid & 31, wid = tid >> 5;

    // load + t_eff + row max
    float tf_ = 0.f, mx = -3.402823466e38f;
    for (int t = tid; t < TT; t += 1024) {
        float s = g_scores[row*TT + t];
        float a = attn[row*TT + t];
        s_scores[t] = s; s_attn[t] = a;
        tf_ += a; mx = fmaxf(mx, s);
    }
    for (int o = 16; o; o >>= 1) {
        tf_ += __shfl_xor_sync(0xffffffffu, tf_, o);
        mx = fmaxf(mx, __shfl_xor_sync(0xffffffffu, mx, o));
    }
    if (lane == 0) { red[wid] = tf_; red2[wid] = mx; }
    __syncthreads();
    if (tid == 0) {
        float a = 0.f, b = -3.402823466e38f;
        for (int w = 0; w < 32; w++) { a += red[w]; b = fmaxf(b, red2[w]); }
        sh_teff = a; sh_mx = b;
        sh_support = 0;
    }
    __syncthreads();
    mx = sh_mx;

    // x = (scores - max)/2; sort descending
    for (int t = tid; t < TT; t += 1024) s_a[t] = (s_scores[t] - mx) * 0.5f;
    bitonic_desc(s_a, tid, 1024);

    // block scans of sorted values and their squares (blocked: 4 per thread)
    const int p0 = tid * 4;
    float v0 = s_a[p0+0], v1 = s_a[p0+1], v2 = s_a[p0+2], v3 = s_a[p0+3];
    float c0 = v0, c1 = c0 + v1, c2 = c1 + v2, c3 = c2 + v3;
    float d0 = v0*v0, d1 = d0 + v1*v1, d2 = d1 + v2*v2, d3 = d2 + v3*v3;
    float s = c3, s2 = d3;
    const float tot = c3, tot2 = d3;
    for (int o = 1; o < 32; o <<= 1) {
        float n  = __shfl_up_sync(0xffffffffu, s, o);
        float n2 = __shfl_up_sync(0xffffffffu, s2, o);
        if (lane >= o) { s += n; s2 += n2; }
    }
    if (lane == 31) { red[wid] = s; red2[wid] = s2; }
    __syncthreads();
    if (wid == 0) {
        float w = red[lane], w2 = red2[lane];
        for (int o = 1; o < 32; o <<= 1) {
            float n  = __shfl_up_sync(0xffffffffu, w, o);
            float n2 = __shfl_up_sync(0xffffffffu, w2, o);
            if (lane >= o) { w += n; w2 += n2; }
        }
        red[lane] = w; red2[lane] = w2;
    }
    __syncthreads();
    float base  = (wid ? red[wid-1]  : 0.f) + (s  - tot);
    float base2 = (wid ? red2[wid-1] : 0.f) + (s2 - tot2);
    s_cum[p0+0] = base + c0;  s_cum[p0+1] = base + c1;
    s_cum[p0+2] = base + c2;  s_cum[p0+3] = base + c3;
    s_cum2[p0+0] = base2 + d0; s_cum2[p0+1] = base2 + d1;
    s_cum2[p0+2] = base2 + d2; s_cum2[p0+3] = base2 + d3;
    __syncthreads();

    // support count
    int cnt = 0;
#pragma unroll
    for (int j = 0; j < 4; j++) {
        int p = p0 + j;
        float rho = (float)(p + 1);
        float mean = s_cum[p] / rho;
        float msq  = s_cum2[p] / rho;
        float ssv  = rho * (msq - mean*mean);
        float delta = (1.f - ssv) / rho;
        float tau = mean - sqrtf(fmaxf(delta, 0.f));
        cnt += (tau <= s_a[p]) ? 1 : 0;
    }
    for (int o = 16; o; o >>= 1) cnt += __shfl_xor_sync(0xffffffffu, cnt, o);
    if (lane == 0) atomicAdd(&sh_support, cnt);
    __syncthreads();
    if (tid == 0) {
        int p = sh_support - 1;
        float rho = (float)(p + 1);
        float mean = s_cum[p] / rho;
        float msq  = s_cum2[p] / rho;
        float ssv  = rho * (msq - mean*mean);
        float delta = (1.f - ssv) / rho;
        sh_tau = mean - sqrtf(fmaxf(delta, 0.f));
    }
    __syncthreads();
    const float taustar = sh_tau;

    // z output
    for (int t = tid; t < TT; t += 1024) {
        float x = (s_scores[t] - mx) * 0.5f;
        float dd = fmaxf(x - taustar, 0.f);
        out[row*TT + t] = dd*dd*s_attn[t];
    }
    __syncthreads();   // s_cum/s_a safe to reuse

    // gumbel-perturbed scores (NaN-safe: ref's jnp.sort pushes NaN to the
    // bottom of the descending order, so map NaN -> -inf for the sort copy)
    for (int t = tid; t < TT; t += 1024) {
        uint32_t lin = (uint32_t)(row*TT + t);
        uint32_t bits = jax_bits(lin);
        float u = __uint_as_float((bits >> 9) | 0x3f800000u) - 1.0f;
        u = fmaxf(u, 0.f);
        float gum = -logf(-logf(u + 1e-6f) + 1e-6f);
        float pert = s_scores[t] * s_attn[t] + gum;
        s_cum[t] = pert;                       // raw pert (NaN>=thr is false, matches ref h=0)
        s_a[t] = (pert != pert) ? __int_as_float(0xff800000) : pert;
    }
    bitonic_desc(s_a, tid, 1024);

    const float teff = sh_teff;
    float kf = rintf(0.3f * teff);
    kf = fminf(fmaxf(kf, 1.f), fmaxf(teff, 1.f));
    const int ki = (int)kf;
    const float thr = s_a[ki - 1];

    // g output + TV accumulation
    float num = 0.f, den = 0.f;
    for (int t = tid; t < TT; t += 1024) {
        float a0 = s_attn[t];
        float gv = (s_cum[t] >= thr) ? a0 : 0.f;
        out[BT + row*TT + t] = gv;
        if (t < TT - 1) {
            float a1 = s_attn[t+1];
            float gv1 = (s_cum[t+1] >= thr) ? a1 : 0.f;
            float valid = a0 * a1;
            num += fabsf(gv1 - gv) * valid;
            den += valid;
        }
    }
    for (int o = 16; o; o >>= 1) {
        num += __shfl_xor_sync(0xffffffffu, num, o);
        den += __shfl_xor_sync(0xffffffffu, den, o);
    }
    if (lane == 0) { red[wid] = num; red2[wid] = den; }
    __syncthreads();
    if (tid == 0) {
        float a = 0.f, b = 0.f;
        for (int w = 0; w < 32; w++) { a += red[w]; b += red2[w]; }
        g_tv[row] = a / fmaxf(b, 1.f);
    }
}

// ---------------------------------------------------------------------------
// Kernel C: reg = 0.1 * mean(tv)
// ---------------------------------------------------------------------------
__global__ void kernelC(float* __restrict__ out)
{
    __shared__ float r[64];
    r[threadIdx.x] = g_tv[threadIdx.x];
    __syncthreads();
    if (threadIdx.x == 0) {
        float s = 0.f;
        for (int i = 0; i < 64; i++) s += r[i];
        out[2*BT] = 0.1f * (s / 64.f);
    }
}

extern "C" void kernel_launch(void* const* d_in, const int* in_sizes, int n_in,
                              void* d_out, int out_size)
{
    const float* emb   = (const float*)d_in[0];
    const float* attn  = (const float*)d_in[1];
    const float* gamma = (const float*)d_in[2];
    const float* beta  = (const float*)d_in[3];
    const float* W1    = (const float*)d_in[4];
    const float* b1    = (const float*)d_in[5];
    const float* W2    = (const float*)d_in[6];
    const float* b2    = (const float*)d_in[7];
    float* out = (float*)d_out;

    cudaFuncSetAttribute(kernelA, cudaFuncAttributeMaxDynamicSharedMemorySize, SMEM_A);
    cudaFuncSetAttribute(kernelB, cudaFuncAttributeMaxDynamicSharedMemorySize, SMEM_B);

    kernelA<<<BT/64, 256, SMEM_A>>>(emb, attn, gamma, beta, W1, b1, W2, b2);
    kernelB<<<BB, 1024, SMEM_B>>>(attn, out);
    kernelC<<<1, 64>>>(out);
}

// round 6
// speedup vs baseline: 1.7852x; 1.0044x over previous
#include <cuda_runtime.h>
#include <cstdint>
#include <math.h>

// Problem constants
#define BB 64
#define TT 4096
#define DD 256
#define HH 341
#define BT (BB*TT)
#define NEGV (-1e9f)

__device__ float g_scores[BT];
__device__ float g_tv[BB];

// packed fp32 helpers (sm_103a FFMA2 path — exact fp32 math at 2x rate)
#define FMA_F32X2(d, a, b) \
    asm("fma.rn.f32x2 %0, %1, %2, %0;" : "+l"(d) : "l"(a), "l"(b))
#define PACK_F32X2(out, lo, hi) \
    asm("mov.b64 %0, {%1, %2};" : "=l"(out) : "f"(lo), "f"(hi))
__device__ __forceinline__ float f2x2_lo(unsigned long long v) {
    return __uint_as_float((unsigned)(v & 0xffffffffull));
}
__device__ __forceinline__ float f2x2_hi(unsigned long long v) {
    return __uint_as_float((unsigned)(v >> 32));
}

// ---------------------------------------------------------------------------
// Kernel A: fused  emb*attn -> LayerNorm -> GEMM(256x341) -> GELU -> dot(W2)
// One block = 64 tokens, 256 threads. Early-exit on fully-masked tiles.
// Inner loop: 8m x 2n per thread, m-pairs packed in f32x2 lanes, FFMA2.
// warp w owns m-rows [8w, 8w+8); lane = n-pair index.
// ---------------------------------------------------------------------------
#define XP 68
#define SMEM_A ((256*XP + 128*64)*4)

__global__ __launch_bounds__(256, 2)
void kernelA(const float* __restrict__ emb, const float* __restrict__ attn,
             const float* __restrict__ gamma, const float* __restrict__ beta,
             const float* __restrict__ W1, const float* __restrict__ b1,
             const float* __restrict__ W2, const float* __restrict__ b2)
{
    extern __shared__ float smA[];
    float* xsT = smA;                 // [256][XP] transposed normalized tile
    float* ws  = smA + 256*XP;        // [128][64] W1 half-chunk
    __shared__ float attn_sm[64], mu_sm[64], rstd_sm[64], scores_sm[64];
    __shared__ int sh_any;

    const int tid = threadIdx.x;
    const int base64 = blockIdx.x * 64;

    if (tid == 0) sh_any = 0;
    __syncthreads();
    if (tid < 64) {
        float a = attn[base64 + tid];
        attn_sm[tid] = a;
        scores_sm[tid] = 0.f;
        if (a != 0.f) sh_any = 1;     // benign race
    }
    __syncthreads();

    // Fully-masked tile: scores are NEG regardless of the MLP.
    if (!sh_any) {
        if (tid < 64) g_scores[base64 + tid] = NEGV;
        return;
    }

    // load emb tile into transposed smem, multiply by attn
    {
        const float4* emb4 = (const float4*)(emb + (size_t)base64 * DD);
        for (int v = tid; v < 64*64; v += 256) {
            int m = v & 63;
            int q = v >> 6;
            float4 e = emb4[m*64 + q];
            float a = attn_sm[m];
            int d0 = q * 4;
            xsT[(d0+0)*XP + m] = e.x * a;
            xsT[(d0+1)*XP + m] = e.y * a;
            xsT[(d0+2)*XP + m] = e.z * a;
            xsT[(d0+3)*XP + m] = e.w * a;
        }
    }
    __syncthreads();

    // LayerNorm stats: 4 threads per token
    {
        int m = tid >> 2, q = tid & 3;
        float s = 0.f, s2 = 0.f;
        for (int i = 0; i < 64; i++) {
            float v = xsT[(q*64 + i)*XP + m];
            s += v; s2 += v*v;
        }
        s  += __shfl_xor_sync(0xffffffffu, s, 1);
        s  += __shfl_xor_sync(0xffffffffu, s, 2);
        s2 += __shfl_xor_sync(0xffffffffu, s2, 1);
        s2 += __shfl_xor_sync(0xffffffffu, s2, 2);
        if (q == 0) {
            float muv = s * (1.f/256.f);
            float var = s2 * (1.f/256.f) - muv*muv;
            mu_sm[m] = muv;
            rstd_sm[m] = rsqrtf(var + 1e-5f);
        }
    }
    __syncthreads();

    // normalize in place (+ gamma/beta)
    for (int v = tid; v < 64*256; v += 256) {
        int m = v & 63;
        int d = v >> 6;
        float val = xsT[d*XP + m];
        xsT[d*XP + m] = (val - mu_sm[m]) * rstd_sm[m] * gamma[d] + beta[d];
    }

    const int wrp  = tid >> 5;      // 0..7  -> 8 m-rows each
    const int lane = tid & 31;      // 0..31 -> 2 n-cols each
    const int m0 = wrp << 3;
    const int n0 = lane << 1;

    const int nchunks = 6;          // 6*64 = 384 >= 341
    for (int c = 0; c < nchunks; c++) {
        const int h0 = c * 64;

        unsigned long long acc[4][2];   // [m-pair][n], each f32x2 over (2m)
#pragma unroll
        for (int i = 0; i < 4; i++) { acc[i][0] = 0ull; acc[i][1] = 0ull; }

        for (int kb = 0; kb < 2; kb++) {
            __syncthreads();
            // load W1 half-chunk [128][64]
            for (int v = tid; v < 128*64; v += 256) {
                int d = v >> 6, j = v & 63;
                int h = h0 + j;
                ws[v] = (h < HH) ? W1[(kb*128 + d)*HH + h] : 0.f;
            }
            __syncthreads();

            const float* xp = xsT + kb*128*XP + m0;
            const float* wp = ws + n0;
#pragma unroll 8
            for (int k = 0; k < 128; k++) {
                // 8 consecutive m-values as 4 packed f32x2 (broadcast in warp)
                ulonglong2 xa = *(const ulonglong2*)(xp + k*XP);
                ulonglong2 xb = *(const ulonglong2*)(xp + k*XP + 4);
                float w0 = wp[k*64 + 0];
                float w1 = wp[k*64 + 1];
                unsigned long long ww0, ww1;
                PACK_F32X2(ww0, w0, w0);
                PACK_F32X2(ww1, w1, w1);
                FMA_F32X2(acc[0][0], xa.x, ww0);
                FMA_F32X2(acc[0][1], xa.x, ww1);
                FMA_F32X2(acc[1][0], xa.y, ww0);
                FMA_F32X2(acc[1][1], xa.y, ww1);
                FMA_F32X2(acc[2][0], xb.x, ww0);
                FMA_F32X2(acc[2][1], xb.x, ww1);
                FMA_F32X2(acc[3][0], xb.y, ww0);
                FMA_F32X2(acc[3][1], xb.y, ww1);
            }
        }

        // epilogue: bias + exact gelu + * W2, partial per m-row
        float part[8];
#pragma unroll
        for (int i = 0; i < 8; i++) part[i] = 0.f;
#pragma unroll
        for (int j = 0; j < 2; j++) {
            int h = h0 + n0 + j;
            if (h < HH) {
                float b1v = b1[h], w2v = W2[h];
#pragma unroll
                for (int i = 0; i < 4; i++) {
                    float vlo = f2x2_lo(acc[i][j]) + b1v;
                    float vhi = f2x2_hi(acc[i][j]) + b1v;
                    part[2*i+0] += 0.5f*vlo*(1.f + erff(vlo*0.70710678118654752f)) * w2v;
                    part[2*i+1] += 0.5f*vhi*(1.f + erff(vhi*0.70710678118654752f)) * w2v;
                }
            }
        }
        // full-warp reduction over the 32 n-pair lanes
#pragma unroll
        for (int o = 16; o >= 1; o >>= 1) {
#pragma unroll
            for (int i = 0; i < 8; i++)
                part[i] += __shfl_xor_sync(0xffffffffu, part[i], o);
        }
        if (lane == 0) {
#pragma unroll
            for (int i = 0; i < 8; i++)
                scores_sm[m0 + i] += part[i];   // warp owns rows m0..m0+7
        }
    }
    __syncthreads();
    if (tid < 64) {
        float sc = scores_sm[tid] + b2[0];
        if (attn_sm[tid] == 0.f) sc = NEGV;
        g_scores[base64 + tid] = sc;
    }
}

// ---------------------------------------------------------------------------
// Threefry-2x32-20, JAX "partitionable" scheme:
//   per-element i: bind(k1, k2, ctr_hi=0, ctr_lo=i); 32-bit draw = out0 ^ out1
// ---------------------------------------------------------------------------
__device__ __forceinline__ uint32_t rotl32(uint32_t x, int r) { return (x << r) | (x >> (32 - r)); }
__device__ __forceinline__ void tf_r4(uint32_t& x0, uint32_t& x1, int a, int b, int c, int d) {
    x0 += x1; x1 = rotl32(x1, a); x1 ^= x0;
    x0 += x1; x1 = rotl32(x1, b); x1 ^= x0;
    x0 += x1; x1 = rotl32(x1, c); x1 ^= x0;
    x0 += x1; x1 = rotl32(x1, d); x1 ^= x0;
}
__device__ __forceinline__ uint32_t jax_bits(uint32_t i) {
    const uint32_t k0 = 0u, k1 = 42u;
    const uint32_t k2 = k0 ^ k1 ^ 0x1BD11BDAu;
    uint32_t x0 = 0u + k0;
    uint32_t x1 = i  + k1;
    tf_r4(x0, x1, 13, 15, 26, 6);   x0 += k1; x1 += k2 + 1u;
    tf_r4(x0, x1, 17, 29, 16, 24);  x0 += k2; x1 += k0 + 2u;
    tf_r4(x0, x1, 13, 15, 26, 6);   x0 += k0; x1 += k1 + 3u;
    tf_r4(x0, x1, 17, 29, 16, 24);  x0 += k1; x1 += k2 + 4u;
    tf_r4(x0, x1, 13, 15, 26, 6);   x0 += k2; x1 += k0 + 5u;
    return x0 ^ x1;
}

// descending bitonic sort of 4096 floats in smem
__device__ void bitonic_desc(float* a, int tid, int nthr) {
    for (int k = 2; k <= 4096; k <<= 1) {
        for (int j = k >> 1; j > 0; j >>= 1) {
            __syncthreads();
            for (int i = tid; i < 4096; i += nthr) {
                int ixj = i ^ j;
                if (ixj > i) {
                    float x = a[i], y = a[ixj];
                    bool up = ((i & k) == 0);
                    if (up ? (x < y) : (x > y)) { a[i] = y; a[ixj] = x; }
                }
            }
        }
    }
    __syncthreads();
}

// ---------------------------------------------------------------------------
// Kernel B: per-row entmax1.5 (sort-based) + gumbel top-k mask + TV row term
// ---------------------------------------------------------------------------
#define SMEM_B (5*4096*4)

__global__ __launch_bounds__(1024, 1)
void kernelB(const float* __restrict__ attn, float* __restrict__ out)
{
    extern __shared__ float sm[];
    float* s_scores = sm;
    float* s_attn   = sm + 4096;
    float* s_a      = sm + 8192;
    float* s_cum    = sm + 12288;
    float* s_cum2   = sm + 16384;
    __shared__ float red[32], red2[32];
    __shared__ float sh_mx, sh_teff, sh_tau;
    __shared__ int sh_support;

    const int row = blockIdx.x;
    const int tid = threadIdx.x;
    const int lane = tid & 31, wid = tid >> 5;

    float tf_ = 0.f, mx = -3.402823466e38f;
    for (int t = tid; t < TT; t += 1024) {
        float s = g_scores[row*TT + t];
        float a = attn[row*TT + t];
        s_scores[t] = s; s_attn[t] = a;
        tf_ += a; mx = fmaxf(mx, s);
    }
    for (int o = 16; o; o >>= 1) {
        tf_ += __shfl_xor_sync(0xffffffffu, tf_, o);
        mx = fmaxf(mx, __shfl_xor_sync(0xffffffffu, mx, o));
    }
    if (lane == 0) { red[wid] = tf_; red2[wid] = mx; }
    __syncthreads();
    if (tid == 0) {
        float a = 0.f, b = -3.402823466e38f;
        for (int w = 0; w < 32; w++) { a += red[w]; b = fmaxf(b, red2[w]); }
        sh_teff = a; sh_mx = b;
        sh_support = 0;
    }
    __syncthreads();
    mx = sh_mx;

    for (int t = tid; t < TT; t += 1024) s_a[t] = (s_scores[t] - mx) * 0.5f;
    bitonic_desc(s_a, tid, 1024);

    const int p0 = tid * 4;
    float v0 = s_a[p0+0], v1 = s_a[p0+1], v2 = s_a[p0+2], v3 = s_a[p0+3];
    float c0 = v0, c1 = c0 + v1, c2 = c1 + v2, c3 = c2 + v3;
    float d0 = v0*v0, d1 = d0 + v1*v1, d2 = d1 + v2*v2, d3 = d2 + v3*v3;
    float s = c3, s2 = d3;
    const float tot = c3, tot2 = d3;
    for (int o = 1; o < 32; o <<= 1) {
        float n  = __shfl_up_sync(0xffffffffu, s, o);
        float n2 = __shfl_up_sync(0xffffffffu, s2, o);
        if (lane >= o) { s += n; s2 += n2; }
    }
    if (lane == 31) { red[wid] = s; red2[wid] = s2; }
    __syncthreads();
    if (wid == 0) {
        float w = red[lane], w2 = red2[lane];
        for (int o = 1; o < 32; o <<= 1) {
            float n  = __shfl_up_sync(0xffffffffu, w, o);
            float n2 = __shfl_up_sync(0xffffffffu, w2, o);
            if (lane >= o) { w += n; w2 += n2; }
        }
        red[lane] = w; red2[lane] = w2;
    }
    __syncthreads();
    float base  = (wid ? red[wid-1]  : 0.f) + (s  - tot);
    float base2 = (wid ? red2[wid-1] : 0.f) + (s2 - tot2);
    s_cum[p0+0] = base + c0;  s_cum[p0+1] = base + c1;
    s_cum[p0+2] = base + c2;  s_cum[p0+3] = base + c3;
    s_cum2[p0+0] = base2 + d0; s_cum2[p0+1] = base2 + d1;
    s_cum2[p0+2] = base2 + d2; s_cum2[p0+3] = base2 + d3;
    __syncthreads();

    int cnt = 0;
#pragma unroll
    for (int j = 0; j < 4; j++) {
        int p = p0 + j;
        float rho = (float)(p + 1);
        float mean = s_cum[p] / rho;
        float msq  = s_cum2[p] / rho;
        float ssv  = rho * (msq - mean*mean);
        float delta = (1.f - ssv) / rho;
        float tau = mean - sqrtf(fmaxf(delta, 0.f));
        cnt += (tau <= s_a[p]) ? 1 : 0;
    }
    for (int o = 16; o; o >>= 1) cnt += __shfl_xor_sync(0xffffffffu, cnt, o);
    if (lane == 0) atomicAdd(&sh_support, cnt);
    __syncthreads();
    if (tid == 0) {
        int p = sh_support - 1;
        float rho = (float)(p + 1);
        float mean = s_cum[p] / rho;
        float msq  = s_cum2[p] / rho;
        float ssv  = rho * (msq - mean*mean);
        float delta = (1.f - ssv) / rho;
        sh_tau = mean - sqrtf(fmaxf(delta, 0.f));
    }
    __syncthreads();
    const float taustar = sh_tau;

    for (int t = tid; t < TT; t += 1024) {
        float x = (s_scores[t] - mx) * 0.5f;
        float dd = fmaxf(x - taustar, 0.f);
        out[row*TT + t] = dd*dd*s_attn[t];
    }
    __syncthreads();

    for (int t = tid; t < TT; t += 1024) {
        uint32_t lin = (uint32_t)(row*TT + t);
        uint32_t bits = jax_bits(lin);
        float u = __uint_as_float((bits >> 9) | 0x3f800000u) - 1.0f;
        u = fmaxf(u, 0.f);
        float gum = -logf(-logf(u + 1e-6f) + 1e-6f);
        float pert = s_scores[t] * s_attn[t] + gum;
        s_cum[t] = pert;
        s_a[t] = (pert != pert) ? __int_as_float(0xff800000) : pert;
    }
    bitonic_desc(s_a, tid, 1024);

    const float teff = sh_teff;
    float kf = rintf(0.3f * teff);
    kf = fminf(fmaxf(kf, 1.f), fmaxf(teff, 1.f));
    const int ki = (int)kf;
    const float thr = s_a[ki - 1];

    float num = 0.f, den = 0.f;
    for (int t = tid; t < TT; t += 1024) {
        float a0 = s_attn[t];
        float gv = (s_cum[t] >= thr) ? a0 : 0.f;
        out[BT + row*TT + t] = gv;
        if (t < TT - 1) {
            float a1 = s_attn[t+1];
            float gv1 = (s_cum[t+1] >= thr) ? a1 : 0.f;
            float valid = a0 * a1;
            num += fabsf(gv1 - gv) * valid;
            den += valid;
        }
    }
    for (int o = 16; o; o >>= 1) {
        num += __shfl_xor_sync(0xffffffffu, num, o);
        den += __shfl_xor_sync(0xffffffffu, den, o);
    }
    if (lane == 0) { red[wid] = num; red2[wid] = den; }
    __syncthreads();
    if (tid == 0) {
        float a = 0.f, b = 0.f;
        for (int w = 0; w < 32; w++) { a += red[w]; b += red2[w]; }
        g_tv[row] = a / fmaxf(b, 1.f);
    }
}

// ---------------------------------------------------------------------------
// Kernel C: reg = 0.1 * mean(tv)
// ---------------------------------------------------------------------------
__global__ void kernelC(float* __restrict__ out)
{
    __shared__ float r[64];
    r[threadIdx.x] = g_tv[threadIdx.x];
    __syncthreads();
    if (threadIdx.x == 0) {
        float s = 0.f;
        for (int i = 0; i < 64; i++) s += r[i];
        out[2*BT] = 0.1f * (s / 64.f);
    }
}

extern "C" void kernel_launch(void* const* d_in, const int* in_sizes, int n_in,
                              void* d_out, int out_size)
{
    const float* emb   = (const float*)d_in[0];
    const float* attn  = (const float*)d_in[1];
    const float* gamma = (const float*)d_in[2];
    const float* beta  = (const float*)d_in[3];
    const float* W1    = (const float*)d_in[4];
    const float* b1    = (const float*)d_in[5];
    const float* W2    = (const float*)d_in[6];
    const float* b2    = (const float*)d_in[7];
    float* out = (float*)d_out;

    cudaFuncSetAttribute(kernelA, cudaFuncAttributeMaxDynamicSharedMemorySize, SMEM_A);
    cudaFuncSetAttribute(kernelB, cudaFuncAttributeMaxDynamicSharedMemorySize, SMEM_B);

    kernelA<<<BT/64, 256, SMEM_A>>>(emb, attn, gamma, beta, W1, b1, W2, b2);
    kernelB<<<BB, 1024, SMEM_B>>>(attn, out);
    kernelC<<<1, 64>>>(out);
}

// round 8
// speedup vs baseline: 3.0766x; 1.7234x over previous
#include <cuda_runtime.h>
#include <cuda_bf16.h>
#include <cstdint>
#include <math.h>

// Problem constants
#define BB 64
#define TT 4096
#define DD 256
#define HH 341
#define BT (BB*TT)
#define NEGV (-1e9f)
#define NP 384            // hidden padded to 6*64
#define NCHUNK 6

__device__ float g_scores[BT];
__device__ float g_tv[BB];
__device__ __align__(16) __nv_bfloat16 g_w1t_hi[NP*DD];  // W1^T [h][d] bf16 hi
__device__ __align__(16) __nv_bfloat16 g_w1t_lo[NP*DD];  // bf16 lo residual
__device__ __align__(16) float g_w1t32[NP*DD];           // W1^T fp32 (refinement)
__device__ float g_b1p[NP];
__device__ float g_w2p[NP];

#define MMA16816(d, a0,a1,a2,a3, b0,b1) \
    asm volatile("mma.sync.aligned.m16n8k16.row.col.f32.bf16.bf16.f32 " \
        "{%0,%1,%2,%3}, {%4,%5,%6,%7}, {%8,%9}, {%0,%1,%2,%3};" \
        : "+f"((d)[0]), "+f"((d)[1]), "+f"((d)[2]), "+f"((d)[3]) \
        : "r"(a0), "r"(a1), "r"(a2), "r"(a3), "r"(b0), "r"(b1))

__device__ __forceinline__ uint32_t packbf(__nv_bfloat16 a, __nv_bfloat16 b) {
    return (uint32_t)__bfloat16_as_ushort(a) | ((uint32_t)__bfloat16_as_ushort(b) << 16);
}
__device__ __forceinline__ float gelu_w2(float v, float w2v) {
    return 0.5f*v*(1.f + erff(v*0.70710678118654752f)) * w2v;
}

// ---------------------------------------------------------------------------
// Prologue: transpose + bf16-split W1 (zero-padded to NP), pad b1/W2
// ---------------------------------------------------------------------------
__global__ void kernelW(const float* __restrict__ W1, const float* __restrict__ b1,
                        const float* __restrict__ W2)
{
    int h = blockIdx.x;       // 0..383
    int d = threadIdx.x;      // 0..255
    float w = (h < HH) ? W1[d*HH + h] : 0.f;
    __nv_bfloat16 hi = __float2bfloat16(w);
    __nv_bfloat16 lo = __float2bfloat16(w - __bfloat162float(hi));
    g_w1t_hi[h*DD + d] = hi;
    g_w1t_lo[h*DD + d] = lo;
    g_w1t32[h*DD + d] = w;
    if (d == 0) {
        g_b1p[h] = (h < HH) ? b1[h] : 0.f;
        g_w2p[h] = (h < HH) ? W2[h] : 0.f;
    }
}

// ---------------------------------------------------------------------------
// Kernel A: emb*attn -> LN -> mma.sync bf16 3-term GEMM -> GELU -> dot W2
// Block = 128 tokens, 256 threads (8 warps, 16 m-rows each). Early-exit.
// smem rows padded to 528B for conflict-free per-lane LDS.
// ---------------------------------------------------------------------------
#define RP 528            // padded row pitch (bytes) for 256 bf16 = 512B data
#define OFF_AHI 0
#define OFF_ALO 67584
#define OFF_BHI 135168
#define OFF_BLO 168960
#define OFF_ATTN 202752
#define OFF_B1P 203264
#define OFF_W2P 204800
#define OFF_ANY 206336
#define SMEM_A_TOT 206400

extern __shared__ char smx[];

__global__ __launch_bounds__(256, 1)
void kernelA(const float* __restrict__ emb, const float* __restrict__ attn,
             const float* __restrict__ gamma_, const float* __restrict__ beta_,
             const float* __restrict__ b2)
{
    const int tid = threadIdx.x, lane = tid & 31, wid = tid >> 5;
    const int base = blockIdx.x * 128;

    float* s_attn = (float*)(smx + OFF_ATTN);
    float* s_b1p  = (float*)(smx + OFF_B1P);
    float* s_w2p  = (float*)(smx + OFF_W2P);
    int*   s_any  = (int*)(smx + OFF_ANY);

    if (tid == 0) *s_any = 0;
    __syncthreads();
    if (tid < 128) {
        float a = attn[base + tid];
        s_attn[tid] = a;
        if (a != 0.f) *s_any = 1;   // benign race
    }
    __syncthreads();
    if (!*s_any) {
        if (tid < 128) g_scores[base + tid] = NEGV;
        return;
    }

    // stage b1/w2
    { int v = tid; s_b1p[v] = g_b1p[v]; s_w2p[v] = g_w2p[v];
      if (tid < NP - 256) { v = tid + 256; s_b1p[v] = g_b1p[v]; s_w2p[v] = g_w2p[v]; } }

    // ---- LN + bf16 hi/lo split -> A tiles (warp w owns tokens 16w..16w+15)
    for (int it = 0; it < 16; ++it) {
        int mt = wid * 16 + it;
        const float4* e4 = (const float4*)(emb + (size_t)(base + mt) * DD);
        float4 va = e4[lane*2], vb = e4[lane*2 + 1];
        float am = s_attn[mt];
        va.x *= am; va.y *= am; va.z *= am; va.w *= am;
        vb.x *= am; vb.y *= am; vb.z *= am; vb.w *= am;
        float s  = va.x+va.y+va.z+va.w+vb.x+vb.y+vb.z+vb.w;
        float s2 = va.x*va.x+va.y*va.y+va.z*va.z+va.w*va.w
                 + vb.x*vb.x+vb.y*vb.y+vb.z*vb.z+vb.w*vb.w;
#pragma unroll
        for (int o = 16; o; o >>= 1) {
            s  += __shfl_xor_sync(0xffffffffu, s, o);
            s2 += __shfl_xor_sync(0xffffffffu, s2, o);
        }
        float mu = s * (1.f/256.f);
        float rstd = rsqrtf(s2 * (1.f/256.f) - mu*mu + 1e-5f);

        float x[8] = {va.x, va.y, va.z, va.w, vb.x, vb.y, vb.z, vb.w};
        uint32_t qh[4], ql[4];
        const int d0 = lane * 8;
#pragma unroll
        for (int p = 0; p < 4; ++p) {
            float x0 = (x[2*p]   - mu) * rstd * gamma_[d0+2*p]   + beta_[d0+2*p];
            float x1 = (x[2*p+1] - mu) * rstd * gamma_[d0+2*p+1] + beta_[d0+2*p+1];
            __nv_bfloat16 h0 = __float2bfloat16(x0);
            __nv_bfloat16 h1 = __float2bfloat16(x1);
            __nv_bfloat16 l0 = __float2bfloat16(x0 - __bfloat162float(h0));
            __nv_bfloat16 l1 = __float2bfloat16(x1 - __bfloat162float(h1));
            qh[p] = packbf(h0, h1);
            ql[p] = packbf(l0, l1);
        }
        uint32_t off = mt * RP + lane * 16;
        *(uint4*)(smx + OFF_AHI + off) = make_uint4(qh[0],qh[1],qh[2],qh[3]);
        *(uint4*)(smx + OFF_ALO + off) = make_uint4(ql[0],ql[1],ql[2],ql[3]);
    }
    __syncthreads();

    const int g = lane >> 2;      // 0..7  (m-row / n-col group)
    const int q = lane & 3;       // 0..3  (k / col pair)
    const int m0 = wid * 16;
    const float b2v = b2[0];

    float part0 = 0.f, part1 = 0.f;   // row sums for rows m0+g, m0+g+8

    for (int c = 0; c < NCHUNK; ++c) {
        const int h0 = c * 64;
        __syncthreads();   // all warps done with previous B chunk
        // stage B chunk [64][256] hi+lo
        for (int v = tid; v < 2048; v += 256) {
            int r = v >> 5, u = v & 31;
            uint32_t dst = r * RP + u * 16;
            *(uint4*)(smx + OFF_BHI + dst) = ((const uint4*)g_w1t_hi)[(size_t)(h0 + r)*32 + u];
            *(uint4*)(smx + OFF_BLO + dst) = ((const uint4*)g_w1t_lo)[(size_t)(h0 + r)*32 + u];
        }
        __syncthreads();

        float acc[8][4];
#pragma unroll
        for (int j = 0; j < 8; ++j)
#pragma unroll
            for (int r = 0; r < 4; ++r) acc[j][r] = 0.f;

        const char* Ah = smx + OFF_AHI + (m0 + g) * RP + q * 4;
        const char* Al = smx + OFF_ALO + (m0 + g) * RP + q * 4;
        const char* Bh = smx + OFF_BHI + g * RP + q * 4;
        const char* Bl = smx + OFF_BLO + g * RP + q * 4;

#pragma unroll 4
        for (int ks = 0; ks < 16; ++ks) {
            const int kb = ks * 32;     // byte offset of k-block (16 bf16)
            uint32_t a0h = *(const uint32_t*)(Ah + kb);
            uint32_t a1h = *(const uint32_t*)(Ah + kb + 8*RP);
            uint32_t a2h = *(const uint32_t*)(Ah + kb + 16);
            uint32_t a3h = *(const uint32_t*)(Ah + kb + 8*RP + 16);
            uint32_t a0l = *(const uint32_t*)(Al + kb);
            uint32_t a1l = *(const uint32_t*)(Al + kb + 8*RP);
            uint32_t a2l = *(const uint32_t*)(Al + kb + 16);
            uint32_t a3l = *(const uint32_t*)(Al + kb + 8*RP + 16);
#pragma unroll
            for (int j = 0; j < 8; ++j) {
                uint32_t b0h = *(const uint32_t*)(Bh + j*8*RP + kb);
                uint32_t b1h = *(const uint32_t*)(Bh + j*8*RP + kb + 16);
                uint32_t b0l = *(const uint32_t*)(Bl + j*8*RP + kb);
                uint32_t b1l = *(const uint32_t*)(Bl + j*8*RP + kb + 16);
                MMA16816(acc[j], a0h,a1h,a2h,a3h, b0h,b1h);
                MMA16816(acc[j], a0h,a1h,a2h,a3h, b0l,b1l);
                MMA16816(acc[j], a0l,a1l,a2l,a3l, b0h,b1h);
            }
        }

        // epilogue: bias + gelu + * W2 (padded h: all-zero -> contributes 0)
#pragma unroll
        for (int j = 0; j < 8; ++j) {
            int h = h0 + 8*j + 2*q;
            float b1a = s_b1p[h],   w2a = s_w2p[h];
            float b1b = s_b1p[h+1], w2b = s_w2p[h+1];
            part0 += gelu_w2(acc[j][0] + b1a, w2a) + gelu_w2(acc[j][1] + b1b, w2b);
            part1 += gelu_w2(acc[j][2] + b1a, w2a) + gelu_w2(acc[j][3] + b1b, w2b);
        }
    }

    // reduce across the 4 lanes sharing g
    part0 += __shfl_xor_sync(0xffffffffu, part0, 1);
    part0 += __shfl_xor_sync(0xffffffffu, part0, 2);
    part1 += __shfl_xor_sync(0xffffffffu, part1, 1);
    part1 += __shfl_xor_sync(0xffffffffu, part1, 2);
    if (q == 0) {
        int ma = m0 + g, mb = m0 + g + 8;
        float sa = part0 + b2v, sb = part1 + b2v;
        if (s_attn[ma] == 0.f) sa = NEGV;
        if (s_attn[mb] == 0.f) sb = NEGV;
        g_scores[base + ma] = sa;
        g_scores[base + mb] = sb;
    }
}

// ---------------------------------------------------------------------------
// Threefry-2x32-20, JAX partitionable: ctr=(0,i), draw = out0 ^ out1
// ---------------------------------------------------------------------------
__device__ __forceinline__ uint32_t rotl32(uint32_t x, int r) { return (x << r) | (x >> (32 - r)); }
__device__ __forceinline__ void tf_r4(uint32_t& x0, uint32_t& x1, int a, int b, int c, int d) {
    x0 += x1; x1 = rotl32(x1, a); x1 ^= x0;
    x0 += x1; x1 = rotl32(x1, b); x1 ^= x0;
    x0 += x1; x1 = rotl32(x1, c); x1 ^= x0;
    x0 += x1; x1 = rotl32(x1, d); x1 ^= x0;
}
__device__ __forceinline__ uint32_t jax_bits(uint32_t i) {
    const uint32_t k0 = 0u, k1 = 42u;
    const uint32_t k2 = k0 ^ k1 ^ 0x1BD11BDAu;
    uint32_t x0 = 0u + k0;
    uint32_t x1 = i  + k1;
    tf_r4(x0, x1, 13, 15, 26, 6);   x0 += k1; x1 += k2 + 1u;
    tf_r4(x0, x1, 17, 29, 16, 24);  x0 += k2; x1 += k0 + 2u;
    tf_r4(x0, x1, 13, 15, 26, 6);   x0 += k0; x1 += k1 + 3u;
    tf_r4(x0, x1, 17, 29, 16, 24);  x0 += k1; x1 += k2 + 4u;
    tf_r4(x0, x1, 13, 15, 26, 6);   x0 += k2; x1 += k0 + 5u;
    return x0 ^ x1;
}
__device__ __forceinline__ float gumbel_of(uint32_t lin) {
    uint32_t bits = jax_bits(lin);
    float u = __uint_as_float((bits >> 9) | 0x3f800000u) - 1.0f;
    u = fmaxf(u, 0.f);
    return -logf(-logf(u + 1e-6f) + 1e-6f);
}

__device__ void bitonic_desc(float* a, int tid, int nthr) {
    for (int k = 2; k <= 4096; k <<= 1) {
        for (int j = k >> 1; j > 0; j >>= 1) {
            __syncthreads();
            for (int i = tid; i < 4096; i += nthr) {
                int ixj = i ^ j;
                if (ixj > i) {
                    float x = a[i], y = a[ixj];
                    bool up = ((i & k) == 0);
                    if (up ? (x < y) : (x > y)) { a[i] = y; a[ixj] = x; }
                }
            }
        }
    }
    __syncthreads();
}

// ---------------------------------------------------------------------------
// Kernel B: entmax1.5 + gumbel top-k with EXACT boundary refinement + TV
// ---------------------------------------------------------------------------
#define EPS_W 5e-4f
#define MAXC 64
#define SMEM_B ((5*4096 + 32*256)*4)

__global__ __launch_bounds__(1024, 1)
void kernelB(const float* __restrict__ attn, const float* __restrict__ emb,
             const float* __restrict__ gamma_, const float* __restrict__ beta_,
             const float* __restrict__ b2, float* __restrict__ out)
{
    extern __shared__ float sm[];
    float* s_scores = sm;
    float* s_attn   = sm + 4096;
    float* s_a      = sm + 8192;
    float* s_cum    = sm + 12288;
    float* s_cum2   = sm + 16384;
    float* s_xn     = sm + 20480;     // [32 warps][256]
    __shared__ float red[32], red2[32];
    __shared__ float sh_mx, sh_teff, sh_tau, sh_thr;
    __shared__ int sh_support, sh_above, sh_ncand;
    __shared__ int cand_idx[MAXC];
    __shared__ float cand_pert[MAXC];
    __shared__ int cand_sel[MAXC];

    const int row = blockIdx.x;
    const int tid = threadIdx.x;
    const int lane = tid & 31, wid = tid >> 5;

    float tf_ = 0.f, mx = -3.402823466e38f;
    for (int t = tid; t < TT; t += 1024) {
        float s = g_scores[row*TT + t];
        float a = attn[row*TT + t];
        s_scores[t] = s; s_attn[t] = a;
        tf_ += a; mx = fmaxf(mx, s);
    }
    for (int o = 16; o; o >>= 1) {
        tf_ += __shfl_xor_sync(0xffffffffu, tf_, o);
        mx = fmaxf(mx, __shfl_xor_sync(0xffffffffu, mx, o));
    }
    if (lane == 0) { red[wid] = tf_; red2[wid] = mx; }
    __syncthreads();
    if (tid == 0) {
        float a = 0.f, b = -3.402823466e38f;
        for (int w = 0; w < 32; w++) { a += red[w]; b = fmaxf(b, red2[w]); }
        sh_teff = a; sh_mx = b;
        sh_support = 0; sh_above = 0; sh_ncand = 0;
    }
    __syncthreads();
    mx = sh_mx;

    // ---- entmax 1.5
    for (int t = tid; t < TT; t += 1024) s_a[t] = (s_scores[t] - mx) * 0.5f;
    bitonic_desc(s_a, tid, 1024);

    const int p0 = tid * 4;
    {
        float v0 = s_a[p0+0], v1 = s_a[p0+1], v2 = s_a[p0+2], v3 = s_a[p0+3];
        float c0 = v0, c1 = c0 + v1, c2 = c1 + v2, c3 = c2 + v3;
        float d0 = v0*v0, d1 = d0 + v1*v1, d2 = d1 + v2*v2, d3 = d2 + v3*v3;
        float s = c3, s2 = d3;
        const float tot = c3, tot2 = d3;
        for (int o = 1; o < 32; o <<= 1) {
            float n  = __shfl_up_sync(0xffffffffu, s, o);
            float n2 = __shfl_up_sync(0xffffffffu, s2, o);
            if (lane >= o) { s += n; s2 += n2; }
        }
        if (lane == 31) { red[wid] = s; red2[wid] = s2; }
        __syncthreads();
        if (wid == 0) {
            float w = red[lane], w2 = red2[lane];
            for (int o = 1; o < 32; o <<= 1) {
                float n  = __shfl_up_sync(0xffffffffu, w, o);
                float n2 = __shfl_up_sync(0xffffffffu, w2, o);
                if (lane >= o) { w += n; w2 += n2; }
            }
            red[lane] = w; red2[lane] = w2;
        }
        __syncthreads();
        float base  = (wid ? red[wid-1]  : 0.f) + (s  - tot);
        float base2 = (wid ? red2[wid-1] : 0.f) + (s2 - tot2);
        s_cum[p0+0] = base + c0;  s_cum[p0+1] = base + c1;
        s_cum[p0+2] = base + c2;  s_cum[p0+3] = base + c3;
        s_cum2[p0+0] = base2 + d0; s_cum2[p0+1] = base2 + d1;
        s_cum2[p0+2] = base2 + d2; s_cum2[p0+3] = base2 + d3;
    }
    __syncthreads();

    int cnt = 0;
#pragma unroll
    for (int j = 0; j < 4; j++) {
        int p = p0 + j;
        float rho = (float)(p + 1);
        float mean = s_cum[p] / rho;
        float msq  = s_cum2[p] / rho;
        float ssv  = rho * (msq - mean*mean);
        float delta = (1.f - ssv) / rho;
        float tau = mean - sqrtf(fmaxf(delta, 0.f));
        cnt += (tau <= s_a[p]) ? 1 : 0;
    }
    for (int o = 16; o; o >>= 1) cnt += __shfl_xor_sync(0xffffffffu, cnt, o);
    if (lane == 0) atomicAdd(&sh_support, cnt);
    __syncthreads();
    if (tid == 0) {
        int p = sh_support - 1;
        float rho = (float)(p + 1);
        float mean = s_cum[p] / rho;
        float msq  = s_cum2[p] / rho;
        float ssv  = rho * (msq - mean*mean);
        float delta = (1.f - ssv) / rho;
        sh_tau = mean - sqrtf(fmaxf(delta, 0.f));
    }
    __syncthreads();
    const float taustar = sh_tau;

    for (int t = tid; t < TT; t += 1024) {
        float x = (s_scores[t] - mx) * 0.5f;
        float dd = fmaxf(x - taustar, 0.f);
        out[row*TT + t] = dd*dd*s_attn[t];
    }
    __syncthreads();

    // ---- gumbel-perturbed scores
    for (int t = tid; t < TT; t += 1024) {
        float gum = gumbel_of((uint32_t)(row*TT + t));
        float pert = s_scores[t] * s_attn[t] + gum;
        s_cum[t] = pert;
        s_a[t] = (pert != pert) ? __int_as_float(0xff800000) : pert;
    }
    bitonic_desc(s_a, tid, 1024);

    const float teff = sh_teff;
    float kf = rintf(0.3f * teff);
    kf = fminf(fmaxf(kf, 1.f), fmaxf(teff, 1.f));
    const int ki = (int)kf;
    if (tid == 0) sh_thr = s_a[ki - 1];
    __syncthreads();
    const float thr = sh_thr;
    const float hiW = thr + EPS_W, loW = thr - EPS_W;

    // ---- classification counts + candidate gather
    {
        int my_above = 0;
        for (int t = tid; t < TT; t += 1024) {
            float p = s_cum[t];
            if (p > hiW) my_above++;
            else if (p >= loW) {
                int pos = atomicAdd(&sh_ncand, 1);
                if (pos < MAXC) cand_idx[pos] = t;
            }
        }
        for (int o = 16; o; o >>= 1) my_above += __shfl_xor_sync(0xffffffffu, my_above, o);
        if (lane == 0) atomicAdd(&sh_above, my_above);
    }
    __syncthreads();
    const int ncand = sh_ncand;
    const bool refine = (ncand <= MAXC);

    // ---- exact recompute of candidate perts (warp per candidate)
    if (refine) {
        const float b2v = b2[0];
        for (int c = wid; c < ncand; c += 32) {
            int t = cand_idx[c];
            float ex;
            if (s_attn[t] == 0.f) {
                ex = s_cum[t];    // masked: pert = gumbel, already exact
            } else {
                const float4* e4 = (const float4*)(emb + ((size_t)row*TT + t)*DD);
                float4 va = e4[lane*2], vb = e4[lane*2+1];
                float s  = va.x+va.y+va.z+va.w+vb.x+vb.y+vb.z+vb.w;
                float s2 = va.x*va.x+va.y*va.y+va.z*va.z+va.w*va.w
                         + vb.x*vb.x+vb.y*vb.y+vb.z*vb.z+vb.w*vb.w;
#pragma unroll
                for (int o = 16; o; o >>= 1) {
                    s  += __shfl_xor_sync(0xffffffffu, s, o);
                    s2 += __shfl_xor_sync(0xffffffffu, s2, o);
                }
                float mu = s * (1.f/256.f);
                float rstd = rsqrtf(s2 * (1.f/256.f) - mu*mu + 1e-5f);
                float xv[8] = {va.x,va.y,va.z,va.w,vb.x,vb.y,vb.z,vb.w};
                float* xw = s_xn + wid*256 + lane*8;
#pragma unroll
                for (int p = 0; p < 8; ++p) {
                    int d = lane*8 + p;
                    xw[p] = (xv[p] - mu) * rstd * gamma_[d] + beta_[d];
                }
                __syncwarp();
                float sc = 0.f;
                for (int h = lane; h < HH; h += 32) {
                    const float4* wr = (const float4*)(g_w1t32 + (size_t)h*DD);
                    const float4* xr = (const float4*)(s_xn + wid*256);
                    float dot = 0.f;
#pragma unroll 8
                    for (int u = 0; u < 64; ++u) {
                        float4 a = wr[u], bq = xr[u];
                        dot += a.x*bq.x + a.y*bq.y + a.z*bq.z + a.w*bq.w;
                    }
                    float v = dot + g_b1p[h];
                    sc += gelu_w2(v, g_w2p[h]);
                }
#pragma unroll
                for (int o = 16; o; o >>= 1) sc += __shfl_xor_sync(0xffffffffu, sc, o);
                float score = sc + b2v;
                float pert = score + gumbel_of((uint32_t)(row*TT + t));  // attn==1
                ex = pert;
                __syncwarp();
            }
            if (lane == 0) cand_pert[c] = ex;
        }
    }
    __syncthreads();

    // ---- select top-'need' among candidates (rank by strict greater)
    if (refine && tid == 0) {
        int need = ki - sh_above;
        for (int c = 0; c < ncand; ++c) {
            int rank = 0;
            float pc = cand_pert[c];
            for (int c2 = 0; c2 < ncand; ++c2)
                if (cand_pert[c2] > pc) rank++;
            cand_sel[c] = (rank < need) ? 1 : 0;
        }
    }
    __syncthreads();

    // ---- g output (store into s_a for TV)
    for (int t = tid; t < TT; t += 1024) {
        float p = s_cum[t];
        float a0 = s_attn[t];
        float gv;
        if (refine) {
            if (p > hiW) gv = a0;
            else if (p >= loW) {
                gv = 0.f;
                for (int c = 0; c < ncand; ++c)
                    if (cand_idx[c] == t) { gv = cand_sel[c] ? a0 : 0.f; break; }
            } else gv = 0.f;
        } else {
            gv = (p >= thr) ? a0 : 0.f;
        }
        out[BT + row*TT + t] = gv;
        s_a[t] = gv;
    }
    __syncthreads();

    // ---- TV
    float num = 0.f, den = 0.f;
    for (int t = tid; t < TT - 1; t += 1024) {
        float valid = s_attn[t] * s_attn[t+1];
        num += fabsf(s_a[t+1] - s_a[t]) * valid;
        den += valid;
    }
    for (int o = 16; o; o >>= 1) {
        num += __shfl_xor_sync(0xffffffffu, num, o);
        den += __shfl_xor_sync(0xffffffffu, den, o);
    }
    if (lane == 0) { red[wid] = num; red2[wid] = den; }
    __syncthreads();
    if (tid == 0) {
        float a = 0.f, b = 0.f;
        for (int w = 0; w < 32; w++) { a += red[w]; b += red2[w]; }
        g_tv[row] = a / fmaxf(b, 1.f);
    }
}

__global__ void kernelC(float* __restrict__ out)
{
    __shared__ float r[64];
    r[threadIdx.x] = g_tv[threadIdx.x];
    __syncthreads();
    if (threadIdx.x == 0) {
        float s = 0.f;
        for (int i = 0; i < 64; i++) s += r[i];
        out[2*BT] = 0.1f * (s / 64.f);
    }
}

extern "C" void kernel_launch(void* const* d_in, const int* in_sizes, int n_in,
                              void* d_out, int out_size)
{
    const float* emb   = (const float*)d_in[0];
    const float* attn  = (const float*)d_in[1];
    const float* gamma = (const float*)d_in[2];
    const float* beta  = (const float*)d_in[3];
    const float* W1    = (const float*)d_in[4];
    const float* b1    = (const float*)d_in[5];
    const float* W2    = (const float*)d_in[6];
    const float* b2    = (const float*)d_in[7];
    float* out = (float*)d_out;

    cudaFuncSetAttribute(kernelA, cudaFuncAttributeMaxDynamicSharedMemorySize, SMEM_A_TOT);
    cudaFuncSetAttribute(kernelB, cudaFuncAttributeMaxDynamicSharedMemorySize, SMEM_B);

    kernelW<<<NP, 256>>>(W1, b1, W2);
    kernelA<<<BT/128, 256, SMEM_A_TOT>>>(emb, attn, gamma, beta, b2);
    kernelB<<<BB, 1024, SMEM_B>>>(attn, emb, gamma, beta, b2, out);
    kernelC<<<1, 64>>>(out);
}

// round 9
// speedup vs baseline: 3.0973x; 1.0067x over previous
#include <cuda_runtime.h>
#include <cuda_bf16.h>
#include <cstdint>
#include <math.h>

// Problem constants
#define BB 64
#define TT 4096
#define DD 256
#define HH 341
#define BT (BB*TT)
#define NEGV (-1e9f)
#define NP 384            // hidden padded to 12*32
#define NCHUNK 12         // 32 n-cols per chunk

__device__ float g_scores[BT];
__device__ float g_tv[BB];
__device__ __align__(16) __nv_bfloat16 g_w1t_hi[NP*DD];  // W1^T [h][d] bf16 hi
__device__ __align__(16) __nv_bfloat16 g_w1t_lo[NP*DD];  // bf16 lo residual
__device__ __align__(16) float g_w1t32[NP*DD];           // W1^T fp32 (refinement)
__device__ float g_b1p[NP];
__device__ float g_w2p[NP];

#define MMA16816(d, a0,a1,a2,a3, b0,b1) \
    asm volatile("mma.sync.aligned.m16n8k16.row.col.f32.bf16.bf16.f32 " \
        "{%0,%1,%2,%3}, {%4,%5,%6,%7}, {%8,%9}, {%0,%1,%2,%3};" \
        : "+f"((d)[0]), "+f"((d)[1]), "+f"((d)[2]), "+f"((d)[3]) \
        : "r"(a0), "r"(a1), "r"(a2), "r"(a3), "r"(b0), "r"(b1))

#define LDSM_X4(r0,r1,r2,r3, addr) \
    asm volatile("ldmatrix.sync.aligned.m8n8.x4.shared.b16 {%0,%1,%2,%3}, [%4];" \
        : "=r"(r0), "=r"(r1), "=r"(r2), "=r"(r3) : "r"(addr))

#define CP_ASYNC16(dst, src) \
    asm volatile("cp.async.cg.shared.global [%0], [%1], 16;" :: "r"(dst), "l"(src))
#define CP_COMMIT() asm volatile("cp.async.commit_group;" ::: "memory")
#define CP_WAIT(n)  asm volatile("cp.async.wait_group %0;" :: "n"(n) : "memory")

__device__ __forceinline__ uint32_t smem_u32(const void* p) {
    uint32_t a;
    asm("{ .reg .u64 t; cvta.to.shared.u64 t, %1; cvt.u32.u64 %0, t; }" : "=r"(a) : "l"(p));
    return a;
}
__device__ __forceinline__ uint32_t packbf(__nv_bfloat16 a, __nv_bfloat16 b) {
    return (uint32_t)__bfloat16_as_ushort(a) | ((uint32_t)__bfloat16_as_ushort(b) << 16);
}
__device__ __forceinline__ float gelu_w2(float v, float w2v) {
    return 0.5f*v*(1.f + erff(v*0.70710678118654752f)) * w2v;
}

// ---------------------------------------------------------------------------
// Prologue: transpose + bf16-split W1 (zero-padded to NP), pad b1/W2
// ---------------------------------------------------------------------------
__global__ void kernelW(const float* __restrict__ W1, const float* __restrict__ b1,
                        const float* __restrict__ W2)
{
    int h = blockIdx.x;       // 0..383
    int d = threadIdx.x;      // 0..255
    float w = (h < HH) ? W1[d*HH + h] : 0.f;
    __nv_bfloat16 hi = __float2bfloat16(w);
    __nv_bfloat16 lo = __float2bfloat16(w - __bfloat162float(hi));
    g_w1t_hi[h*DD + d] = hi;
    g_w1t_lo[h*DD + d] = lo;
    g_w1t32[h*DD + d] = w;
    if (d == 0) {
        g_b1p[h] = (h < HH) ? b1[h] : 0.f;
        g_w2p[h] = (h < HH) ? W2[h] : 0.f;
    }
}

// ---------------------------------------------------------------------------
// Kernel A: emb*attn -> LN -> ldmatrix+mma bf16 3-term GEMM -> GELU -> dot W2
// Block = 128 tokens, 512 threads (16 warps: 8 m-tiles x 2 n-halves).
// B chunks (32 n) double-buffered via cp.async. Early-exit on dead tiles.
// ---------------------------------------------------------------------------
#define RP 528            // padded row pitch (bytes), 256 bf16 = 512B data
#define OFF_AHI 0
#define OFF_ALO 67584
#define OFF_B0  135168    // buf: hi 32*RP (16896) + lo 16896 = 33792; 2 bufs
#define BUFSZ   33792
#define OFF_ATTN 202752
#define OFF_B1P 203264
#define OFF_W2P 204800
#define OFF_SC  206336
#define OFF_ANY 206848
#define SMEM_A_TOT 206912

extern __shared__ char smx[];

__device__ __forceinline__ void stage_B(int c, int buf, int tid, uint32_t sb) {
    // chunk c: rows [c*32, c*32+32) of g_w1t_{hi,lo}, 32 uint4 per row
#pragma unroll
    for (int i = 0; i < 4; ++i) {
        int v = tid + i*512;              // 0..2047
        int half = v >> 10;               // 0=hi, 1=lo
        int r = (v >> 5) & 31;
        int u = v & 31;
        const uint4* src = (half ? (const uint4*)g_w1t_lo : (const uint4*)g_w1t_hi)
                         + (size_t)(c*32 + r)*32 + u;
        uint32_t dst = sb + OFF_B0 + buf*BUFSZ + half*16896 + r*RP + u*16;
        CP_ASYNC16(dst, src);
    }
}

__global__ __launch_bounds__(512, 1)
void kernelA(const float* __restrict__ emb, const float* __restrict__ attn,
             const float* __restrict__ gamma_, const float* __restrict__ beta_,
             const float* __restrict__ b2)
{
    const int tid = threadIdx.x, lane = tid & 31, wid = tid >> 5;
    const int base = blockIdx.x * 128;
    uint32_t sb = smem_u32(smx);

    float* s_attn = (float*)(smx + OFF_ATTN);
    float* s_b1p  = (float*)(smx + OFF_B1P);
    float* s_w2p  = (float*)(smx + OFF_W2P);
    float* s_sc   = (float*)(smx + OFF_SC);
    int*   s_any  = (int*)(smx + OFF_ANY);

    if (tid == 0) *s_any = 0;
    __syncthreads();
    if (tid < 128) {
        float a = attn[base + tid];
        s_attn[tid] = a;
        s_sc[tid] = 0.f;
        if (a != 0.f) *s_any = 1;   // benign race
    }
    __syncthreads();
    if (!*s_any) {
        if (tid < 128) g_scores[base + tid] = NEGV;
        return;
    }

    // kick off B chunk 0 while we build A
    stage_B(0, 0, tid, sb);
    CP_COMMIT();

    if (tid < NP) { s_b1p[tid] = g_b1p[tid]; s_w2p[tid] = g_w2p[tid]; }

    // ---- LN + bf16 hi/lo split -> A tiles (warp w owns tokens 8w..8w+7)
    for (int it = 0; it < 8; ++it) {
        int mt = wid * 8 + it;
        const float4* e4 = (const float4*)(emb + (size_t)(base + mt) * DD);
        float4 va = e4[lane*2], vb = e4[lane*2 + 1];
        float am = s_attn[mt];
        va.x *= am; va.y *= am; va.z *= am; va.w *= am;
        vb.x *= am; vb.y *= am; vb.z *= am; vb.w *= am;
        float s  = va.x+va.y+va.z+va.w+vb.x+vb.y+vb.z+vb.w;
        float s2 = va.x*va.x+va.y*va.y+va.z*va.z+va.w*va.w
                 + vb.x*vb.x+vb.y*vb.y+vb.z*vb.z+vb.w*vb.w;
#pragma unroll
        for (int o = 16; o; o >>= 1) {
            s  += __shfl_xor_sync(0xffffffffu, s, o);
            s2 += __shfl_xor_sync(0xffffffffu, s2, o);
        }
        float mu = s * (1.f/256.f);
        float rstd = rsqrtf(s2 * (1.f/256.f) - mu*mu + 1e-5f);

        float x[8] = {va.x, va.y, va.z, va.w, vb.x, vb.y, vb.z, vb.w};
        uint32_t qh[4], ql[4];
        const int d0 = lane * 8;
#pragma unroll
        for (int p = 0; p < 4; ++p) {
            float x0 = (x[2*p]   - mu) * rstd * gamma_[d0+2*p]   + beta_[d0+2*p];
            float x1 = (x[2*p+1] - mu) * rstd * gamma_[d0+2*p+1] + beta_[d0+2*p+1];
            __nv_bfloat16 h0 = __float2bfloat16(x0);
            __nv_bfloat16 h1 = __float2bfloat16(x1);
            __nv_bfloat16 l0 = __float2bfloat16(x0 - __bfloat162float(h0));
            __nv_bfloat16 l1 = __float2bfloat16(x1 - __bfloat162float(h1));
            qh[p] = packbf(h0, h1);
            ql[p] = packbf(l0, l1);
        }
        uint32_t off = mt * RP + lane * 16;
        *(uint4*)(smx + OFF_AHI + off) = make_uint4(qh[0],qh[1],qh[2],qh[3]);
        *(uint4*)(smx + OFF_ALO + off) = make_uint4(ql[0],ql[1],ql[2],ql[3]);
    }

    const int wm = wid & 7;        // m-tile
    const int wn = wid >> 3;       // n-half (0/1)
    const int m0 = wm * 16;
    const int g = lane >> 2, q = lane & 3;
    const int lrow = lane & 15;
    const int lcol = (lane >> 4) * 16;

    const uint32_t aAddrHi = sb + OFF_AHI + (m0 + lrow) * RP + lcol;
    const uint32_t aAddrLo = sb + OFF_ALO + (m0 + lrow) * RP + lcol;
    const uint32_t bRowOff = (wn*16 + lrow) * RP + lcol;

    float part0 = 0.f, part1 = 0.f;

    for (int c = 0; c < NCHUNK; ++c) {
        if (c + 1 < NCHUNK) { stage_B(c+1, (c+1) & 1, tid, sb); CP_COMMIT(); }
        if (c + 1 < NCHUNK) CP_WAIT(1); else CP_WAIT(0);
        __syncthreads();

        const uint32_t bHi = sb + OFF_B0 + (c & 1)*BUFSZ + bRowOff;
        const uint32_t bLo = bHi + 16896;

        float acc0[4] = {0.f,0.f,0.f,0.f};
        float acc1[4] = {0.f,0.f,0.f,0.f};

#pragma unroll 4
        for (int ks = 0; ks < 16; ++ks) {
            const int kb = ks * 32;
            uint32_t ah0,ah1,ah2,ah3, al0,al1,al2,al3;
            uint32_t bh0,bh1,bh2,bh3, bl0,bl1,bl2,bl3;
            LDSM_X4(ah0,ah1,ah2,ah3, aAddrHi + kb);
            LDSM_X4(al0,al1,al2,al3, aAddrLo + kb);
            LDSM_X4(bh0,bh1,bh2,bh3, bHi + kb);
            LDSM_X4(bl0,bl1,bl2,bl3, bLo + kb);
            // j0 (n rows 0-7 of half): b = (r0, r2); j1: (r1, r3)
            MMA16816(acc0, ah0,ah1,ah2,ah3, bh0,bh2);
            MMA16816(acc0, ah0,ah1,ah2,ah3, bl0,bl2);
            MMA16816(acc0, al0,al1,al2,al3, bh0,bh2);
            MMA16816(acc1, ah0,ah1,ah2,ah3, bh1,bh3);
            MMA16816(acc1, ah0,ah1,ah2,ah3, bl1,bl3);
            MMA16816(acc1, al0,al1,al2,al3, bh1,bh3);
        }

        // epilogue: bias + gelu + * W2 (padded h contributes 0)
        {
            int hb = c*32 + wn*16 + 2*q;
            float b1a = s_b1p[hb],   w2a = s_w2p[hb];
            float b1b = s_b1p[hb+1], w2b = s_w2p[hb+1];
            part0 += gelu_w2(acc0[0] + b1a, w2a) + gelu_w2(acc0[1] + b1b, w2b);
            part1 += gelu_w2(acc0[2] + b1a, w2a) + gelu_w2(acc0[3] + b1b, w2b);
            int hc = hb + 8;
            float b1c = s_b1p[hc],   w2c = s_w2p[hc];
            float b1d = s_b1p[hc+1], w2d = s_w2p[hc+1];
            part0 += gelu_w2(acc1[0] + b1c, w2c) + gelu_w2(acc1[1] + b1d, w2d);
            part1 += gelu_w2(acc1[2] + b1c, w2c) + gelu_w2(acc1[3] + b1d, w2d);
        }
        __syncthreads();   // all warps done with buf (c&1) before overwrite
    }

    // reduce across 4 q-lanes, then cross-warp (2 n-halves) via smem atomics
    part0 += __shfl_xor_sync(0xffffffffu, part0, 1);
    part0 += __shfl_xor_sync(0xffffffffu, part0, 2);
    part1 += __shfl_xor_sync(0xffffffffu, part1, 1);
    part1 += __shfl_xor_sync(0xffffffffu, part1, 2);
    if (q == 0) {
        atomicAdd(&s_sc[m0 + g], part0);
        atomicAdd(&s_sc[m0 + g + 8], part1);
    }
    __syncthreads();
    if (tid < 128) {
        float sc = s_sc[tid] + b2[0];
        if (s_attn[tid] == 0.f) sc = NEGV;
        g_scores[base + tid] = sc;
    }
}

// ---------------------------------------------------------------------------
// Threefry-2x32-20, JAX partitionable: ctr=(0,i), draw = out0 ^ out1
// ---------------------------------------------------------------------------
__device__ __forceinline__ uint32_t rotl32(uint32_t x, int r) { return (x << r) | (x >> (32 - r)); }
__device__ __forceinline__ void tf_r4(uint32_t& x0, uint32_t& x1, int a, int b, int c, int d) {
    x0 += x1; x1 = rotl32(x1, a); x1 ^= x0;
    x0 += x1; x1 = rotl32(x1, b); x1 ^= x0;
    x0 += x1; x1 = rotl32(x1, c); x1 ^= x0;
    x0 += x1; x1 = rotl32(x1, d); x1 ^= x0;
}
__device__ __forceinline__ uint32_t jax_bits(uint32_t i) {
    const uint32_t k0 = 0u, k1 = 42u;
    const uint32_t k2 = k0 ^ k1 ^ 0x1BD11BDAu;
    uint32_t x0 = 0u + k0;
    uint32_t x1 = i  + k1;
    tf_r4(x0, x1, 13, 15, 26, 6);   x0 += k1; x1 += k2 + 1u;
    tf_r4(x0, x1, 17, 29, 16, 24);  x0 += k2; x1 += k0 + 2u;
    tf_r4(x0, x1, 13, 15, 26, 6);   x0 += k0; x1 += k1 + 3u;
    tf_r4(x0, x1, 17, 29, 16, 24);  x0 += k1; x1 += k2 + 4u;
    tf_r4(x0, x1, 13, 15, 26, 6);   x0 += k2; x1 += k0 + 5u;
    return x0 ^ x1;
}
__device__ __forceinline__ float gumbel_of(uint32_t lin) {
    uint32_t bits = jax_bits(lin);
    float u = __uint_as_float((bits >> 9) | 0x3f800000u) - 1.0f;
    u = fmaxf(u, 0.f);
    return -logf(-logf(u + 1e-6f) + 1e-6f);
}

__device__ void bitonic_desc(float* a, int tid, int nthr) {
    for (int k = 2; k <= 4096; k <<= 1) {
        for (int j = k >> 1; j > 0; j >>= 1) {
            __syncthreads();
            for (int i = tid; i < 4096; i += nthr) {
                int ixj = i ^ j;
                if (ixj > i) {
                    float x = a[i], y = a[ixj];
                    bool up = ((i & k) == 0);
                    if (up ? (x < y) : (x > y)) { a[i] = y; a[ixj] = x; }
                }
            }
        }
    }
    __syncthreads();
}

// ---------------------------------------------------------------------------
// Kernel B: entmax1.5 + gumbel top-k with EXACT boundary refinement + TV
// ---------------------------------------------------------------------------
#define EPS_W 5e-4f
#define MAXC 64
#define SMEM_B ((5*4096 + 32*256)*4)

__global__ __launch_bounds__(1024, 1)
void kernelB(const float* __restrict__ attn, const float* __restrict__ emb,
             const float* __restrict__ gamma_, const float* __restrict__ beta_,
             const float* __restrict__ b2, float* __restrict__ out)
{
    extern __shared__ float sm[];
    float* s_scores = sm;
    float* s_attn   = sm + 4096;
    float* s_a      = sm + 8192;
    float* s_cum    = sm + 12288;
    float* s_cum2   = sm + 16384;
    float* s_xn     = sm + 20480;     // [32 warps][256]
    __shared__ float red[32], red2[32];
    __shared__ float sh_mx, sh_teff, sh_tau, sh_thr;
    __shared__ int sh_support, sh_above, sh_ncand;
    __shared__ int cand_idx[MAXC];
    __shared__ float cand_pert[MAXC];
    __shared__ int cand_sel[MAXC];

    const int row = blockIdx.x;
    const int tid = threadIdx.x;
    const int lane = tid & 31, wid = tid >> 5;

    float tf_ = 0.f, mx = -3.402823466e38f;
    for (int t = tid; t < TT; t += 1024) {
        float s = g_scores[row*TT + t];
        float a = attn[row*TT + t];
        s_scores[t] = s; s_attn[t] = a;
        tf_ += a; mx = fmaxf(mx, s);
    }
    for (int o = 16; o; o >>= 1) {
        tf_ += __shfl_xor_sync(0xffffffffu, tf_, o);
        mx = fmaxf(mx, __shfl_xor_sync(0xffffffffu, mx, o));
    }
    if (lane == 0) { red[wid] = tf_; red2[wid] = mx; }
    __syncthreads();
    if (tid == 0) {
        float a = 0.f, b = -3.402823466e38f;
        for (int w = 0; w < 32; w++) { a += red[w]; b = fmaxf(b, red2[w]); }
        sh_teff = a; sh_mx = b;
        sh_support = 0; sh_above = 0; sh_ncand = 0;
    }
    __syncthreads();
    mx = sh_mx;

    // ---- entmax 1.5
    for (int t = tid; t < TT; t += 1024) s_a[t] = (s_scores[t] - mx) * 0.5f;
    bitonic_desc(s_a, tid, 1024);

    const int p0 = tid * 4;
    {
        float v0 = s_a[p0+0], v1 = s_a[p0+1], v2 = s_a[p0+2], v3 = s_a[p0+3];
        float c0 = v0, c1 = c0 + v1, c2 = c1 + v2, c3 = c2 + v3;
        float d0 = v0*v0, d1 = d0 + v1*v1, d2 = d1 + v2*v2, d3 = d2 + v3*v3;
        float s = c3, s2 = d3;
        const float tot = c3, tot2 = d3;
        for (int o = 1; o < 32; o <<= 1) {
            float n  = __shfl_up_sync(0xffffffffu, s, o);
            float n2 = __shfl_up_sync(0xffffffffu, s2, o);
            if (lane >= o) { s += n; s2 += n2; }
        }
        if (lane == 31) { red[wid] = s; red2[wid] = s2; }
        __syncthreads();
        if (wid == 0) {
            float w = red[lane], w2 = red2[lane];
            for (int o = 1; o < 32; o <<= 1) {
                float n  = __shfl_up_sync(0xffffffffu, w, o);
                float n2 = __shfl_up_sync(0xffffffffu, w2, o);
                if (lane >= o) { w += n; w2 += n2; }
            }
            red[lane] = w; red2[lane] = w2;
        }
        __syncthreads();
        float base  = (wid ? red[wid-1]  : 0.f) + (s  - tot);
        float base2 = (wid ? red2[wid-1] : 0.f) + (s2 - tot2);
        s_cum[p0+0] = base + c0;  s_cum[p0+1] = base + c1;
        s_cum[p0+2] = base + c2;  s_cum[p0+3] = base + c3;
        s_cum2[p0+0] = base2 + d0; s_cum2[p0+1] = base2 + d1;
        s_cum2[p0+2] = base2 + d2; s_cum2[p0+3] = base2 + d3;
    }
    __syncthreads();

    int cnt = 0;
#pragma unroll
    for (int j = 0; j < 4; j++) {
        int p = p0 + j;
        float rho = (float)(p + 1);
        float mean = s_cum[p] / rho;
        float msq  = s_cum2[p] / rho;
        float ssv  = rho * (msq - mean*mean);
        float delta = (1.f - ssv) / rho;
        float tau = mean - sqrtf(fmaxf(delta, 0.f));
        cnt += (tau <= s_a[p]) ? 1 : 0;
    }
    for (int o = 16; o; o >>= 1) cnt += __shfl_xor_sync(0xffffffffu, cnt, o);
    if (lane == 0) atomicAdd(&sh_support, cnt);
    __syncthreads();
    if (tid == 0) {
        int p = sh_support - 1;
        float rho = (float)(p + 1);
        float mean = s_cum[p] / rho;
        float msq  = s_cum2[p] / rho;
        float ssv  = rho * (msq - mean*mean);
        float delta = (1.f - ssv) / rho;
        sh_tau = mean - sqrtf(fmaxf(delta, 0.f));
    }
    __syncthreads();
    const float taustar = sh_tau;

    for (int t = tid; t < TT; t += 1024) {
        float x = (s_scores[t] - mx) * 0.5f;
        float dd = fmaxf(x - taustar, 0.f);
        out[row*TT + t] = dd*dd*s_attn[t];
    }
    __syncthreads();

    // ---- gumbel-perturbed scores
    for (int t = tid; t < TT; t += 1024) {
        float gum = gumbel_of((uint32_t)(row*TT + t));
        float pert = s_scores[t] * s_attn[t] + gum;
        s_cum[t] = pert;
        s_a[t] = (pert != pert) ? __int_as_float(0xff800000) : pert;
    }
    bitonic_desc(s_a, tid, 1024);

    const float teff = sh_teff;
    float kf = rintf(0.3f * teff);
    kf = fminf(fmaxf(kf, 1.f), fmaxf(teff, 1.f));
    const int ki = (int)kf;
    if (tid == 0) sh_thr = s_a[ki - 1];
    __syncthreads();
    const float thr = sh_thr;
    const float hiW = thr + EPS_W, loW = thr - EPS_W;

    // ---- classification counts + candidate gather
    {
        int my_above = 0;
        for (int t = tid; t < TT; t += 1024) {
            float p = s_cum[t];
            if (p > hiW) my_above++;
            else if (p >= loW) {
                int pos = atomicAdd(&sh_ncand, 1);
                if (pos < MAXC) cand_idx[pos] = t;
            }
        }
        for (int o = 16; o; o >>= 1) my_above += __shfl_xor_sync(0xffffffffu, my_above, o);
        if (lane == 0) atomicAdd(&sh_above, my_above);
    }
    __syncthreads();
    const int ncand = sh_ncand;
    const bool refine = (ncand <= MAXC);

    // ---- exact recompute of candidate perts (warp per candidate)
    if (refine) {
        const float b2v = b2[0];
        for (int c = wid; c < ncand; c += 32) {
            int t = cand_idx[c];
            float ex;
            if (s_attn[t] == 0.f) {
                ex = s_cum[t];    // masked: pert = gumbel, already exact
            } else {
                const float4* e4 = (const float4*)(emb + ((size_t)row*TT + t)*DD);
                float4 va = e4[lane*2], vb = e4[lane*2+1];
                float s  = va.x+va.y+va.z+va.w+vb.x+vb.y+vb.z+vb.w;
                float s2 = va.x*va.x+va.y*va.y+va.z*va.z+va.w*va.w
                         + vb.x*vb.x+vb.y*vb.y+vb.z*vb.z+vb.w*vb.w;
#pragma unroll
                for (int o = 16; o; o >>= 1) {
                    s  += __shfl_xor_sync(0xffffffffu, s, o);
                    s2 += __shfl_xor_sync(0xffffffffu, s2, o);
                }
                float mu = s * (1.f/256.f);
                float rstd = rsqrtf(s2 * (1.f/256.f) - mu*mu + 1e-5f);
                float xv[8] = {va.x,va.y,va.z,va.w,vb.x,vb.y,vb.z,vb.w};
                float* xw = s_xn + wid*256 + lane*8;
#pragma unroll
                for (int p = 0; p < 8; ++p) {
                    int d = lane*8 + p;
                    xw[p] = (xv[p] - mu) * rstd * gamma_[d] + beta_[d];
                }
                __syncwarp();
                float sc = 0.f;
                for (int h = lane; h < HH; h += 32) {
                    const float4* wr = (const float4*)(g_w1t32 + (size_t)h*DD);
                    const float4* xr = (const float4*)(s_xn + wid*256);
                    float dot = 0.f;
#pragma unroll 8
                    for (int u = 0; u < 64; ++u) {
                        float4 a = wr[u], bq = xr[u];
                        dot += a.x*bq.x + a.y*bq.y + a.z*bq.z + a.w*bq.w;
                    }
                    float v = dot + g_b1p[h];
                    sc += gelu_w2(v, g_w2p[h]);
                }
#pragma unroll
                for (int o = 16; o; o >>= 1) sc += __shfl_xor_sync(0xffffffffu, sc, o);
                float score = sc + b2v;
                float pert = score + gumbel_of((uint32_t)(row*TT + t));  // attn==1
                ex = pert;
                __syncwarp();
            }
            if (lane == 0) cand_pert[c] = ex;
        }
    }
    __syncthreads();

    // ---- select top-'need' among candidates (rank by strict greater)
    if (refine && tid == 0) {
        int need = ki - sh_above;
        for (int c = 0; c < ncand; ++c) {
            int rank = 0;
            float pc = cand_pert[c];
            for (int c2 = 0; c2 < ncand; ++c2)
                if (cand_pert[c2] > pc) rank++;
            cand_sel[c] = (rank < need) ? 1 : 0;
        }
    }
    __syncthreads();

    // ---- g output (store into s_a for TV)
    for (int t = tid; t < TT; t += 1024) {
        float p = s_cum[t];
        float a0 = s_attn[t];
        float gv;
        if (refine) {
            if (p > hiW) gv = a0;
            else if (p >= loW) {
                gv = 0.f;
                for (int c = 0; c < ncand; ++c)
                    if (cand_idx[c] == t) { gv = cand_sel[c] ? a0 : 0.f; break; }
            } else gv = 0.f;
        } else {
            gv = (p >= thr) ? a0 : 0.f;
        }
        out[BT + row*TT + t] = gv;
        s_a[t] = gv;
    }
    __syncthreads();

    // ---- TV
    float num = 0.f, den = 0.f;
    for (int t = tid; t < TT - 1; t += 1024) {
        float valid = s_attn[t] * s_attn[t+1];
        num += fabsf(s_a[t+1] - s_a[t]) * valid;
        den += valid;
    }
    for (int o = 16; o; o >>= 1) {
        num += __shfl_xor_sync(0xffffffffu, num, o);
        den += __shfl_xor_sync(0xffffffffu, den, o);
    }
    if (lane == 0) { red[wid] = num; red2[wid] = den; }
    __syncthreads();
    if (tid == 0) {
        float a = 0.f, b = 0.f;
        for (int w = 0; w < 32; w++) { a += red[w]; b += red2[w]; }
        g_tv[row] = a / fmaxf(b, 1.f);
    }
}

__global__ void kernelC(float* __restrict__ out)
{
    __shared__ float r[64];
    r[threadIdx.x] = g_tv[threadIdx.x];
    __syncthreads();
    if (threadIdx.x == 0) {
        float s = 0.f;
        for (int i = 0; i < 64; i++) s += r[i];
        out[2*BT] = 0.1f * (s / 64.f);
    }
}

extern "C" void kernel_launch(void* const* d_in, const int* in_sizes, int n_in,
                              void* d_out, int out_size)
{
    const float* emb   = (const float*)d_in[0];
    const float* attn  = (const float*)d_in[1];
    const float* gamma = (const float*)d_in[2];
    const float* beta  = (const float*)d_in[3];
    const float* W1    = (const float*)d_in[4];
    const float* b1    = (const float*)d_in[5];
    const float* W2    = (const float*)d_in[6];
    const float* b2    = (const float*)d_in[7];
    float* out = (float*)d_out;

    cudaFuncSetAttribute(kernelA, cudaFuncAttributeMaxDynamicSharedMemorySize, SMEM_A_TOT);
    cudaFuncSetAttribute(kernelB, cudaFuncAttributeMaxDynamicSharedMemorySize, SMEM_B);

    kernelW<<<NP, 256>>>(W1, b1, W2);
    kernelA<<<BT/128, 512, SMEM_A_TOT>>>(emb, attn, gamma, beta, b2);
    kernelB<<<BB, 1024, SMEM_B>>>(attn, emb, gamma, beta, b2, out);
    kernelC<<<1, 64>>>(out);
}

// round 10
// speedup vs baseline: 3.2263x; 1.0416x over previous
#include <cuda_runtime.h>
#include <cuda_bf16.h>
#include <cstdint>
#include <math.h>

// Problem constants
#define BB 64
#define TT 4096
#define DD 256
#define HH 341
#define BT (BB*TT)
#define NEGV (-1e9f)
#define NP 352            // hidden padded to 11*32
#define NCHUNK 11         // 32 n-cols per chunk

__device__ float g_scores[BT];
__device__ float g_tv[BB];
__device__ __align__(16) __nv_bfloat16 g_w1t_hi[NP*DD];  // W1^T [h][d] bf16 hi
__device__ __align__(16) __nv_bfloat16 g_w1t_lo[NP*DD];  // bf16 lo residual
__device__ __align__(16) float g_w1t32[NP*DD];           // W1^T fp32 (refinement)
__device__ float g_b1p[NP];
__device__ float g_w2p[NP];

#define MMA16816(d, a0,a1,a2,a3, b0,b1) \
    asm volatile("mma.sync.aligned.m16n8k16.row.col.f32.bf16.bf16.f32 " \
        "{%0,%1,%2,%3}, {%4,%5,%6,%7}, {%8,%9}, {%0,%1,%2,%3};" \
        : "+f"((d)[0]), "+f"((d)[1]), "+f"((d)[2]), "+f"((d)[3]) \
        : "r"(a0), "r"(a1), "r"(a2), "r"(a3), "r"(b0), "r"(b1))

#define LDSM_X4(r0,r1,r2,r3, addr) \
    asm volatile("ldmatrix.sync.aligned.m8n8.x4.shared.b16 {%0,%1,%2,%3}, [%4];" \
        : "=r"(r0), "=r"(r1), "=r"(r2), "=r"(r3) : "r"(addr))

#define CP_ASYNC16(dst, src) \
    asm volatile("cp.async.cg.shared.global [%0], [%1], 16;" :: "r"(dst), "l"(src))
#define CP_COMMIT() asm volatile("cp.async.commit_group;" ::: "memory")
#define CP_WAIT(n)  asm volatile("cp.async.wait_group %0;" :: "n"(n) : "memory")

__device__ __forceinline__ uint32_t smem_u32(const void* p) {
    uint32_t a;
    asm("{ .reg .u64 t; cvta.to.shared.u64 t, %1; cvt.u32.u64 %0, t; }" : "=r"(a) : "l"(p));
    return a;
}
__device__ __forceinline__ uint32_t packbf(__nv_bfloat16 a, __nv_bfloat16 b) {
    return (uint32_t)__bfloat16_as_ushort(a) | ((uint32_t)__bfloat16_as_ushort(b) << 16);
}
__device__ __forceinline__ float gelu_w2(float v, float w2v) {
    return 0.5f*v*(1.f + erff(v*0.70710678118654752f)) * w2v;
}

// ---------------------------------------------------------------------------
// Prologue: transpose + bf16-split W1 (zero-padded to NP), pad b1/W2
// ---------------------------------------------------------------------------
__global__ void kernelW(const float* __restrict__ W1, const float* __restrict__ b1,
                        const float* __restrict__ W2)
{
    int h = blockIdx.x;       // 0..351
    int d = threadIdx.x;      // 0..255
    float w = (h < HH) ? W1[d*HH + h] : 0.f;
    __nv_bfloat16 hi = __float2bfloat16(w);
    __nv_bfloat16 lo = __float2bfloat16(w - __bfloat162float(hi));
    g_w1t_hi[h*DD + d] = hi;
    g_w1t_lo[h*DD + d] = lo;
    g_w1t32[h*DD + d] = w;
    if (d == 0) {
        g_b1p[h] = (h < HH) ? b1[h] : 0.f;
        g_w2p[h] = (h < HH) ? W2[h] : 0.f;
    }
}

// ---------------------------------------------------------------------------
// Kernel A: emb*attn -> LN -> ldmatrix+mma bf16 3-term GEMM -> GELU -> dot W2
// Block = 128 tokens, 512 threads (16 warps: 8 m-tiles x 2 n-halves).
// 6 independent accumulator chains per warp (term x n-half) to expose MMA ILP.
// B chunks (32 n) double-buffered via cp.async. Early-exit on dead tiles.
// ---------------------------------------------------------------------------
#define RP 528            // padded row pitch (bytes), 256 bf16 = 512B data
#define OFF_AHI 0
#define OFF_ALO 67584
#define OFF_B0  135168    // buf: hi 32*RP (16896) + lo 16896 = 33792; 2 bufs
#define BUFSZ   33792
#define OFF_ATTN 202752
#define OFF_B1P 203264
#define OFF_W2P 204672
#define OFF_SC  206080
#define OFF_ANY 206592
#define SMEM_A_TOT 206656

extern __shared__ char smx[];

__device__ __forceinline__ void stage_B(int c, int buf, int tid, uint32_t sb) {
    // chunk c: rows [c*32, c*32+32) of g_w1t_{hi,lo}, 32 uint4 per row
#pragma unroll
    for (int i = 0; i < 4; ++i) {
        int v = tid + i*512;              // 0..2047
        int half = v >> 10;               // 0=hi, 1=lo
        int r = (v >> 5) & 31;
        int u = v & 31;
        const uint4* src = (half ? (const uint4*)g_w1t_lo : (const uint4*)g_w1t_hi)
                         + (size_t)(c*32 + r)*32 + u;
        uint32_t dst = sb + OFF_B0 + buf*BUFSZ + half*16896 + r*RP + u*16;
        CP_ASYNC16(dst, src);
    }
}

__global__ __launch_bounds__(512, 1)
void kernelA(const float* __restrict__ emb, const float* __restrict__ attn,
             const float* __restrict__ gamma_, const float* __restrict__ beta_,
             const float* __restrict__ b2)
{
    const int tid = threadIdx.x, lane = tid & 31, wid = tid >> 5;
    const int base = blockIdx.x * 128;
    uint32_t sb = smem_u32(smx);

    float* s_attn = (float*)(smx + OFF_ATTN);
    float* s_b1p  = (float*)(smx + OFF_B1P);
    float* s_w2p  = (float*)(smx + OFF_W2P);
    float* s_sc   = (float*)(smx + OFF_SC);
    int*   s_any  = (int*)(smx + OFF_ANY);

    if (tid == 0) *s_any = 0;
    __syncthreads();
    if (tid < 128) {
        float a = attn[base + tid];
        s_attn[tid] = a;
        s_sc[tid] = 0.f;
        if (a != 0.f) *s_any = 1;   // benign race
    }
    __syncthreads();
    if (!*s_any) {
        if (tid < 128) g_scores[base + tid] = NEGV;
        return;
    }

    // kick off B chunk 0 while we build A
    stage_B(0, 0, tid, sb);
    CP_COMMIT();

    if (tid < NP) { s_b1p[tid] = g_b1p[tid]; s_w2p[tid] = g_w2p[tid]; }

    // ---- LN + bf16 hi/lo split -> A tiles (warp w owns tokens 8w..8w+7)
    for (int it = 0; it < 8; ++it) {
        int mt = wid * 8 + it;
        const float4* e4 = (const float4*)(emb + (size_t)(base + mt) * DD);
        float4 va = e4[lane*2], vb = e4[lane*2 + 1];
        float am = s_attn[mt];
        va.x *= am; va.y *= am; va.z *= am; va.w *= am;
        vb.x *= am; vb.y *= am; vb.z *= am; vb.w *= am;
        float s  = va.x+va.y+va.z+va.w+vb.x+vb.y+vb.z+vb.w;
        float s2 = va.x*va.x+va.y*va.y+va.z*va.z+va.w*va.w
                 + vb.x*vb.x+vb.y*vb.y+vb.z*vb.z+vb.w*vb.w;
#pragma unroll
        for (int o = 16; o; o >>= 1) {
            s  += __shfl_xor_sync(0xffffffffu, s, o);
            s2 += __shfl_xor_sync(0xffffffffu, s2, o);
        }
        float mu = s * (1.f/256.f);
        float rstd = rsqrtf(s2 * (1.f/256.f) - mu*mu + 1e-5f);

        float x[8] = {va.x, va.y, va.z, va.w, vb.x, vb.y, vb.z, vb.w};
        uint32_t qh[4], ql[4];
        const int d0 = lane * 8;
#pragma unroll
        for (int p = 0; p < 4; ++p) {
            float x0 = (x[2*p]   - mu) * rstd * gamma_[d0+2*p]   + beta_[d0+2*p];
            float x1 = (x[2*p+1] - mu) * rstd * gamma_[d0+2*p+1] + beta_[d0+2*p+1];
            __nv_bfloat16 h0 = __float2bfloat16(x0);
            __nv_bfloat16 h1 = __float2bfloat16(x1);
            __nv_bfloat16 l0 = __float2bfloat16(x0 - __bfloat162float(h0));
            __nv_bfloat16 l1 = __float2bfloat16(x1 - __bfloat162float(h1));
            qh[p] = packbf(h0, h1);
            ql[p] = packbf(l0, l1);
        }
        uint32_t off = mt * RP + lane * 16;
        *(uint4*)(smx + OFF_AHI + off) = make_uint4(qh[0],qh[1],qh[2],qh[3]);
        *(uint4*)(smx + OFF_ALO + off) = make_uint4(ql[0],ql[1],ql[2],ql[3]);
    }

    const int wm = wid & 7;        // m-tile
    const int wn = wid >> 3;       // n-half (0/1)
    const int m0 = wm * 16;
    const int g = lane >> 2, q = lane & 3;
    const int lrow = lane & 15;
    const int lcol = (lane >> 4) * 16;

    const uint32_t aAddrHi = sb + OFF_AHI + (m0 + lrow) * RP + lcol;
    const uint32_t aAddrLo = sb + OFF_ALO + (m0 + lrow) * RP + lcol;
    const uint32_t bRowOff = (wn*16 + lrow) * RP + lcol;

    float part0 = 0.f, part1 = 0.f;

    for (int c = 0; c < NCHUNK; ++c) {
        if (c + 1 < NCHUNK) { stage_B(c+1, (c+1) & 1, tid, sb); CP_COMMIT(); }
        if (c + 1 < NCHUNK) CP_WAIT(1); else CP_WAIT(0);
        __syncthreads();

        const uint32_t bHi = sb + OFF_B0 + (c & 1)*BUFSZ + bRowOff;
        const uint32_t bLo = bHi + 16896;

        // 6 independent accumulator chains (3 terms x 2 n-subtiles)
        float aA0[4] = {0.f,0.f,0.f,0.f};
        float aB0[4] = {0.f,0.f,0.f,0.f};
        float aC0[4] = {0.f,0.f,0.f,0.f};
        float aA1[4] = {0.f,0.f,0.f,0.f};
        float aB1[4] = {0.f,0.f,0.f,0.f};
        float aC1[4] = {0.f,0.f,0.f,0.f};

#pragma unroll 4
        for (int ks = 0; ks < 16; ++ks) {
            const int kb = ks * 32;
            uint32_t ah0,ah1,ah2,ah3, al0,al1,al2,al3;
            uint32_t bh0,bh1,bh2,bh3, bl0,bl1,bl2,bl3;
            LDSM_X4(ah0,ah1,ah2,ah3, aAddrHi + kb);
            LDSM_X4(al0,al1,al2,al3, aAddrLo + kb);
            LDSM_X4(bh0,bh1,bh2,bh3, bHi + kb);
            LDSM_X4(bl0,bl1,bl2,bl3, bLo + kb);
            // j0 (n rows 0-7 of half): b = (r0, r2); j1: (r1, r3)
            MMA16816(aA0, ah0,ah1,ah2,ah3, bh0,bh2);
            MMA16816(aB0, ah0,ah1,ah2,ah3, bl0,bl2);
            MMA16816(aC0, al0,al1,al2,al3, bh0,bh2);
            MMA16816(aA1, ah0,ah1,ah2,ah3, bh1,bh3);
            MMA16816(aB1, ah0,ah1,ah2,ah3, bl1,bl3);
            MMA16816(aC1, al0,al1,al2,al3, bh1,bh3);
        }

        // epilogue: combine terms, bias + gelu + * W2 (padded h contributes 0)
        {
            float acc0[4], acc1[4];
#pragma unroll
            for (int r = 0; r < 4; ++r) {
                acc0[r] = aA0[r] + aB0[r] + aC0[r];
                acc1[r] = aA1[r] + aB1[r] + aC1[r];
            }
            int hb = c*32 + wn*16 + 2*q;
            float b1a = s_b1p[hb],   w2a = s_w2p[hb];
            float b1b = s_b1p[hb+1], w2b = s_w2p[hb+1];
            part0 += gelu_w2(acc0[0] + b1a, w2a) + gelu_w2(acc0[1] + b1b, w2b);
            part1 += gelu_w2(acc0[2] + b1a, w2a) + gelu_w2(acc0[3] + b1b, w2b);
            int hc = hb + 8;
            float b1c = s_b1p[hc],   w2c = s_w2p[hc];
            float b1d = s_b1p[hc+1], w2d = s_w2p[hc+1];
            part0 += gelu_w2(acc1[0] + b1c, w2c) + gelu_w2(acc1[1] + b1d, w2d);
            part1 += gelu_w2(acc1[2] + b1c, w2c) + gelu_w2(acc1[3] + b1d, w2d);
        }
        __syncthreads();   // all warps done with buf (c&1) before overwrite
    }

    // reduce across 4 q-lanes, then cross-warp (2 n-halves) via smem atomics
    part0 += __shfl_xor_sync(0xffffffffu, part0, 1);
    part0 += __shfl_xor_sync(0xffffffffu, part0, 2);
    part1 += __shfl_xor_sync(0xffffffffu, part1, 1);
    part1 += __shfl_xor_sync(0xffffffffu, part1, 2);
    if (q == 0) {
        atomicAdd(&s_sc[m0 + g], part0);
        atomicAdd(&s_sc[m0 + g + 8], part1);
    }
    __syncthreads();
    if (tid < 128) {
        float sc = s_sc[tid] + b2[0];
        if (s_attn[tid] == 0.f) sc = NEGV;
        g_scores[base + tid] = sc;
    }
}

// ---------------------------------------------------------------------------
// Threefry-2x32-20, JAX partitionable: ctr=(0,i), draw = out0 ^ out1
// ---------------------------------------------------------------------------
__device__ __forceinline__ uint32_t rotl32(uint32_t x, int r) { return (x << r) | (x >> (32 - r)); }
__device__ __forceinline__ void tf_r4(uint32_t& x0, uint32_t& x1, int a, int b, int c, int d) {
    x0 += x1; x1 = rotl32(x1, a); x1 ^= x0;
    x0 += x1; x1 = rotl32(x1, b); x1 ^= x0;
    x0 += x1; x1 = rotl32(x1, c); x1 ^= x0;
    x0 += x1; x1 = rotl32(x1, d); x1 ^= x0;
}
__device__ __forceinline__ uint32_t jax_bits(uint32_t i) {
    const uint32_t k0 = 0u, k1 = 42u;
    const uint32_t k2 = k0 ^ k1 ^ 0x1BD11BDAu;
    uint32_t x0 = 0u + k0;
    uint32_t x1 = i  + k1;
    tf_r4(x0, x1, 13, 15, 26, 6);   x0 += k1; x1 += k2 + 1u;
    tf_r4(x0, x1, 17, 29, 16, 24);  x0 += k2; x1 += k0 + 2u;
    tf_r4(x0, x1, 13, 15, 26, 6);   x0 += k0; x1 += k1 + 3u;
    tf_r4(x0, x1, 17, 29, 16, 24);  x0 += k1; x1 += k2 + 4u;
    tf_r4(x0, x1, 13, 15, 26, 6);   x0 += k2; x1 += k0 + 5u;
    return x0 ^ x1;
}
__device__ __forceinline__ float gumbel_of(uint32_t lin) {
    uint32_t bits = jax_bits(lin);
    float u = __uint_as_float((bits >> 9) | 0x3f800000u) - 1.0f;
    u = fmaxf(u, 0.f);
    return -logf(-logf(u + 1e-6f) + 1e-6f);
}

__device__ void bitonic_desc(float* a, int tid, int nthr) {
    for (int k = 2; k <= 4096; k <<= 1) {
        for (int j = k >> 1; j > 0; j >>= 1) {
            __syncthreads();
            for (int i = tid; i < 4096; i += nthr) {
                int ixj = i ^ j;
                if (ixj > i) {
                    float x = a[i], y = a[ixj];
                    bool up = ((i & k) == 0);
                    if (up ? (x < y) : (x > y)) { a[i] = y; a[ixj] = x; }
                }
            }
        }
    }
    __syncthreads();
}

// ---------------------------------------------------------------------------
// Kernel B: entmax1.5 + gumbel top-k with EXACT boundary refinement + TV
// ---------------------------------------------------------------------------
#define EPS_W 5e-4f
#define MAXC 64
#define SMEM_B ((5*4096 + 32*256)*4)

__global__ __launch_bounds__(1024, 1)
void kernelB(const float* __restrict__ attn, const float* __restrict__ emb,
             const float* __restrict__ gamma_, const float* __restrict__ beta_,
             const float* __restrict__ b2, float* __restrict__ out)
{
    extern __shared__ float sm[];
    float* s_scores = sm;
    float* s_attn   = sm + 4096;
    float* s_a      = sm + 8192;
    float* s_cum    = sm + 12288;
    float* s_cum2   = sm + 16384;
    float* s_xn     = sm + 20480;     // [32 warps][256]
    __shared__ float red[32], red2[32];
    __shared__ float sh_mx, sh_teff, sh_tau, sh_thr;
    __shared__ int sh_support, sh_above, sh_ncand;
    __shared__ int cand_idx[MAXC];
    __shared__ float cand_pert[MAXC];
    __shared__ int cand_sel[MAXC];

    const int row = blockIdx.x;
    const int tid = threadIdx.x;
    const int lane = tid & 31, wid = tid >> 5;

    float tf_ = 0.f, mx = -3.402823466e38f;
    for (int t = tid; t < TT; t += 1024) {
        float s = g_scores[row*TT + t];
        float a = attn[row*TT + t];
        s_scores[t] = s; s_attn[t] = a;
        tf_ += a; mx = fmaxf(mx, s);
    }
    for (int o = 16; o; o >>= 1) {
        tf_ += __shfl_xor_sync(0xffffffffu, tf_, o);
        mx = fmaxf(mx, __shfl_xor_sync(0xffffffffu, mx, o));
    }
    if (lane == 0) { red[wid] = tf_; red2[wid] = mx; }
    __syncthreads();
    if (tid == 0) {
        float a = 0.f, b = -3.402823466e38f;
        for (int w = 0; w < 32; w++) { a += red[w]; b = fmaxf(b, red2[w]); }
        sh_teff = a; sh_mx = b;
        sh_support = 0; sh_above = 0; sh_ncand = 0;
    }
    __syncthreads();
    mx = sh_mx;

    // ---- entmax 1.5
    for (int t = tid; t < TT; t += 1024) s_a[t] = (s_scores[t] - mx) * 0.5f;
    bitonic_desc(s_a, tid, 1024);

    const int p0 = tid * 4;
    {
        float v0 = s_a[p0+0], v1 = s_a[p0+1], v2 = s_a[p0+2], v3 = s_a[p0+3];
        float c0 = v0, c1 = c0 + v1, c2 = c1 + v2, c3 = c2 + v3;
        float d0 = v0*v0, d1 = d0 + v1*v1, d2 = d1 + v2*v2, d3 = d2 + v3*v3;
        float s = c3, s2 = d3;
        const float tot = c3, tot2 = d3;
        for (int o = 1; o < 32; o <<= 1) {
            float n  = __shfl_up_sync(0xffffffffu, s, o);
            float n2 = __shfl_up_sync(0xffffffffu, s2, o);
            if (lane >= o) { s += n; s2 += n2; }
        }
        if (lane == 31) { red[wid] = s; red2[wid] = s2; }
        __syncthreads();
        if (wid == 0) {
            float w = red[lane], w2 = red2[lane];
            for (int o = 1; o < 32; o <<= 1) {
                float n  = __shfl_up_sync(0xffffffffu, w, o);
                float n2 = __shfl_up_sync(0xffffffffu, w2, o);
                if (lane >= o) { w += n; w2 += n2; }
            }
            red[lane] = w; red2[lane] = w2;
        }
        __syncthreads();
        float base  = (wid ? red[wid-1]  : 0.f) + (s  - tot);
        float base2 = (wid ? red2[wid-1] : 0.f) + (s2 - tot2);
        s_cum[p0+0] = base + c0;  s_cum[p0+1] = base + c1;
        s_cum[p0+2] = base + c2;  s_cum[p0+3] = base + c3;
        s_cum2[p0+0] = base2 + d0; s_cum2[p0+1] = base2 + d1;
        s_cum2[p0+2] = base2 + d2; s_cum2[p0+3] = base2 + d3;
    }
    __syncthreads();

    int cnt = 0;
#pragma unroll
    for (int j = 0; j < 4; j++) {
        int p = p0 + j;
        float rho = (float)(p + 1);
        float mean = s_cum[p] / rho;
        float msq  = s_cum2[p] / rho;
        float ssv  = rho * (msq - mean*mean);
        float delta = (1.f - ssv) / rho;
        float tau = mean - sqrtf(fmaxf(delta, 0.f));
        cnt += (tau <= s_a[p]) ? 1 : 0;
    }
    for (int o = 16; o; o >>= 1) cnt += __shfl_xor_sync(0xffffffffu, cnt, o);
    if (lane == 0) atomicAdd(&sh_support, cnt);
    __syncthreads();
    if (tid == 0) {
        int p = sh_support - 1;
        float rho = (float)(p + 1);
        float mean = s_cum[p] / rho;
        float msq  = s_cum2[p] / rho;
        float ssv  = rho * (msq - mean*mean);
        float delta = (1.f - ssv) / rho;
        sh_tau = mean - sqrtf(fmaxf(delta, 0.f));
    }
    __syncthreads();
    const float taustar = sh_tau;

    for (int t = tid; t < TT; t += 1024) {
        float x = (s_scores[t] - mx) * 0.5f;
        float dd = fmaxf(x - taustar, 0.f);
        out[row*TT + t] = dd*dd*s_attn[t];
    }
    __syncthreads();

    // ---- gumbel-perturbed scores
    for (int t = tid; t < TT; t += 1024) {
        float gum = gumbel_of((uint32_t)(row*TT + t));
        float pert = s_scores[t] * s_attn[t] + gum;
        s_cum[t] = pert;
        s_a[t] = (pert != pert) ? __int_as_float(0xff800000) : pert;
    }
    bitonic_desc(s_a, tid, 1024);

    const float teff = sh_teff;
    float kf = rintf(0.3f * teff);
    kf = fminf(fmaxf(kf, 1.f), fmaxf(teff, 1.f));
    const int ki = (int)kf;
    if (tid == 0) sh_thr = s_a[ki - 1];
    __syncthreads();
    const float thr = sh_thr;
    const float hiW = thr + EPS_W, loW = thr - EPS_W;

    // ---- classification counts + candidate gather
    {
        int my_above = 0;
        for (int t = tid; t < TT; t += 1024) {
            float p = s_cum[t];
            if (p > hiW) my_above++;
            else if (p >= loW) {
                int pos = atomicAdd(&sh_ncand, 1);
                if (pos < MAXC) cand_idx[pos] = t;
            }
        }
        for (int o = 16; o; o >>= 1) my_above += __shfl_xor_sync(0xffffffffu, my_above, o);
        if (lane == 0) atomicAdd(&sh_above, my_above);
    }
    __syncthreads();
    const int ncand = sh_ncand;
    const bool refine = (ncand <= MAXC);

    // ---- exact recompute of candidate perts (warp per candidate)
    if (refine) {
        const float b2v = b2[0];
        for (int c = wid; c < ncand; c += 32) {
            int t = cand_idx[c];
            float ex;
            if (s_attn[t] == 0.f) {
                ex = s_cum[t];    // masked: pert = gumbel, already exact
            } else {
                const float4* e4 = (const float4*)(emb + ((size_t)row*TT + t)*DD);
                float4 va = e4[lane*2], vb = e4[lane*2+1];
                float s  = va.x+va.y+va.z+va.w+vb.x+vb.y+vb.z+vb.w;
                float s2 = va.x*va.x+va.y*va.y+va.z*va.z+va.w*va.w
                         + vb.x*vb.x+vb.y*vb.y+vb.z*vb.z+vb.w*vb.w;
#pragma unroll
                for (int o = 16; o; o >>= 1) {
                    s  += __shfl_xor_sync(0xffffffffu, s, o);
                    s2 += __shfl_xor_sync(0xffffffffu, s2, o);
                }
                float mu = s * (1.f/256.f);
                float rstd = rsqrtf(s2 * (1.f/256.f) - mu*mu + 1e-5f);
                float xv[8] = {va.x,va.y,va.z,va.w,vb.x,vb.y,vb.z,vb.w};
                float* xw = s_xn + wid*256 + lane*8;
#pragma unroll
                for (int p = 0; p < 8; ++p) {
                    int d = lane*8 + p;
                    xw[p] = (xv[p] - mu) * rstd * gamma_[d] + beta_[d];
                }
                __syncwarp();
                float sc = 0.f;
                for (int h = lane; h < HH; h += 32) {
                    const float4* wr = (const float4*)(g_w1t32 + (size_t)h*DD);
                    const float4* xr = (const float4*)(s_xn + wid*256);
                    float dot = 0.f;
#pragma unroll 8
                    for (int u = 0; u < 64; ++u) {
                        float4 a = wr[u], bq = xr[u];
                        dot += a.x*bq.x + a.y*bq.y + a.z*bq.z + a.w*bq.w;
                    }
                    float v = dot + g_b1p[h];
                    sc += gelu_w2(v, g_w2p[h]);
                }
#pragma unroll
                for (int o = 16; o; o >>= 1) sc += __shfl_xor_sync(0xffffffffu, sc, o);
                float score = sc + b2v;
                float pert = score + gumbel_of((uint32_t)(row*TT + t));  // attn==1
                ex = pert;
                __syncwarp();
            }
            if (lane == 0) cand_pert[c] = ex;
        }
    }
    __syncthreads();

    // ---- select top-'need' among candidates (rank by strict greater)
    if (refine && tid == 0) {
        int need = ki - sh_above;
        for (int c = 0; c < ncand; ++c) {
            int rank = 0;
            float pc = cand_pert[c];
            for (int c2 = 0; c2 < ncand; ++c2)
                if (cand_pert[c2] > pc) rank++;
            cand_sel[c] = (rank < need) ? 1 : 0;
        }
    }
    __syncthreads();

    // ---- g output (store into s_a for TV)
    for (int t = tid; t < TT; t += 1024) {
        float p = s_cum[t];
        float a0 = s_attn[t];
        float gv;
        if (refine) {
            if (p > hiW) gv = a0;
            else if (p >= loW) {
                gv = 0.f;
                for (int c = 0; c < ncand; ++c)
                    if (cand_idx[c] == t) { gv = cand_sel[c] ? a0 : 0.f; break; }
            } else gv = 0.f;
        } else {
            gv = (p >= thr) ? a0 : 0.f;
        }
        out[BT + row*TT + t] = gv;
        s_a[t] = gv;
    }
    __syncthreads();

    // ---- TV
    float num = 0.f, den = 0.f;
    for (int t = tid; t < TT - 1; t += 1024) {
        float valid = s_attn[t] * s_attn[t+1];
        num += fabsf(s_a[t+1] - s_a[t]) * valid;
        den += valid;
    }
    for (int o = 16; o; o >>= 1) {
        num += __shfl_xor_sync(0xffffffffu, num, o);
        den += __shfl_xor_sync(0xffffffffu, den, o);
    }
    if (lane == 0) { red[wid] = num; red2[wid] = den; }
    __syncthreads();
    if (tid == 0) {
        float a = 0.f, b = 0.f;
        for (int w = 0; w < 32; w++) { a += red[w]; b += red2[w]; }
        g_tv[row] = a / fmaxf(b, 1.f);
    }
}

__global__ void kernelC(float* __restrict__ out)
{
    __shared__ float r[64];
    r[threadIdx.x] = g_tv[threadIdx.x];
    __syncthreads();
    if (threadIdx.x == 0) {
        float s = 0.f;
        for (int i = 0; i < 64; i++) s += r[i];
        out[2*BT] = 0.1f * (s / 64.f);
    }
}

extern "C" void kernel_launch(void* const* d_in, const int* in_sizes, int n_in,
                              void* d_out, int out_size)
{
    const float* emb   = (const float*)d_in[0];
    const float* attn  = (const float*)d_in[1];
    const float* gamma = (const float*)d_in[2];
    const float* beta  = (const float*)d_in[3];
    const float* W1    = (const float*)d_in[4];
    const float* b1    = (const float*)d_in[5];
    const float* W2    = (const float*)d_in[6];
    const float* b2    = (const float*)d_in[7];
    float* out = (float*)d_out;

    cudaFuncSetAttribute(kernelA, cudaFuncAttributeMaxDynamicSharedMemorySize, SMEM_A_TOT);
    cudaFuncSetAttribute(kernelB, cudaFuncAttributeMaxDynamicSharedMemorySize, SMEM_B);

    kernelW<<<NP, 256>>>(W1, b1, W2);
    kernelA<<<BT/128, 512, SMEM_A_TOT>>>(emb, attn, gamma, beta, b2);
    kernelB<<<BB, 1024, SMEM_B>>>(attn, emb, gamma, beta, b2, out);
    kernelC<<<1, 64>>>(out);
}

// round 11
// speedup vs baseline: 3.2566x; 1.0094x over previous
#include <cuda_runtime.h>
#include <cuda_fp16.h>
#include <cstdint>
#include <math.h>

// Problem constants
#define BB 64
#define TT 4096
#define DD 256
#define HH 341
#define BT (BB*TT)
#define NEGV (-1e9f)
#define NP 352            // hidden padded to 11*32
#define NCHUNK 11         // 32 n-cols per chunk
#define LSCALE 2048.0f
#define INV_LSCALE (1.0f/2048.0f)

__device__ float g_scores[BT];
__device__ float g_tv[BB];
__device__ __align__(16) __half g_w1t_hi[NP*DD];   // W1^T [h][d] fp16 hi
__device__ __align__(16) __half g_w1t_lo[NP*DD];   // fp16 residual * 2048
__device__ __align__(16) float g_w1t32[NP*DD];     // W1^T fp32 (refinement)
__device__ float g_b1p[NP];
__device__ float g_w2p[NP];

// f32-accumulator fp16 MMA
#define MMA16816F(d, a0,a1,a2,a3, b0,b1) \
    asm volatile("mma.sync.aligned.m16n8k16.row.col.f32.f16.f16.f32 " \
        "{%0,%1,%2,%3}, {%4,%5,%6,%7}, {%8,%9}, {%0,%1,%2,%3};" \
        : "+f"((d)[0]), "+f"((d)[1]), "+f"((d)[2]), "+f"((d)[3]) \
        : "r"(a0), "r"(a1), "r"(a2), "r"(a3), "r"(b0), "r"(b1))

// f16-accumulator fp16 MMA (c0 = halves r0,r1; c1 = halves r2,r3)
#define MMA16816H(c0, c1, a0,a1,a2,a3, b0,b1) \
    asm volatile("mma.sync.aligned.m16n8k16.row.col.f16.f16.f16.f16 " \
        "{%0,%1}, {%2,%3,%4,%5}, {%6,%7}, {%0,%1};" \
        : "+r"(c0), "+r"(c1) \
        : "r"(a0), "r"(a1), "r"(a2), "r"(a3), "r"(b0), "r"(b1))

#define LDSM_X4(r0,r1,r2,r3, addr) \
    asm volatile("ldmatrix.sync.aligned.m8n8.x4.shared.b16 {%0,%1,%2,%3}, [%4];" \
        : "=r"(r0), "=r"(r1), "=r"(r2), "=r"(r3) : "r"(addr))

#define CP_ASYNC16(dst, src) \
    asm volatile("cp.async.cg.shared.global [%0], [%1], 16;" :: "r"(dst), "l"(src))
#define CP_COMMIT() asm volatile("cp.async.commit_group;" ::: "memory")
#define CP_WAIT(n)  asm volatile("cp.async.wait_group %0;" :: "n"(n) : "memory")

__device__ __forceinline__ uint32_t smem_u32(const void* p) {
    uint32_t a;
    asm("{ .reg .u64 t; cvta.to.shared.u64 t, %1; cvt.u32.u64 %0, t; }" : "=r"(a) : "l"(p));
    return a;
}
__device__ __forceinline__ uint32_t packh(__half a, __half b) {
    return (uint32_t)__half_as_ushort(a) | ((uint32_t)__half_as_ushort(b) << 16);
}
__device__ __forceinline__ float2 h2f2(uint32_t v) {
    __half2 h = *reinterpret_cast<__half2*>(&v);
    return __half22float2(h);
}
__device__ __forceinline__ float gelu_w2(float v, float w2v) {
    return 0.5f*v*(1.f + erff(v*0.70710678118654752f)) * w2v;
}

// ---------------------------------------------------------------------------
// Prologue: transpose + fp16-split W1 (lo pre-scaled by 2048), pad b1/W2
// ---------------------------------------------------------------------------
__global__ void kernelW(const float* __restrict__ W1, const float* __restrict__ b1,
                        const float* __restrict__ W2)
{
    int h = blockIdx.x;       // 0..351
    int d = threadIdx.x;      // 0..255
    float w = (h < HH) ? W1[d*HH + h] : 0.f;
    __half hi = __float2half_rn(w);
    __half lo = __float2half_rn((w - __half2float(hi)) * LSCALE);
    g_w1t_hi[h*DD + d] = hi;
    g_w1t_lo[h*DD + d] = lo;
    g_w1t32[h*DD + d] = w;
    if (d == 0) {
        g_b1p[h] = (h < HH) ? b1[h] : 0.f;
        g_w2p[h] = (h < HH) ? W2[h] : 0.f;
    }
}

// ---------------------------------------------------------------------------
// Kernel A: emb*attn -> LN -> ldmatrix+mma fp16 3-term GEMM -> GELU -> dot W2
// hi x hi in f32 accum; two cross terms in f16 accum (residuals x2048).
// Block = 128 tokens, 512 threads (16 warps: 8 m-tiles x 2 n-halves).
// ---------------------------------------------------------------------------
#define RP 528            // padded row pitch (bytes), 256 fp16 = 512B data
#define OFF_AHI 0
#define OFF_ALO 67584
#define OFF_B0  135168    // buf: hi 32*RP (16896) + lo 16896 = 33792; 2 bufs
#define BUFSZ   33792
#define OFF_ATTN 202752
#define OFF_B1P 203264
#define OFF_W2P 204672
#define OFF_SC  206080
#define OFF_ANY 206592
#define SMEM_A_TOT 206656

extern __shared__ char smx[];

__device__ __forceinline__ void stage_B(int c, int buf, int tid, uint32_t sb) {
#pragma unroll
    for (int i = 0; i < 4; ++i) {
        int v = tid + i*512;              // 0..2047
        int half_ = v >> 10;              // 0=hi, 1=lo
        int r = (v >> 5) & 31;
        int u = v & 31;
        const uint4* src = (half_ ? (const uint4*)g_w1t_lo : (const uint4*)g_w1t_hi)
                         + (size_t)(c*32 + r)*32 + u;
        uint32_t dst = sb + OFF_B0 + buf*BUFSZ + half_*16896 + r*RP + u*16;
        CP_ASYNC16(dst, src);
    }
}

__global__ __launch_bounds__(512, 1)
void kernelA(const float* __restrict__ emb, const float* __restrict__ attn,
             const float* __restrict__ gamma_, const float* __restrict__ beta_,
             const float* __restrict__ b2)
{
    const int tid = threadIdx.x, lane = tid & 31, wid = tid >> 5;
    const int base = blockIdx.x * 128;
    uint32_t sb = smem_u32(smx);

    float* s_attn = (float*)(smx + OFF_ATTN);
    float* s_b1p  = (float*)(smx + OFF_B1P);
    float* s_w2p  = (float*)(smx + OFF_W2P);
    float* s_sc   = (float*)(smx + OFF_SC);
    int*   s_any  = (int*)(smx + OFF_ANY);

    if (tid == 0) *s_any = 0;
    __syncthreads();
    if (tid < 128) {
        float a = attn[base + tid];
        s_attn[tid] = a;
        s_sc[tid] = 0.f;
        if (a != 0.f) *s_any = 1;   // benign race
    }
    __syncthreads();
    if (!*s_any) {
        if (tid < 128) g_scores[base + tid] = NEGV;
        return;
    }

    stage_B(0, 0, tid, sb);
    CP_COMMIT();

    if (tid < NP) { s_b1p[tid] = g_b1p[tid]; s_w2p[tid] = g_w2p[tid]; }

    // ---- LN + fp16 hi/lo split (lo * 2048) -> A tiles
    for (int it = 0; it < 8; ++it) {
        int mt = wid * 8 + it;
        const float4* e4 = (const float4*)(emb + (size_t)(base + mt) * DD);
        float4 va = e4[lane*2], vb = e4[lane*2 + 1];
        float am = s_attn[mt];
        va.x *= am; va.y *= am; va.z *= am; va.w *= am;
        vb.x *= am; vb.y *= am; vb.z *= am; vb.w *= am;
        float s  = va.x+va.y+va.z+va.w+vb.x+vb.y+vb.z+vb.w;
        float s2 = va.x*va.x+va.y*va.y+va.z*va.z+va.w*va.w
                 + vb.x*vb.x+vb.y*vb.y+vb.z*vb.z+vb.w*vb.w;
#pragma unroll
        for (int o = 16; o; o >>= 1) {
            s  += __shfl_xor_sync(0xffffffffu, s, o);
            s2 += __shfl_xor_sync(0xffffffffu, s2, o);
        }
        float mu = s * (1.f/256.f);
        float rstd = rsqrtf(s2 * (1.f/256.f) - mu*mu + 1e-5f);

        float x[8] = {va.x, va.y, va.z, va.w, vb.x, vb.y, vb.z, vb.w};
        uint32_t qh[4], ql[4];
        const int d0 = lane * 8;
#pragma unroll
        for (int p = 0; p < 4; ++p) {
            float x0 = (x[2*p]   - mu) * rstd * gamma_[d0+2*p]   + beta_[d0+2*p];
            float x1 = (x[2*p+1] - mu) * rstd * gamma_[d0+2*p+1] + beta_[d0+2*p+1];
            __half h0 = __float2half_rn(x0);
            __half h1 = __float2half_rn(x1);
            __half l0 = __float2half_rn((x0 - __half2float(h0)) * LSCALE);
            __half l1 = __float2half_rn((x1 - __half2float(h1)) * LSCALE);
            qh[p] = packh(h0, h1);
            ql[p] = packh(l0, l1);
        }
        uint32_t off = mt * RP + lane * 16;
        *(uint4*)(smx + OFF_AHI + off) = make_uint4(qh[0],qh[1],qh[2],qh[3]);
        *(uint4*)(smx + OFF_ALO + off) = make_uint4(ql[0],ql[1],ql[2],ql[3]);
    }

    const int wm = wid & 7;        // m-tile
    const int wn = wid >> 3;       // n-half (0/1)
    const int m0 = wm * 16;
    const int g = lane >> 2, q = lane & 3;
    const int lrow = lane & 15;
    const int lcol = (lane >> 4) * 16;

    const uint32_t aAddrHi = sb + OFF_AHI + (m0 + lrow) * RP + lcol;
    const uint32_t aAddrLo = sb + OFF_ALO + (m0 + lrow) * RP + lcol;
    const uint32_t bRowOff = (wn*16 + lrow) * RP + lcol;

    float part0 = 0.f, part1 = 0.f;

    for (int c = 0; c < NCHUNK; ++c) {
        if (c + 1 < NCHUNK) { stage_B(c+1, (c+1) & 1, tid, sb); CP_COMMIT(); }
        if (c + 1 < NCHUNK) CP_WAIT(1); else CP_WAIT(0);
        __syncthreads();

        const uint32_t bHi = sb + OFF_B0 + (c & 1)*BUFSZ + bRowOff;
        const uint32_t bLo = bHi + 16896;

        // hi x hi: f32 accum; cross terms: f16 accum (x2048 scaled residuals)
        float hA0[4] = {0.f,0.f,0.f,0.f};
        float hA1[4] = {0.f,0.f,0.f,0.f};
        uint32_t xA0a = 0u, xA0b = 0u;   // ah x bl' (subtile 0)
        uint32_t xB0a = 0u, xB0b = 0u;   // al' x bh (subtile 0)
        uint32_t xA1a = 0u, xA1b = 0u;   // ah x bl' (subtile 1)
        uint32_t xB1a = 0u, xB1b = 0u;   // al' x bh (subtile 1)

#pragma unroll 4
        for (int ks = 0; ks < 16; ++ks) {
            const int kb = ks * 32;
            uint32_t ah0,ah1,ah2,ah3, al0,al1,al2,al3;
            uint32_t bh0,bh1,bh2,bh3, bl0,bl1,bl2,bl3;
            LDSM_X4(ah0,ah1,ah2,ah3, aAddrHi + kb);
            LDSM_X4(al0,al1,al2,al3, aAddrLo + kb);
            LDSM_X4(bh0,bh1,bh2,bh3, bHi + kb);
            LDSM_X4(bl0,bl1,bl2,bl3, bLo + kb);
            MMA16816F(hA0, ah0,ah1,ah2,ah3, bh0,bh2);
            MMA16816H(xA0a,xA0b, ah0,ah1,ah2,ah3, bl0,bl2);
            MMA16816H(xB0a,xB0b, al0,al1,al2,al3, bh0,bh2);
            MMA16816F(hA1, ah0,ah1,ah2,ah3, bh1,bh3);
            MMA16816H(xA1a,xA1b, ah0,ah1,ah2,ah3, bl1,bl3);
            MMA16816H(xB1a,xB1b, al0,al1,al2,al3, bh1,bh3);
        }

        // epilogue: combine (hi + cross/2048), bias + gelu + * W2
        {
            float2 pA0 = h2f2(xA0a), pA0b = h2f2(xA0b);
            float2 pB0 = h2f2(xB0a), pB0b = h2f2(xB0b);
            float2 pA1 = h2f2(xA1a), pA1b = h2f2(xA1b);
            float2 pB1 = h2f2(xB1a), pB1b = h2f2(xB1b);
            float acc0[4], acc1[4];
            acc0[0] = hA0[0] + (pA0.x  + pB0.x ) * INV_LSCALE;
            acc0[1] = hA0[1] + (pA0.y  + pB0.y ) * INV_LSCALE;
            acc0[2] = hA0[2] + (pA0b.x + pB0b.x) * INV_LSCALE;
            acc0[3] = hA0[3] + (pA0b.y + pB0b.y) * INV_LSCALE;
            acc1[0] = hA1[0] + (pA1.x  + pB1.x ) * INV_LSCALE;
            acc1[1] = hA1[1] + (pA1.y  + pB1.y ) * INV_LSCALE;
            acc1[2] = hA1[2] + (pA1b.x + pB1b.x) * INV_LSCALE;
            acc1[3] = hA1[3] + (pA1b.y + pB1b.y) * INV_LSCALE;

            int hb = c*32 + wn*16 + 2*q;
            float b1a = s_b1p[hb],   w2a = s_w2p[hb];
            float b1b = s_b1p[hb+1], w2b = s_w2p[hb+1];
            part0 += gelu_w2(acc0[0] + b1a, w2a) + gelu_w2(acc0[1] + b1b, w2b);
            part1 += gelu_w2(acc0[2] + b1a, w2a) + gelu_w2(acc0[3] + b1b, w2b);
            int hc = hb + 8;
            float b1c = s_b1p[hc],   w2c = s_w2p[hc];
            float b1d = s_b1p[hc+1], w2d = s_w2p[hc+1];
            part0 += gelu_w2(acc1[0] + b1c, w2c) + gelu_w2(acc1[1] + b1d, w2d);
            part1 += gelu_w2(acc1[2] + b1c, w2c) + gelu_w2(acc1[3] + b1d, w2d);
        }
        __syncthreads();   // all warps done with buf (c&1) before overwrite
    }

    part0 += __shfl_xor_sync(0xffffffffu, part0, 1);
    part0 += __shfl_xor_sync(0xffffffffu, part0, 2);
    part1 += __shfl_xor_sync(0xffffffffu, part1, 1);
    part1 += __shfl_xor_sync(0xffffffffu, part1, 2);
    if (q == 0) {
        atomicAdd(&s_sc[m0 + g], part0);
        atomicAdd(&s_sc[m0 + g + 8], part1);
    }
    __syncthreads();
    if (tid < 128) {
        float sc = s_sc[tid] + b2[0];
        if (s_attn[tid] == 0.f) sc = NEGV;
        g_scores[base + tid] = sc;
    }
}

// ---------------------------------------------------------------------------
// Threefry-2x32-20, JAX partitionable: ctr=(0,i), draw = out0 ^ out1
// ---------------------------------------------------------------------------
__device__ __forceinline__ uint32_t rotl32(uint32_t x, int r) { return (x << r) | (x >> (32 - r)); }
__device__ __forceinline__ void tf_r4(uint32_t& x0, uint32_t& x1, int a, int b, int c, int d) {
    x0 += x1; x1 = rotl32(x1, a); x1 ^= x0;
    x0 += x1; x1 = rotl32(x1, b); x1 ^= x0;
    x0 += x1; x1 = rotl32(x1, c); x1 ^= x0;
    x0 += x1; x1 = rotl32(x1, d); x1 ^= x0;
}
__device__ __forceinline__ uint32_t jax_bits(uint32_t i) {
    const uint32_t k0 = 0u, k1 = 42u;
    const uint32_t k2 = k0 ^ k1 ^ 0x1BD11BDAu;
    uint32_t x0 = 0u + k0;
    uint32_t x1 = i  + k1;
    tf_r4(x0, x1, 13, 15, 26, 6);   x0 += k1; x1 += k2 + 1u;
    tf_r4(x0, x1, 17, 29, 16, 24);  x0 += k2; x1 += k0 + 2u;
    tf_r4(x0, x1, 13, 15, 26, 6);   x0 += k0; x1 += k1 + 3u;
    tf_r4(x0, x1, 17, 29, 16, 24);  x0 += k1; x1 += k2 + 4u;
    tf_r4(x0, x1, 13, 15, 26, 6);   x0 += k2; x1 += k0 + 5u;
    return x0 ^ x1;
}
__device__ __forceinline__ float gumbel_of(uint32_t lin) {
    uint32_t bits = jax_bits(lin);
    float u = __uint_as_float((bits >> 9) | 0x3f800000u) - 1.0f;
    u = fmaxf(u, 0.f);
    return -logf(-logf(u + 1e-6f) + 1e-6f);
}

__device__ void bitonic_desc(float* a, int tid, int nthr) {
    for (int k = 2; k <= 4096; k <<= 1) {
        for (int j = k >> 1; j > 0; j >>= 1) {
            __syncthreads();
            for (int i = tid; i < 4096; i += nthr) {
                int ixj = i ^ j;
                if (ixj > i) {
                    float x = a[i], y = a[ixj];
                    bool up = ((i & k) == 0);
                    if (up ? (x < y) : (x > y)) { a[i] = y; a[ixj] = x; }
                }
            }
        }
    }
    __syncthreads();
}

// ---------------------------------------------------------------------------
// Kernel B: entmax1.5 + gumbel top-k with EXACT boundary refinement + TV
// ---------------------------------------------------------------------------
#define EPS_W 5e-4f
#define MAXC 64
#define SMEM_B ((5*4096 + 32*256)*4)

__global__ __launch_bounds__(1024, 1)
void kernelB(const float* __restrict__ attn, const float* __restrict__ emb,
             const float* __restrict__ gamma_, const float* __restrict__ beta_,
             const float* __restrict__ b2, float* __restrict__ out)
{
    extern __shared__ float sm[];
    float* s_scores = sm;
    float* s_attn   = sm + 4096;
    float* s_a      = sm + 8192;
    float* s_cum    = sm + 12288;
    float* s_cum2   = sm + 16384;
    float* s_xn     = sm + 20480;     // [32 warps][256]
    __shared__ float red[32], red2[32];
    __shared__ float sh_mx, sh_teff, sh_tau, sh_thr;
    __shared__ int sh_support, sh_above, sh_ncand;
    __shared__ int cand_idx[MAXC];
    __shared__ float cand_pert[MAXC];
    __shared__ int cand_sel[MAXC];

    const int row = blockIdx.x;
    const int tid = threadIdx.x;
    const int lane = tid & 31, wid = tid >> 5;

    float tf_ = 0.f, mx = -3.402823466e38f;
    for (int t = tid; t < TT; t += 1024) {
        float s = g_scores[row*TT + t];
        float a = attn[row*TT + t];
        s_scores[t] = s; s_attn[t] = a;
        tf_ += a; mx = fmaxf(mx, s);
    }
    for (int o = 16; o; o >>= 1) {
        tf_ += __shfl_xor_sync(0xffffffffu, tf_, o);
        mx = fmaxf(mx, __shfl_xor_sync(0xffffffffu, mx, o));
    }
    if (lane == 0) { red[wid] = tf_; red2[wid] = mx; }
    __syncthreads();
    if (tid == 0) {
        float a = 0.f, b = -3.402823466e38f;
        for (int w = 0; w < 32; w++) { a += red[w]; b = fmaxf(b, red2[w]); }
        sh_teff = a; sh_mx = b;
        sh_support = 0; sh_above = 0; sh_ncand = 0;
    }
    __syncthreads();
    mx = sh_mx;

    // ---- entmax 1.5
    for (int t = tid; t < TT; t += 1024) s_a[t] = (s_scores[t] - mx) * 0.5f;
    bitonic_desc(s_a, tid, 1024);

    const int p0 = tid * 4;
    {
        float v0 = s_a[p0+0], v1 = s_a[p0+1], v2 = s_a[p0+2], v3 = s_a[p0+3];
        float c0 = v0, c1 = c0 + v1, c2 = c1 + v2, c3 = c2 + v3;
        float d0 = v0*v0, d1 = d0 + v1*v1, d2 = d1 + v2*v2, d3 = d2 + v3*v3;
        float s = c3, s2 = d3;
        const float tot = c3, tot2 = d3;
        for (int o = 1; o < 32; o <<= 1) {
            float n  = __shfl_up_sync(0xffffffffu, s, o);
            float n2 = __shfl_up_sync(0xffffffffu, s2, o);
            if (lane >= o) { s += n; s2 += n2; }
        }
        if (lane == 31) { red[wid] = s; red2[wid] = s2; }
        __syncthreads();
        if (wid == 0) {
            float w = red[lane], w2 = red2[lane];
            for (int o = 1; o < 32; o <<= 1) {
                float n  = __shfl_up_sync(0xffffffffu, w, o);
                float n2 = __shfl_up_sync(0xffffffffu, w2, o);
                if (lane >= o) { w += n; w2 += n2; }
            }
            red[lane] = w; red2[lane] = w2;
        }
        __syncthreads();
        float base  = (wid ? red[wid-1]  : 0.f) + (s  - tot);
        float base2 = (wid ? red2[wid-1] : 0.f) + (s2 - tot2);
        s_cum[p0+0] = base + c0;  s_cum[p0+1] = base + c1;
        s_cum[p0+2] = base + c2;  s_cum[p0+3] = base + c3;
        s_cum2[p0+0] = base2 + d0; s_cum2[p0+1] = base2 + d1;
        s_cum2[p0+2] = base2 + d2; s_cum2[p0+3] = base2 + d3;
    }
    __syncthreads();

    int cnt = 0;
#pragma unroll
    for (int j = 0; j < 4; j++) {
        int p = p0 + j;
        float rho = (float)(p + 1);
        float mean = s_cum[p] / rho;
        float msq  = s_cum2[p] / rho;
        float ssv  = rho * (msq - mean*mean);
        float delta = (1.f - ssv) / rho;
        float tau = mean - sqrtf(fmaxf(delta, 0.f));
        cnt += (tau <= s_a[p]) ? 1 : 0;
    }
    for (int o = 16; o; o >>= 1) cnt += __shfl_xor_sync(0xffffffffu, cnt, o);
    if (lane == 0) atomicAdd(&sh_support, cnt);
    __syncthreads();
    if (tid == 0) {
        int p = sh_support - 1;
        float rho = (float)(p + 1);
        float mean = s_cum[p] / rho;
        float msq  = s_cum2[p] / rho;
        float ssv  = rho * (msq - mean*mean);
        float delta = (1.f - ssv) / rho;
        sh_tau = mean - sqrtf(fmaxf(delta, 0.f));
    }
    __syncthreads();
    const float taustar = sh_tau;

    for (int t = tid; t < TT; t += 1024) {
        float x = (s_scores[t] - mx) * 0.5f;
        float dd = fmaxf(x - taustar, 0.f);
        out[row*TT + t] = dd*dd*s_attn[t];
    }
    __syncthreads();

    // ---- gumbel-perturbed scores
    for (int t = tid; t < TT; t += 1024) {
        float gum = gumbel_of((uint32_t)(row*TT + t));
        float pert = s_scores[t] * s_attn[t] + gum;
        s_cum[t] = pert;
        s_a[t] = (pert != pert) ? __int_as_float(0xff800000) : pert;
    }
    bitonic_desc(s_a, tid, 1024);

    const float teff = sh_teff;
    float kf = rintf(0.3f * teff);
    kf = fminf(fmaxf(kf, 1.f), fmaxf(teff, 1.f));
    const int ki = (int)kf;
    if (tid == 0) sh_thr = s_a[ki - 1];
    __syncthreads();
    const float thr = sh_thr;
    const float hiW = thr + EPS_W, loW = thr - EPS_W;

    // ---- classification counts + candidate gather
    {
        int my_above = 0;
        for (int t = tid; t < TT; t += 1024) {
            float p = s_cum[t];
            if (p > hiW) my_above++;
            else if (p >= loW) {
                int pos = atomicAdd(&sh_ncand, 1);
                if (pos < MAXC) cand_idx[pos] = t;
            }
        }
        for (int o = 16; o; o >>= 1) my_above += __shfl_xor_sync(0xffffffffu, my_above, o);
        if (lane == 0) atomicAdd(&sh_above, my_above);
    }
    __syncthreads();
    const int ncand = sh_ncand;
    const bool refine = (ncand <= MAXC);

    // ---- exact recompute of candidate perts (warp per candidate)
    if (refine) {
        const float b2v = b2[0];
        for (int c = wid; c < ncand; c += 32) {
            int t = cand_idx[c];
            float ex;
            if (s_attn[t] == 0.f) {
                ex = s_cum[t];    // masked: pert = gumbel, already exact
            } else {
                const float4* e4 = (const float4*)(emb + ((size_t)row*TT + t)*DD);
                float4 va = e4[lane*2], vb = e4[lane*2+1];
                float s  = va.x+va.y+va.z+va.w+vb.x+vb.y+vb.z+vb.w;
                float s2 = va.x*va.x+va.y*va.y+va.z*va.z+va.w*va.w
                         + vb.x*vb.x+vb.y*vb.y+vb.z*vb.z+vb.w*vb.w;
#pragma unroll
                for (int o = 16; o; o >>= 1) {
                    s  += __shfl_xor_sync(0xffffffffu, s, o);
                    s2 += __shfl_xor_sync(0xffffffffu, s2, o);
                }
                float mu = s * (1.f/256.f);
                float rstd = rsqrtf(s2 * (1.f/256.f) - mu*mu + 1e-5f);
                float xv[8] = {va.x,va.y,va.z,va.w,vb.x,vb.y,vb.z,vb.w};
                float* xw = s_xn + wid*256 + lane*8;
#pragma unroll
                for (int p = 0; p < 8; ++p) {
                    int d = lane*8 + p;
                    xw[p] = (xv[p] - mu) * rstd * gamma_[d] + beta_[d];
                }
                __syncwarp();
                float sc = 0.f;
                for (int h = lane; h < HH; h += 32) {
                    const float4* wr = (const float4*)(g_w1t32 + (size_t)h*DD);
                    const float4* xr = (const float4*)(s_xn + wid*256);
                    float dot = 0.f;
#pragma unroll 8
                    for (int u = 0; u < 64; ++u) {
                        float4 a = wr[u], bq = xr[u];
                        dot += a.x*bq.x + a.y*bq.y + a.z*bq.z + a.w*bq.w;
                    }
                    float v = dot + g_b1p[h];
                    sc += gelu_w2(v, g_w2p[h]);
                }
#pragma unroll
                for (int o = 16; o; o >>= 1) sc += __shfl_xor_sync(0xffffffffu, sc, o);
                float score = sc + b2v;
                float pert = score + gumbel_of((uint32_t)(row*TT + t));  // attn==1
                ex = pert;
                __syncwarp();
            }
            if (lane == 0) cand_pert[c] = ex;
        }
    }
    __syncthreads();

    // ---- select top-'need' among candidates (rank by strict greater)
    if (refine && tid == 0) {
        int need = ki - sh_above;
        for (int c = 0; c < ncand; ++c) {
            int rank = 0;
            float pc = cand_pert[c];
            for (int c2 = 0; c2 < ncand; ++c2)
                if (cand_pert[c2] > pc) rank++;
            cand_sel[c] = (rank < need) ? 1 : 0;
        }
    }
    __syncthreads();

    // ---- g output (store into s_a for TV)
    for (int t = tid; t < TT; t += 1024) {
        float p = s_cum[t];
        float a0 = s_attn[t];
        float gv;
        if (refine) {
            if (p > hiW) gv = a0;
            else if (p >= loW) {
                gv = 0.f;
                for (int c = 0; c < ncand; ++c)
                    if (cand_idx[c] == t) { gv = cand_sel[c] ? a0 : 0.f; break; }
            } else gv = 0.f;
        } else {
            gv = (p >= thr) ? a0 : 0.f;
        }
        out[BT + row*TT + t] = gv;
        s_a[t] = gv;
    }
    __syncthreads();

    // ---- TV
    float num = 0.f, den = 0.f;
    for (int t = tid; t < TT - 1; t += 1024) {
        float valid = s_attn[t] * s_attn[t+1];
        num += fabsf(s_a[t+1] - s_a[t]) * valid;
        den += valid;
    }
    for (int o = 16; o; o >>= 1) {
        num += __shfl_xor_sync(0xffffffffu, num, o);
        den += __shfl_xor_sync(0xffffffffu, den, o);
    }
    if (lane == 0) { red[wid] = num; red2[wid] = den; }
    __syncthreads();
    if (tid == 0) {
        float a = 0.f, b = 0.f;
        for (int w = 0; w < 32; w++) { a += red[w]; b += red2[w]; }
        g_tv[row] = a / fmaxf(b, 1.f);
    }
}

__global__ void kernelC(float* __restrict__ out)
{
    __shared__ float r[64];
    r[threadIdx.x] = g_tv[threadIdx.x];
    __syncthreads();
    if (threadIdx.x == 0) {
        float s = 0.f;
        for (int i = 0; i < 64; i++) s += r[i];
        out[2*BT] = 0.1f * (s / 64.f);
    }
}

extern "C" void kernel_launch(void* const* d_in, const int* in_sizes, int n_in,
                              void* d_out, int out_size)
{
    const float* emb   = (const float*)d_in[0];
    const float* attn  = (const float*)d_in[1];
    const float* gamma = (const float*)d_in[2];
    const float* beta  = (const float*)d_in[3];
    const float* W1    = (const float*)d_in[4];
    const float* b1    = (const float*)d_in[5];
    const float* W2    = (const float*)d_in[6];
    const float* b2    = (const float*)d_in[7];
    float* out = (float*)d_out;

    cudaFuncSetAttribute(kernelA, cudaFuncAttributeMaxDynamicSharedMemorySize, SMEM_A_TOT);
    cudaFuncSetAttribute(kernelB, cudaFuncAttributeMaxDynamicSharedMemorySize, SMEM_B);

    kernelW<<<NP, 256>>>(W1, b1, W2);
    kernelA<<<BT/128, 512, SMEM_A_TOT>>>(emb, attn, gamma, beta, b2);
    kernelB<<<BB, 1024, SMEM_B>>>(attn, emb, gamma, beta, b2, out);
    kernelC<<<1, 64>>>(out);
}

// round 12
// speedup vs baseline: 3.6324x; 1.1154x over previous
#include <cuda_runtime.h>
#include <cuda_fp16.h>
#include <cstdint>
#include <math.h>

// Problem constants
#define BB 64
#define TT 4096
#define DD 256
#define HH 341
#define BT (BB*TT)
#define NEGV (-1e9f)
#define NP 352            // hidden padded to 11*32
#define NCHUNK 11         // 32 n-cols per chunk
#define LSCALE 2048.0f
#define INV_LSCALE (1.0f/2048.0f)

__device__ float g_scores[BT];
__device__ float g_tv[BB];
__device__ __align__(16) __half g_w1t_hi[NP*DD];   // W1^T [h][d] fp16 hi
__device__ __align__(16) __half g_w1t_lo[NP*DD];   // fp16 residual * 2048
__device__ __align__(16) float g_w1t32[NP*DD];     // W1^T fp32 (refinement)
__device__ float g_b1p[NP];
__device__ float g_w2p[NP];

// f32-accumulator fp16 MMA
#define MMA16816F(d, a0,a1,a2,a3, b0,b1) \
    asm volatile("mma.sync.aligned.m16n8k16.row.col.f32.f16.f16.f32 " \
        "{%0,%1,%2,%3}, {%4,%5,%6,%7}, {%8,%9}, {%0,%1,%2,%3};" \
        : "+f"((d)[0]), "+f"((d)[1]), "+f"((d)[2]), "+f"((d)[3]) \
        : "r"(a0), "r"(a1), "r"(a2), "r"(a3), "r"(b0), "r"(b1))

// f16-accumulator fp16 MMA (c0 = halves r0,r1; c1 = halves r2,r3)
#define MMA16816H(c0, c1, a0,a1,a2,a3, b0,b1) \
    asm volatile("mma.sync.aligned.m16n8k16.row.col.f16.f16.f16.f16 " \
        "{%0,%1}, {%2,%3,%4,%5}, {%6,%7}, {%0,%1};" \
        : "+r"(c0), "+r"(c1) \
        : "r"(a0), "r"(a1), "r"(a2), "r"(a3), "r"(b0), "r"(b1))

#define LDSM_X4(r0,r1,r2,r3, addr) \
    asm volatile("ldmatrix.sync.aligned.m8n8.x4.shared.b16 {%0,%1,%2,%3}, [%4];" \
        : "=r"(r0), "=r"(r1), "=r"(r2), "=r"(r3) : "r"(addr))

#define CP_ASYNC16(dst, src) \
    asm volatile("cp.async.cg.shared.global [%0], [%1], 16;" :: "r"(dst), "l"(src))
#define CP_COMMIT() asm volatile("cp.async.commit_group;" ::: "memory")
#define CP_WAIT(n)  asm volatile("cp.async.wait_group %0;" :: "n"(n) : "memory")

__device__ __forceinline__ uint32_t smem_u32(const void* p) {
    uint32_t a;
    asm("{ .reg .u64 t; cvta.to.shared.u64 t, %1; cvt.u32.u64 %0, t; }" : "=r"(a) : "l"(p));
    return a;
}
__device__ __forceinline__ uint32_t packh(__half a, __half b) {
    return (uint32_t)__half_as_ushort(a) | ((uint32_t)__half_as_ushort(b) << 16);
}
__device__ __forceinline__ float2 h2f2(uint32_t v) {
    __half2 h = *reinterpret_cast<__half2*>(&v);
    return __half22float2(h);
}
__device__ __forceinline__ float gelu_w2(float v, float w2v) {
    return 0.5f*v*(1.f + erff(v*0.70710678118654752f)) * w2v;
}

// ---------------------------------------------------------------------------
// Prologue: transpose + fp16-split W1 (lo pre-scaled by 2048), pad b1/W2
// ---------------------------------------------------------------------------
__global__ void kernelW(const float* __restrict__ W1, const float* __restrict__ b1,
                        const float* __restrict__ W2)
{
    int h = blockIdx.x;       // 0..351
    int d = threadIdx.x;      // 0..255
    float w = (h < HH) ? W1[d*HH + h] : 0.f;
    __half hi = __float2half_rn(w);
    __half lo = __float2half_rn((w - __half2float(hi)) * LSCALE);
    g_w1t_hi[h*DD + d] = hi;
    g_w1t_lo[h*DD + d] = lo;
    g_w1t32[h*DD + d] = w;
    if (d == 0) {
        g_b1p[h] = (h < HH) ? b1[h] : 0.f;
        g_w2p[h] = (h < HH) ? W2[h] : 0.f;
    }
}

// ---------------------------------------------------------------------------
// Kernel A: emb*attn -> LN -> ldmatrix+mma fp16 3-term GEMM -> GELU -> dot W2
// Block = 64 tokens, 256 threads (8 warps: 4 m-tiles x 2 n-halves), ~102KB
// smem -> 2 blocks/SM so independent blocks overlap each other's barriers.
// B single-buffered (cp.async prefetch of chunk 0 overlaps the A build).
// ---------------------------------------------------------------------------
#define RP 528            // padded row pitch (bytes), 256 fp16 = 512B data
#define OFF_AHI 0                 // 64*528 = 33792
#define OFF_ALO 33792             // 33792
#define OFF_B   67584             // hi 16896 + lo 16896 = 33792
#define OFF_ATTN 101376           // 64 floats
#define OFF_B1P 101632            // 352 floats
#define OFF_W2P 103040            // 352 floats
#define OFF_SC  104448            // 64 floats
#define OFF_ANY 104704
#define SMEM_A_TOT 104768

extern __shared__ char smx[];

__device__ __forceinline__ void stage_B(int c, int tid, uint32_t sb) {
    // chunk c: rows [c*32, c*32+32) of g_w1t_{hi,lo}, 32 uint4 per row
#pragma unroll
    for (int i = 0; i < 8; ++i) {
        int v = tid + i*256;              // 0..2047
        int half_ = v >> 10;              // 0=hi, 1=lo
        int r = (v >> 5) & 31;
        int u = v & 31;
        const uint4* src = (half_ ? (const uint4*)g_w1t_lo : (const uint4*)g_w1t_hi)
                         + (size_t)(c*32 + r)*32 + u;
        uint32_t dst = sb + OFF_B + half_*16896 + r*RP + u*16;
        CP_ASYNC16(dst, src);
    }
}

__global__ __launch_bounds__(256, 2)
void kernelA(const float* __restrict__ emb, const float* __restrict__ attn,
             const float* __restrict__ gamma_, const float* __restrict__ beta_,
             const float* __restrict__ b2)
{
    const int tid = threadIdx.x, lane = tid & 31, wid = tid >> 5;
    const int base = blockIdx.x * 64;
    uint32_t sb = smem_u32(smx);

    float* s_attn = (float*)(smx + OFF_ATTN);
    float* s_b1p  = (float*)(smx + OFF_B1P);
    float* s_w2p  = (float*)(smx + OFF_W2P);
    float* s_sc   = (float*)(smx + OFF_SC);
    int*   s_any  = (int*)(smx + OFF_ANY);

    if (tid == 0) *s_any = 0;
    __syncthreads();
    if (tid < 64) {
        float a = attn[base + tid];
        s_attn[tid] = a;
        s_sc[tid] = 0.f;
        if (a != 0.f) *s_any = 1;   // benign race
    }
    __syncthreads();
    if (!*s_any) {
        if (tid < 64) g_scores[base + tid] = NEGV;
        return;
    }

    // prefetch B chunk 0 while we build A
    stage_B(0, tid, sb);
    CP_COMMIT();

    if (tid < NP) s_b1p[tid] = g_b1p[tid], s_w2p[tid] = g_w2p[tid];
    if (tid + 256 < NP) { s_b1p[tid+256] = g_b1p[tid+256]; s_w2p[tid+256] = g_w2p[tid+256]; }

    // ---- LN + fp16 hi/lo split (lo * 2048) -> A tiles (warp w: tokens 8w..8w+7)
    for (int it = 0; it < 8; ++it) {
        int mt = wid * 8 + it;
        const float4* e4 = (const float4*)(emb + (size_t)(base + mt) * DD);
        float4 va = e4[lane*2], vb = e4[lane*2 + 1];
        float am = s_attn[mt];
        va.x *= am; va.y *= am; va.z *= am; va.w *= am;
        vb.x *= am; vb.y *= am; vb.z *= am; vb.w *= am;
        float s  = va.x+va.y+va.z+va.w+vb.x+vb.y+vb.z+vb.w;
        float s2 = va.x*va.x+va.y*va.y+va.z*va.z+va.w*va.w
                 + vb.x*vb.x+vb.y*vb.y+vb.z*vb.z+vb.w*vb.w;
#pragma unroll
        for (int o = 16; o; o >>= 1) {
            s  += __shfl_xor_sync(0xffffffffu, s, o);
            s2 += __shfl_xor_sync(0xffffffffu, s2, o);
        }
        float mu = s * (1.f/256.f);
        float rstd = rsqrtf(s2 * (1.f/256.f) - mu*mu + 1e-5f);

        float x[8] = {va.x, va.y, va.z, va.w, vb.x, vb.y, vb.z, vb.w};
        uint32_t qh[4], ql[4];
        const int d0 = lane * 8;
#pragma unroll
        for (int p = 0; p < 4; ++p) {
            float x0 = (x[2*p]   - mu) * rstd * gamma_[d0+2*p]   + beta_[d0+2*p];
            float x1 = (x[2*p+1] - mu) * rstd * gamma_[d0+2*p+1] + beta_[d0+2*p+1];
            __half h0 = __float2half_rn(x0);
            __half h1 = __float2half_rn(x1);
            __half l0 = __float2half_rn((x0 - __half2float(h0)) * LSCALE);
            __half l1 = __float2half_rn((x1 - __half2float(h1)) * LSCALE);
            qh[p] = packh(h0, h1);
            ql[p] = packh(l0, l1);
        }
        uint32_t off = mt * RP + lane * 16;
        *(uint4*)(smx + OFF_AHI + off) = make_uint4(qh[0],qh[1],qh[2],qh[3]);
        *(uint4*)(smx + OFF_ALO + off) = make_uint4(ql[0],ql[1],ql[2],ql[3]);
    }

    const int wm = wid & 3;        // m-tile (0..3)
    const int wn = wid >> 2;       // n-half (0/1)
    const int m0 = wm * 16;
    const int g = lane >> 2, q = lane & 3;
    const int lrow = lane & 15;
    const int lcol = (lane >> 4) * 16;

    const uint32_t aAddrHi = sb + OFF_AHI + (m0 + lrow) * RP + lcol;
    const uint32_t aAddrLo = sb + OFF_ALO + (m0 + lrow) * RP + lcol;
    const uint32_t bHi = sb + OFF_B + (wn*16 + lrow) * RP + lcol;
    const uint32_t bLo = bHi + 16896;

    float part0 = 0.f, part1 = 0.f;

    for (int c = 0; c < NCHUNK; ++c) {
        CP_WAIT(0);
        __syncthreads();    // B chunk c visible to all

        // hi x hi: f32 accum; cross terms: f16 accum (x2048 scaled residuals)
        float hA0[4] = {0.f,0.f,0.f,0.f};
        float hA1[4] = {0.f,0.f,0.f,0.f};
        uint32_t xA0a = 0u, xA0b = 0u;
        uint32_t xB0a = 0u, xB0b = 0u;
        uint32_t xA1a = 0u, xA1b = 0u;
        uint32_t xB1a = 0u, xB1b = 0u;

#pragma unroll 4
        for (int ks = 0; ks < 16; ++ks) {
            const int kb = ks * 32;
            uint32_t ah0,ah1,ah2,ah3, al0,al1,al2,al3;
            uint32_t bh0,bh1,bh2,bh3, bl0,bl1,bl2,bl3;
            LDSM_X4(ah0,ah1,ah2,ah3, aAddrHi + kb);
            LDSM_X4(al0,al1,al2,al3, aAddrLo + kb);
            LDSM_X4(bh0,bh1,bh2,bh3, bHi + kb);
            LDSM_X4(bl0,bl1,bl2,bl3, bLo + kb);
            MMA16816F(hA0, ah0,ah1,ah2,ah3, bh0,bh2);
            MMA16816H(xA0a,xA0b, ah0,ah1,ah2,ah3, bl0,bl2);
            MMA16816H(xB0a,xB0b, al0,al1,al2,al3, bh0,bh2);
            MMA16816F(hA1, ah0,ah1,ah2,ah3, bh1,bh3);
            MMA16816H(xA1a,xA1b, ah0,ah1,ah2,ah3, bl1,bl3);
            MMA16816H(xB1a,xB1b, al0,al1,al2,al3, bh1,bh3);
        }

        __syncthreads();    // all warps done reading buf before restage
        if (c + 1 < NCHUNK) { stage_B(c+1, tid, sb); CP_COMMIT(); }

        // epilogue: combine (hi + cross/2048), bias + gelu + * W2
        {
            float2 pA0 = h2f2(xA0a), pA0b = h2f2(xA0b);
            float2 pB0 = h2f2(xB0a), pB0b = h2f2(xB0b);
            float2 pA1 = h2f2(xA1a), pA1b = h2f2(xA1b);
            float2 pB1 = h2f2(xB1a), pB1b = h2f2(xB1b);
            float acc0[4], acc1[4];
            acc0[0] = hA0[0] + (pA0.x  + pB0.x ) * INV_LSCALE;
            acc0[1] = hA0[1] + (pA0.y  + pB0.y ) * INV_LSCALE;
            acc0[2] = hA0[2] + (pA0b.x + pB0b.x) * INV_LSCALE;
            acc0[3] = hA0[3] + (pA0b.y + pB0b.y) * INV_LSCALE;
            acc1[0] = hA1[0] + (pA1.x  + pB1.x ) * INV_LSCALE;
            acc1[1] = hA1[1] + (pA1.y  + pB1.y ) * INV_LSCALE;
            acc1[2] = hA1[2] + (pA1b.x + pB1b.x) * INV_LSCALE;
            acc1[3] = hA1[3] + (pA1b.y + pB1b.y) * INV_LSCALE;

            int hb = c*32 + wn*16 + 2*q;
            float b1a = s_b1p[hb],   w2a = s_w2p[hb];
            float b1b = s_b1p[hb+1], w2b = s_w2p[hb+1];
            part0 += gelu_w2(acc0[0] + b1a, w2a) + gelu_w2(acc0[1] + b1b, w2b);
            part1 += gelu_w2(acc0[2] + b1a, w2a) + gelu_w2(acc0[3] + b1b, w2b);
            int hc = hb + 8;
            float b1c = s_b1p[hc],   w2c = s_w2p[hc];
            float b1d = s_b1p[hc+1], w2d = s_w2p[hc+1];
            part0 += gelu_w2(acc1[0] + b1c, w2c) + gelu_w2(acc1[1] + b1d, w2d);
            part1 += gelu_w2(acc1[2] + b1c, w2c) + gelu_w2(acc1[3] + b1d, w2d);
        }
    }

    part0 += __shfl_xor_sync(0xffffffffu, part0, 1);
    part0 += __shfl_xor_sync(0xffffffffu, part0, 2);
    part1 += __shfl_xor_sync(0xffffffffu, part1, 1);
    part1 += __shfl_xor_sync(0xffffffffu, part1, 2);
    if (q == 0) {
        atomicAdd(&s_sc[m0 + g], part0);
        atomicAdd(&s_sc[m0 + g + 8], part1);
    }
    __syncthreads();
    if (tid < 64) {
        float sc = s_sc[tid] + b2[0];
        if (s_attn[tid] == 0.f) sc = NEGV;
        g_scores[base + tid] = sc;
    }
}

// ---------------------------------------------------------------------------
// Threefry-2x32-20, JAX partitionable: ctr=(0,i), draw = out0 ^ out1
// ---------------------------------------------------------------------------
__device__ __forceinline__ uint32_t rotl32(uint32_t x, int r) { return (x << r) | (x >> (32 - r)); }
__device__ __forceinline__ void tf_r4(uint32_t& x0, uint32_t& x1, int a, int b, int c, int d) {
    x0 += x1; x1 = rotl32(x1, a); x1 ^= x0;
    x0 += x1; x1 = rotl32(x1, b); x1 ^= x0;
    x0 += x1; x1 = rotl32(x1, c); x1 ^= x0;
    x0 += x1; x1 = rotl32(x1, d); x1 ^= x0;
}
__device__ __forceinline__ uint32_t jax_bits(uint32_t i) {
    const uint32_t k0 = 0u, k1 = 42u;
    const uint32_t k2 = k0 ^ k1 ^ 0x1BD11BDAu;
    uint32_t x0 = 0u + k0;
    uint32_t x1 = i  + k1;
    tf_r4(x0, x1, 13, 15, 26, 6);   x0 += k1; x1 += k2 + 1u;
    tf_r4(x0, x1, 17, 29, 16, 24);  x0 += k2; x1 += k0 + 2u;
    tf_r4(x0, x1, 13, 15, 26, 6);   x0 += k0; x1 += k1 + 3u;
    tf_r4(x0, x1, 17, 29, 16, 24);  x0 += k1; x1 += k2 + 4u;
    tf_r4(x0, x1, 13, 15, 26, 6);   x0 += k2; x1 += k0 + 5u;
    return x0 ^ x1;
}
__device__ __forceinline__ float gumbel_of(uint32_t lin) {
    uint32_t bits = jax_bits(lin);
    float u = __uint_as_float((bits >> 9) | 0x3f800000u) - 1.0f;
    u = fmaxf(u, 0.f);
    return -logf(-logf(u + 1e-6f) + 1e-6f);
}

__device__ void bitonic_desc(float* a, int tid, int nthr) {
    for (int k = 2; k <= 4096; k <<= 1) {
        for (int j = k >> 1; j > 0; j >>= 1) {
            __syncthreads();
            for (int i = tid; i < 4096; i += nthr) {
                int ixj = i ^ j;
                if (ixj > i) {
                    float x = a[i], y = a[ixj];
                    bool up = ((i & k) == 0);
                    if (up ? (x < y) : (x > y)) { a[i] = y; a[ixj] = x; }
                }
            }
        }
    }
    __syncthreads();
}

// ---------------------------------------------------------------------------
// Kernel B: entmax1.5 + gumbel top-k with EXACT boundary refinement + TV
// ---------------------------------------------------------------------------
#define EPS_W 5e-4f
#define MAXC 64
#define SMEM_B ((5*4096 + 32*256)*4)

__global__ __launch_bounds__(1024, 1)
void kernelB(const float* __restrict__ attn, const float* __restrict__ emb,
             const float* __restrict__ gamma_, const float* __restrict__ beta_,
             const float* __restrict__ b2, float* __restrict__ out)
{
    extern __shared__ float sm[];
    float* s_scores = sm;
    float* s_attn   = sm + 4096;
    float* s_a      = sm + 8192;
    float* s_cum    = sm + 12288;
    float* s_cum2   = sm + 16384;
    float* s_xn     = sm + 20480;     // [32 warps][256]
    __shared__ float red[32], red2[32];
    __shared__ float sh_mx, sh_teff, sh_tau, sh_thr;
    __shared__ int sh_support, sh_above, sh_ncand;
    __shared__ int cand_idx[MAXC];
    __shared__ float cand_pert[MAXC];
    __shared__ int cand_sel[MAXC];

    const int row = blockIdx.x;
    const int tid = threadIdx.x;
    const int lane = tid & 31, wid = tid >> 5;

    float tf_ = 0.f, mx = -3.402823466e38f;
    for (int t = tid; t < TT; t += 1024) {
        float s = g_scores[row*TT + t];
        float a = attn[row*TT + t];
        s_scores[t] = s; s_attn[t] = a;
        tf_ += a; mx = fmaxf(mx, s);
    }
    for (int o = 16; o; o >>= 1) {
        tf_ += __shfl_xor_sync(0xffffffffu, tf_, o);
        mx = fmaxf(mx, __shfl_xor_sync(0xffffffffu, mx, o));
    }
    if (lane == 0) { red[wid] = tf_; red2[wid] = mx; }
    __syncthreads();
    if (tid == 0) {
        float a = 0.f, b = -3.402823466e38f;
        for (int w = 0; w < 32; w++) { a += red[w]; b = fmaxf(b, red2[w]); }
        sh_teff = a; sh_mx = b;
        sh_support = 0; sh_above = 0; sh_ncand = 0;
    }
    __syncthreads();
    mx = sh_mx;

    // ---- entmax 1.5
    for (int t = tid; t < TT; t += 1024) s_a[t] = (s_scores[t] - mx) * 0.5f;
    bitonic_desc(s_a, tid, 1024);

    const int p0 = tid * 4;
    {
        float v0 = s_a[p0+0], v1 = s_a[p0+1], v2 = s_a[p0+2], v3 = s_a[p0+3];
        float c0 = v0, c1 = c0 + v1, c2 = c1 + v2, c3 = c2 + v3;
        float d0 = v0*v0, d1 = d0 + v1*v1, d2 = d1 + v2*v2, d3 = d2 + v3*v3;
        float s = c3, s2 = d3;
        const float tot = c3, tot2 = d3;
        for (int o = 1; o < 32; o <<= 1) {
            float n  = __shfl_up_sync(0xffffffffu, s, o);
            float n2 = __shfl_up_sync(0xffffffffu, s2, o);
            if (lane >= o) { s += n; s2 += n2; }
        }
        if (lane == 31) { red[wid] = s; red2[wid] = s2; }
        __syncthreads();
        if (wid == 0) {
            float w = red[lane], w2 = red2[lane];
            for (int o = 1; o < 32; o <<= 1) {
                float n  = __shfl_up_sync(0xffffffffu, w, o);
                float n2 = __shfl_up_sync(0xffffffffu, w2, o);
                if (lane >= o) { w += n; w2 += n2; }
            }
            red[lane] = w; red2[lane] = w2;
        }
        __syncthreads();
        float base  = (wid ? red[wid-1]  : 0.f) + (s  - tot);
        float base2 = (wid ? red2[wid-1] : 0.f) + (s2 - tot2);
        s_cum[p0+0] = base + c0;  s_cum[p0+1] = base + c1;
        s_cum[p0+2] = base + c2;  s_cum[p0+3] = base + c3;
        s_cum2[p0+0] = base2 + d0; s_cum2[p0+1] = base2 + d1;
        s_cum2[p0+2] = base2 + d2; s_cum2[p0+3] = base2 + d3;
    }
    __syncthreads();

    int cnt = 0;
#pragma unroll
    for (int j = 0; j < 4; j++) {
        int p = p0 + j;
        float rho = (float)(p + 1);
        float mean = s_cum[p] / rho;
        float msq  = s_cum2[p] / rho;
        float ssv  = rho * (msq - mean*mean);
        float delta = (1.f - ssv) / rho;
        float tau = mean - sqrtf(fmaxf(delta, 0.f));
        cnt += (tau <= s_a[p]) ? 1 : 0;
    }
    for (int o = 16; o; o >>= 1) cnt += __shfl_xor_sync(0xffffffffu, cnt, o);
    if (lane == 0) atomicAdd(&sh_support, cnt);
    __syncthreads();
    if (tid == 0) {
        int p = sh_support - 1;
        float rho = (float)(p + 1);
        float mean = s_cum[p] / rho;
        float msq  = s_cum2[p] / rho;
        float ssv  = rho * (msq - mean*mean);
        float delta = (1.f - ssv) / rho;
        sh_tau = mean - sqrtf(fmaxf(delta, 0.f));
    }
    __syncthreads();
    const float taustar = sh_tau;

    for (int t = tid; t < TT; t += 1024) {
        float x = (s_scores[t] - mx) * 0.5f;
        float dd = fmaxf(x - taustar, 0.f);
        out[row*TT + t] = dd*dd*s_attn[t];
    }
    __syncthreads();

    // ---- gumbel-perturbed scores
    for (int t = tid; t < TT; t += 1024) {
        float gum = gumbel_of((uint32_t)(row*TT + t));
        float pert = s_scores[t] * s_attn[t] + gum;
        s_cum[t] = pert;
        s_a[t] = (pert != pert) ? __int_as_float(0xff800000) : pert;
    }
    bitonic_desc(s_a, tid, 1024);

    const float teff = sh_teff;
    float kf = rintf(0.3f * teff);
    kf = fminf(fmaxf(kf, 1.f), fmaxf(teff, 1.f));
    const int ki = (int)kf;
    if (tid == 0) sh_thr = s_a[ki - 1];
    __syncthreads();
    const float thr = sh_thr;
    const float hiW = thr + EPS_W, loW = thr - EPS_W;

    // ---- classification counts + candidate gather
    {
        int my_above = 0;
        for (int t = tid; t < TT; t += 1024) {
            float p = s_cum[t];
            if (p > hiW) my_above++;
            else if (p >= loW) {
                int pos = atomicAdd(&sh_ncand, 1);
                if (pos < MAXC) cand_idx[pos] = t;
            }
        }
        for (int o = 16; o; o >>= 1) my_above += __shfl_xor_sync(0xffffffffu, my_above, o);
        if (lane == 0) atomicAdd(&sh_above, my_above);
    }
    __syncthreads();
    const int ncand = sh_ncand;
    const bool refine = (ncand <= MAXC);

    // ---- exact recompute of candidate perts (warp per candidate)
    if (refine) {
        const float b2v = b2[0];
        for (int c = wid; c < ncand; c += 32) {
            int t = cand_idx[c];
            float ex;
            if (s_attn[t] == 0.f) {
                ex = s_cum[t];    // masked: pert = gumbel, already exact
            } else {
                const float4* e4 = (const float4*)(emb + ((size_t)row*TT + t)*DD);
                float4 va = e4[lane*2], vb = e4[lane*2+1];
                float s  = va.x+va.y+va.z+va.w+vb.x+vb.y+vb.z+vb.w;
                float s2 = va.x*va.x+va.y*va.y+va.z*va.z+va.w*va.w
                         + vb.x*vb.x+vb.y*vb.y+vb.z*vb.z+vb.w*vb.w;
#pragma unroll
                for (int o = 16; o; o >>= 1) {
                    s  += __shfl_xor_sync(0xffffffffu, s, o);
                    s2 += __shfl_xor_sync(0xffffffffu, s2, o);
                }
                float mu = s * (1.f/256.f);
                float rstd = rsqrtf(s2 * (1.f/256.f) - mu*mu + 1e-5f);
                float xv[8] = {va.x,va.y,va.z,va.w,vb.x,vb.y,vb.z,vb.w};
                float* xw = s_xn + wid*256 + lane*8;
#pragma unroll
                for (int p = 0; p < 8; ++p) {
                    int d = lane*8 + p;
                    xw[p] = (xv[p] - mu) * rstd * gamma_[d] + beta_[d];
                }
                __syncwarp();
                float sc = 0.f;
                for (int h = lane; h < HH; h += 32) {
                    const float4* wr = (const float4*)(g_w1t32 + (size_t)h*DD);
                    const float4* xr = (const float4*)(s_xn + wid*256);
                    float dot = 0.f;
#pragma unroll 8
                    for (int u = 0; u < 64; ++u) {
                        float4 a = wr[u], bq = xr[u];
                        dot += a.x*bq.x + a.y*bq.y + a.z*bq.z + a.w*bq.w;
                    }
                    float v = dot + g_b1p[h];
                    sc += gelu_w2(v, g_w2p[h]);
                }
#pragma unroll
                for (int o = 16; o; o >>= 1) sc += __shfl_xor_sync(0xffffffffu, sc, o);
                float score = sc + b2v;
                float pert = score + gumbel_of((uint32_t)(row*TT + t));  // attn==1
                ex = pert;
                __syncwarp();
            }
            if (lane == 0) cand_pert[c] = ex;
        }
    }
    __syncthreads();

    // ---- select top-'need' among candidates (rank by strict greater)
    if (refine && tid == 0) {
        int need = ki - sh_above;
        for (int c = 0; c < ncand; ++c) {
            int rank = 0;
            float pc = cand_pert[c];
            for (int c2 = 0; c2 < ncand; ++c2)
                if (cand_pert[c2] > pc) rank++;
            cand_sel[c] = (rank < need) ? 1 : 0;
        }
    }
    __syncthreads();

    // ---- g output (store into s_a for TV)
    for (int t = tid; t < TT; t += 1024) {
        float p = s_cum[t];
        float a0 = s_attn[t];
        float gv;
        if (refine) {
            if (p > hiW) gv = a0;
            else if (p >= loW) {
                gv = 0.f;
                for (int c = 0; c < ncand; ++c)
                    if (cand_idx[c] == t) { gv = cand_sel[c] ? a0 : 0.f; break; }
            } else gv = 0.f;
        } else {
            gv = (p >= thr) ? a0 : 0.f;
        }
        out[BT + row*TT + t] = gv;
        s_a[t] = gv;
    }
    __syncthreads();

    // ---- TV
    float num = 0.f, den = 0.f;
    for (int t = tid; t < TT - 1; t += 1024) {
        float valid = s_attn[t] * s_attn[t+1];
        num += fabsf(s_a[t+1] - s_a[t]) * valid;
        den += valid;
    }
    for (int o = 16; o; o >>= 1) {
        num += __shfl_xor_sync(0xffffffffu, num, o);
        den += __shfl_xor_sync(0xffffffffu, den, o);
    }
    if (lane == 0) { red[wid] = num; red2[wid] = den; }
    __syncthreads();
    if (tid == 0) {
        float a = 0.f, b = 0.f;
        for (int w = 0; w < 32; w++) { a += red[w]; b += red2[w]; }
        g_tv[row] = a / fmaxf(b, 1.f);
    }
}

__global__ void kernelC(float* __restrict__ out)
{
    __shared__ float r[64];
    r[threadIdx.x] = g_tv[threadIdx.x];
    __syncthreads();
    if (threadIdx.x == 0) {
        float s = 0.f;
        for (int i = 0; i < 64; i++) s += r[i];
        out[2*BT] = 0.1f * (s / 64.f);
    }
}

extern "C" void kernel_launch(void* const* d_in, const int* in_sizes, int n_in,
                              void* d_out, int out_size)
{
    const float* emb   = (const float*)d_in[0];
    const float* attn  = (const float*)d_in[1];
    const float* gamma = (const float*)d_in[2];
    const float* beta  = (const float*)d_in[3];
    const float* W1    = (const float*)d_in[4];
    const float* b1    = (const float*)d_in[5];
    const float* W2    = (const float*)d_in[6];
    const float* b2    = (const float*)d_in[7];
    float* out = (float*)d_out;

    cudaFuncSetAttribute(kernelA, cudaFuncAttributeMaxDynamicSharedMemorySize, SMEM_A_TOT);
    cudaFuncSetAttribute(kernelB, cudaFuncAttributeMaxDynamicSharedMemorySize, SMEM_B);

    kernelW<<<NP, 256>>>(W1, b1, W2);
    kernelA<<<BT/64, 256, SMEM_A_TOT>>>(emb, attn, gamma, beta, b2);
    kernelB<<<BB, 1024, SMEM_B>>>(attn, emb, gamma, beta, b2, out);
    kernelC<<<1, 64>>>(out);
}

// round 13
// speedup vs baseline: 4.0391x; 1.1120x over previous
#include <cuda_runtime.h>
#include <cuda_fp16.h>
#include <cstdint>
#include <math.h>

// Problem constants
#define BB 64
#define TT 4096
#define DD 256
#define HH 341
#define BT (BB*TT)
#define NEGV (-1e9f)
#define NP 352            // hidden padded to 11*32
#define NCHUNK 11         // 32 n-cols per chunk
#define LSCALE 2048.0f
#define INV_LSCALE (1.0f/2048.0f)

__device__ float g_scores[BT];
__device__ float g_tv[BB];
__device__ __align__(16) __half g_w1t_hi[NP*DD];   // W1^T [h][d] fp16 hi
__device__ __align__(16) __half g_w1t_lo[NP*DD];   // fp16 residual * 2048
__device__ __align__(16) float g_w1t32[NP*DD];     // W1^T fp32 (refinement)
__device__ float g_b1p[NP];
__device__ float g_w2p[NP];

// f32-accumulator fp16 MMA
#define MMA16816F(d, a0,a1,a2,a3, b0,b1) \
    asm volatile("mma.sync.aligned.m16n8k16.row.col.f32.f16.f16.f32 " \
        "{%0,%1,%2,%3}, {%4,%5,%6,%7}, {%8,%9}, {%0,%1,%2,%3};" \
        : "+f"((d)[0]), "+f"((d)[1]), "+f"((d)[2]), "+f"((d)[3]) \
        : "r"(a0), "r"(a1), "r"(a2), "r"(a3), "r"(b0), "r"(b1))

// f16-accumulator fp16 MMA (c0 = halves r0,r1; c1 = halves r2,r3)
#define MMA16816H(c0, c1, a0,a1,a2,a3, b0,b1) \
    asm volatile("mma.sync.aligned.m16n8k16.row.col.f16.f16.f16.f16 " \
        "{%0,%1}, {%2,%3,%4,%5}, {%6,%7}, {%0,%1};" \
        : "+r"(c0), "+r"(c1) \
        : "r"(a0), "r"(a1), "r"(a2), "r"(a3), "r"(b0), "r"(b1))

#define LDSM_X4(r0,r1,r2,r3, addr) \
    asm volatile("ldmatrix.sync.aligned.m8n8.x4.shared.b16 {%0,%1,%2,%3}, [%4];" \
        : "=r"(r0), "=r"(r1), "=r"(r2), "=r"(r3) : "r"(addr))

#define CP_ASYNC16(dst, src) \
    asm volatile("cp.async.cg.shared.global [%0], [%1], 16;" :: "r"(dst), "l"(src))
#define CP_COMMIT() asm volatile("cp.async.commit_group;" ::: "memory")
#define CP_WAIT(n)  asm volatile("cp.async.wait_group %0;" :: "n"(n) : "memory")

__device__ __forceinline__ uint32_t smem_u32(const void* p) {
    uint32_t a;
    asm("{ .reg .u64 t; cvta.to.shared.u64 t, %1; cvt.u32.u64 %0, t; }" : "=r"(a) : "l"(p));
    return a;
}
__device__ __forceinline__ uint32_t packh(__half a, __half b) {
    return (uint32_t)__half_as_ushort(a) | ((uint32_t)__half_as_ushort(b) << 16);
}
__device__ __forceinline__ float2 h2f2(uint32_t v) {
    __half2 h = *reinterpret_cast<__half2*>(&v);
    return __half22float2(h);
}
__device__ __forceinline__ float gelu_w2(float v, float w2v) {
    return 0.5f*v*(1.f + erff(v*0.70710678118654752f)) * w2v;
}

// ---------------------------------------------------------------------------
// Prologue: transpose + fp16-split W1 (lo pre-scaled by 2048), pad b1/W2
// ---------------------------------------------------------------------------
__global__ void kernelW(const float* __restrict__ W1, const float* __restrict__ b1,
                        const float* __restrict__ W2)
{
    int h = blockIdx.x;       // 0..351
    int d = threadIdx.x;      // 0..255
    float w = (h < HH) ? W1[d*HH + h] : 0.f;
    __half hi = __float2half_rn(w);
    __half lo = __float2half_rn((w - __half2float(hi)) * LSCALE);
    g_w1t_hi[h*DD + d] = hi;
    g_w1t_lo[h*DD + d] = lo;
    g_w1t32[h*DD + d] = w;
    if (d == 0) {
        g_b1p[h] = (h < HH) ? b1[h] : 0.f;
        g_w2p[h] = (h < HH) ? W2[h] : 0.f;
    }
}

// ---------------------------------------------------------------------------
// Kernel A (unchanged from R12): 64-token blocks, 2 blocks/SM, fp16 3-term
// ---------------------------------------------------------------------------
#define RP 528
#define OFF_AHI 0
#define OFF_ALO 33792
#define OFF_B   67584
#define OFF_ATTN 101376
#define OFF_B1P 101632
#define OFF_W2P 103040
#define OFF_SC  104448
#define OFF_ANY 104704
#define SMEM_A_TOT 104768

extern __shared__ char smx[];

__device__ __forceinline__ void stage_B(int c, int tid, uint32_t sb) {
#pragma unroll
    for (int i = 0; i < 8; ++i) {
        int v = tid + i*256;
        int half_ = v >> 10;
        int r = (v >> 5) & 31;
        int u = v & 31;
        const uint4* src = (half_ ? (const uint4*)g_w1t_lo : (const uint4*)g_w1t_hi)
                         + (size_t)(c*32 + r)*32 + u;
        uint32_t dst = sb + OFF_B + half_*16896 + r*RP + u*16;
        CP_ASYNC16(dst, src);
    }
}

__global__ __launch_bounds__(256, 2)
void kernelA(const float* __restrict__ emb, const float* __restrict__ attn,
             const float* __restrict__ gamma_, const float* __restrict__ beta_,
             const float* __restrict__ b2)
{
    const int tid = threadIdx.x, lane = tid & 31, wid = tid >> 5;
    const int base = blockIdx.x * 64;
    uint32_t sb = smem_u32(smx);

    float* s_attn = (float*)(smx + OFF_ATTN);
    float* s_b1p  = (float*)(smx + OFF_B1P);
    float* s_w2p  = (float*)(smx + OFF_W2P);
    float* s_sc   = (float*)(smx + OFF_SC);
    int*   s_any  = (int*)(smx + OFF_ANY);

    if (tid == 0) *s_any = 0;
    __syncthreads();
    if (tid < 64) {
        float a = attn[base + tid];
        s_attn[tid] = a;
        s_sc[tid] = 0.f;
        if (a != 0.f) *s_any = 1;
    }
    __syncthreads();
    if (!*s_any) {
        if (tid < 64) g_scores[base + tid] = NEGV;
        return;
    }

    stage_B(0, tid, sb);
    CP_COMMIT();

    if (tid < NP) s_b1p[tid] = g_b1p[tid], s_w2p[tid] = g_w2p[tid];
    if (tid + 256 < NP) { s_b1p[tid+256] = g_b1p[tid+256]; s_w2p[tid+256] = g_w2p[tid+256]; }

    for (int it = 0; it < 8; ++it) {
        int mt = wid * 8 + it;
        const float4* e4 = (const float4*)(emb + (size_t)(base + mt) * DD);
        float4 va = e4[lane*2], vb = e4[lane*2 + 1];
        float am = s_attn[mt];
        va.x *= am; va.y *= am; va.z *= am; va.w *= am;
        vb.x *= am; vb.y *= am; vb.z *= am; vb.w *= am;
        float s  = va.x+va.y+va.z+va.w+vb.x+vb.y+vb.z+vb.w;
        float s2 = va.x*va.x+va.y*va.y+va.z*va.z+va.w*va.w
                 + vb.x*vb.x+vb.y*vb.y+vb.z*vb.z+vb.w*vb.w;
#pragma unroll
        for (int o = 16; o; o >>= 1) {
            s  += __shfl_xor_sync(0xffffffffu, s, o);
            s2 += __shfl_xor_sync(0xffffffffu, s2, o);
        }
        float mu = s * (1.f/256.f);
        float rstd = rsqrtf(s2 * (1.f/256.f) - mu*mu + 1e-5f);

        float x[8] = {va.x, va.y, va.z, va.w, vb.x, vb.y, vb.z, vb.w};
        uint32_t qh[4], ql[4];
        const int d0 = lane * 8;
#pragma unroll
        for (int p = 0; p < 4; ++p) {
            float x0 = (x[2*p]   - mu) * rstd * gamma_[d0+2*p]   + beta_[d0+2*p];
            float x1 = (x[2*p+1] - mu) * rstd * gamma_[d0+2*p+1] + beta_[d0+2*p+1];
            __half h0 = __float2half_rn(x0);
            __half h1 = __float2half_rn(x1);
            __half l0 = __float2half_rn((x0 - __half2float(h0)) * LSCALE);
            __half l1 = __float2half_rn((x1 - __half2float(h1)) * LSCALE);
            qh[p] = packh(h0, h1);
            ql[p] = packh(l0, l1);
        }
        uint32_t off = mt * RP + lane * 16;
        *(uint4*)(smx + OFF_AHI + off) = make_uint4(qh[0],qh[1],qh[2],qh[3]);
        *(uint4*)(smx + OFF_ALO + off) = make_uint4(ql[0],ql[1],ql[2],ql[3]);
    }

    const int wm = wid & 3;
    const int wn = wid >> 2;
    const int m0 = wm * 16;
    const int g = lane >> 2, q = lane & 3;
    const int lrow = lane & 15;
    const int lcol = (lane >> 4) * 16;

    const uint32_t aAddrHi = sb + OFF_AHI + (m0 + lrow) * RP + lcol;
    const uint32_t aAddrLo = sb + OFF_ALO + (m0 + lrow) * RP + lcol;
    const uint32_t bHi = sb + OFF_B + (wn*16 + lrow) * RP + lcol;
    const uint32_t bLo = bHi + 16896;

    float part0 = 0.f, part1 = 0.f;

    for (int c = 0; c < NCHUNK; ++c) {
        CP_WAIT(0);
        __syncthreads();

        float hA0[4] = {0.f,0.f,0.f,0.f};
        float hA1[4] = {0.f,0.f,0.f,0.f};
        uint32_t xA0a = 0u, xA0b = 0u;
        uint32_t xB0a = 0u, xB0b = 0u;
        uint32_t xA1a = 0u, xA1b = 0u;
        uint32_t xB1a = 0u, xB1b = 0u;

#pragma unroll 4
        for (int ks = 0; ks < 16; ++ks) {
            const int kb = ks * 32;
            uint32_t ah0,ah1,ah2,ah3, al0,al1,al2,al3;
            uint32_t bh0,bh1,bh2,bh3, bl0,bl1,bl2,bl3;
            LDSM_X4(ah0,ah1,ah2,ah3, aAddrHi + kb);
            LDSM_X4(al0,al1,al2,al3, aAddrLo + kb);
            LDSM_X4(bh0,bh1,bh2,bh3, bHi + kb);
            LDSM_X4(bl0,bl1,bl2,bl3, bLo + kb);
            MMA16816F(hA0, ah0,ah1,ah2,ah3, bh0,bh2);
            MMA16816H(xA0a,xA0b, ah0,ah1,ah2,ah3, bl0,bl2);
            MMA16816H(xB0a,xB0b, al0,al1,al2,al3, bh0,bh2);
            MMA16816F(hA1, ah0,ah1,ah2,ah3, bh1,bh3);
            MMA16816H(xA1a,xA1b, ah0,ah1,ah2,ah3, bl1,bl3);
            MMA16816H(xB1a,xB1b, al0,al1,al2,al3, bh1,bh3);
        }

        __syncthreads();
        if (c + 1 < NCHUNK) { stage_B(c+1, tid, sb); CP_COMMIT(); }

        {
            float2 pA0 = h2f2(xA0a), pA0b = h2f2(xA0b);
            float2 pB0 = h2f2(xB0a), pB0b = h2f2(xB0b);
            float2 pA1 = h2f2(xA1a), pA1b = h2f2(xA1b);
            float2 pB1 = h2f2(xB1a), pB1b = h2f2(xB1b);
            float acc0[4], acc1[4];
            acc0[0] = hA0[0] + (pA0.x  + pB0.x ) * INV_LSCALE;
            acc0[1] = hA0[1] + (pA0.y  + pB0.y ) * INV_LSCALE;
            acc0[2] = hA0[2] + (pA0b.x + pB0b.x) * INV_LSCALE;
            acc0[3] = hA0[3] + (pA0b.y + pB0b.y) * INV_LSCALE;
            acc1[0] = hA1[0] + (pA1.x  + pB1.x ) * INV_LSCALE;
            acc1[1] = hA1[1] + (pA1.y  + pB1.y ) * INV_LSCALE;
            acc1[2] = hA1[2] + (pA1b.x + pB1b.x) * INV_LSCALE;
            acc1[3] = hA1[3] + (pA1b.y + pB1b.y) * INV_LSCALE;

            int hb = c*32 + wn*16 + 2*q;
            float b1a = s_b1p[hb],   w2a = s_w2p[hb];
            float b1b = s_b1p[hb+1], w2b = s_w2p[hb+1];
            part0 += gelu_w2(acc0[0] + b1a, w2a) + gelu_w2(acc0[1] + b1b, w2b);
            part1 += gelu_w2(acc0[2] + b1a, w2a) + gelu_w2(acc0[3] + b1b, w2b);
            int hc = hb + 8;
            float b1c = s_b1p[hc],   w2c = s_w2p[hc];
            float b1d = s_b1p[hc+1], w2d = s_w2p[hc+1];
            part0 += gelu_w2(acc1[0] + b1c, w2c) + gelu_w2(acc1[1] + b1d, w2d);
            part1 += gelu_w2(acc1[2] + b1c, w2c) + gelu_w2(acc1[3] + b1d, w2d);
        }
    }

    part0 += __shfl_xor_sync(0xffffffffu, part0, 1);
    part0 += __shfl_xor_sync(0xffffffffu, part0, 2);
    part1 += __shfl_xor_sync(0xffffffffu, part1, 1);
    part1 += __shfl_xor_sync(0xffffffffu, part1, 2);
    if (q == 0) {
        atomicAdd(&s_sc[m0 + g], part0);
        atomicAdd(&s_sc[m0 + g + 8], part1);
    }
    __syncthreads();
    if (tid < 64) {
        float sc = s_sc[tid] + b2[0];
        if (s_attn[tid] == 0.f) sc = NEGV;
        g_scores[base + tid] = sc;
    }
}

// ---------------------------------------------------------------------------
// Threefry-2x32-20, JAX partitionable: ctr=(0,i), draw = out0 ^ out1
// ---------------------------------------------------------------------------
__device__ __forceinline__ uint32_t rotl32(uint32_t x, int r) { return (x << r) | (x >> (32 - r)); }
__device__ __forceinline__ void tf_r4(uint32_t& x0, uint32_t& x1, int a, int b, int c, int d) {
    x0 += x1; x1 = rotl32(x1, a); x1 ^= x0;
    x0 += x1; x1 = rotl32(x1, b); x1 ^= x0;
    x0 += x1; x1 = rotl32(x1, c); x1 ^= x0;
    x0 += x1; x1 = rotl32(x1, d); x1 ^= x0;
}
__device__ __forceinline__ uint32_t jax_bits(uint32_t i) {
    const uint32_t k0 = 0u, k1 = 42u;
    const uint32_t k2 = k0 ^ k1 ^ 0x1BD11BDAu;
    uint32_t x0 = 0u + k0;
    uint32_t x1 = i  + k1;
    tf_r4(x0, x1, 13, 15, 26, 6);   x0 += k1; x1 += k2 + 1u;
    tf_r4(x0, x1, 17, 29, 16, 24);  x0 += k2; x1 += k0 + 2u;
    tf_r4(x0, x1, 13, 15, 26, 6);   x0 += k0; x1 += k1 + 3u;
    tf_r4(x0, x1, 17, 29, 16, 24);  x0 += k1; x1 += k2 + 4u;
    tf_r4(x0, x1, 13, 15, 26, 6);   x0 += k2; x1 += k0 + 5u;
    return x0 ^ x1;
}
__device__ __forceinline__ float gumbel_of(uint32_t lin) {
    uint32_t bits = jax_bits(lin);
    float u = __uint_as_float((bits >> 9) | 0x3f800000u) - 1.0f;
    u = fmaxf(u, 0.f);
    return -logf(-logf(u + 1e-6f) + 1e-6f);
}

// ---------------------------------------------------------------------------
// Kernel B: entmax1.5 via bisection + radix-select top-k + exact refinement
// ---------------------------------------------------------------------------
#define EPS_W 5e-4f
#define MAXC 64
#define SMEM_B ((4*4096 + 32*256)*4)

__global__ __launch_bounds__(1024, 1)
void kernelB(const float* __restrict__ attn, const float* __restrict__ emb,
             const float* __restrict__ gamma_, const float* __restrict__ beta_,
             const float* __restrict__ b2, float* __restrict__ out)
{
    extern __shared__ float sm[];
    float* s_scores = sm;             // 4096
    float* s_attn   = sm + 4096;      // 4096
    float* s_cum    = sm + 8192;      // 4096 (pert)
    float* s_g      = sm + 12288;     // 4096 (g staging for TV)
    float* s_xn     = sm + 16384;     // [32 warps][256]
    __shared__ float red[32], red2[32], red3[32];
    __shared__ float sh_mx, sh_teff, sh_tau, sh_thr, sh_S;
    __shared__ int sh_above, sh_ncand;
    __shared__ int hist[256];
    __shared__ uint32_t sh_prefix;
    __shared__ int sh_remain;
    __shared__ int cand_idx[MAXC];
    __shared__ float cand_pert[MAXC];
    __shared__ int cand_sel[MAXC];

    const int row = blockIdx.x;
    const int tid = threadIdx.x;
    const int lane = tid & 31, wid = tid >> 5;
    const int p0 = tid * 4;

    // ---- load + t_eff + row max
    float tf_ = 0.f, mx = -3.402823466e38f;
    for (int t = tid; t < TT; t += 1024) {
        float s = g_scores[row*TT + t];
        float a = attn[row*TT + t];
        s_scores[t] = s; s_attn[t] = a;
        tf_ += a; mx = fmaxf(mx, s);
    }
    for (int o = 16; o; o >>= 1) {
        tf_ += __shfl_xor_sync(0xffffffffu, tf_, o);
        mx = fmaxf(mx, __shfl_xor_sync(0xffffffffu, mx, o));
    }
    if (lane == 0) { red[wid] = tf_; red2[wid] = mx; }
    __syncthreads();
    if (tid == 0) {
        float a = 0.f, b = -3.402823466e38f;
        for (int w = 0; w < 32; w++) { a += red[w]; b = fmaxf(b, red2[w]); }
        sh_teff = a; sh_mx = b;
        sh_above = 0; sh_ncand = 0;
    }
    __syncthreads();
    mx = sh_mx;

    // ---- entmax tau via bisection on f(tau) = sum max(x-tau,0)^2 (dec.)
    float xr[4];
#pragma unroll
    for (int j = 0; j < 4; ++j) xr[j] = (s_scores[p0+j] - mx) * 0.5f;

    float lo = -1.0f, hi = 0.0f;
    for (int it = 0; it < 48; ++it) {
        float tau = 0.5f*(lo + hi);
        float ssum = 0.f;
#pragma unroll
        for (int j = 0; j < 4; ++j) {
            float d = fmaxf(xr[j] - tau, 0.f);
            ssum += d*d;
        }
        for (int o = 16; o; o >>= 1) ssum += __shfl_xor_sync(0xffffffffu, ssum, o);
        if (lane == 0) red[wid] = ssum;
        __syncthreads();
        if (tid == 0) {
            float a = 0.f;
            for (int w = 0; w < 32; w++) a += red[w];
            sh_S = a;
        }
        __syncthreads();
        if (sh_S > 1.f) lo = tau; else hi = tau;
    }
    // support stats over {x > tau_b}
    {
        float taub = 0.5f*(lo + hi);
        float c = 0.f, S1 = 0.f, S2 = 0.f;
#pragma unroll
        for (int j = 0; j < 4; ++j) {
            if (xr[j] > taub) { c += 1.f; S1 += xr[j]; S2 += xr[j]*xr[j]; }
        }
        for (int o = 16; o; o >>= 1) {
            c  += __shfl_xor_sync(0xffffffffu, c, o);
            S1 += __shfl_xor_sync(0xffffffffu, S1, o);
            S2 += __shfl_xor_sync(0xffffffffu, S2, o);
        }
        if (lane == 0) { red[wid] = c; red2[wid] = S1; red3[wid] = S2; }
        __syncthreads();
        if (tid == 0) {
            float cc = 0.f, a1 = 0.f, a2 = 0.f;
            for (int w = 0; w < 32; w++) { cc += red[w]; a1 += red2[w]; a2 += red3[w]; }
            float rho = fmaxf(cc, 1.f);
            float mean = a1 / rho;
            float msq  = a2 / rho;
            float ssv  = rho * (msq - mean*mean);
            float delta = (1.f - ssv) / rho;
            sh_tau = mean - sqrtf(fmaxf(delta, 0.f));
        }
        __syncthreads();
    }
    const float taustar = sh_tau;

    // ---- z output
#pragma unroll
    for (int j = 0; j < 4; ++j) {
        float dd = fmaxf(xr[j] - taustar, 0.f);
        out[row*TT + p0 + j] = dd*dd*s_attn[p0+j];
    }

    // ---- gumbel-perturbed scores (+ radix keys in registers)
    uint32_t ur[4];
#pragma unroll
    for (int j = 0; j < 4; ++j) {
        int t = p0 + j;
        float gum = gumbel_of((uint32_t)(row*TT + t));
        float pert = s_scores[t] * s_attn[t] + gum;
        s_cum[t] = pert;
        uint32_t b = __float_as_uint(pert);
        ur[j] = (pert != pert) ? 0u
              : (b ^ ((b >> 31) ? 0xFFFFFFFFu : 0x80000000u));  // order-preserving
    }

    const float teff = sh_teff;
    float kf = rintf(0.3f * teff);
    kf = fminf(fmaxf(kf, 1.f), fmaxf(teff, 1.f));
    const int ki = (int)kf;

    // ---- radix select: exact ki-th largest pert (MSB-first, 8 bits/round)
    if (tid == 0) { sh_prefix = 0u; sh_remain = ki; }
    __syncthreads();
    for (int sha = 24; sha >= 0; sha -= 8) {
        if (tid < 256) hist[tid] = 0;
        __syncthreads();
        uint32_t pref = sh_prefix;
#pragma unroll
        for (int j = 0; j < 4; ++j) {
            uint32_t u = ur[j];
            bool match = (sha == 24) || ((u >> (sha + 8)) == pref);
            if (match) atomicAdd(&hist[(u >> sha) & 255], 1);
        }
        __syncthreads();
        if (wid == 0) {
            int b0 = 255 - lane*8;    // lane 0 covers highest bins
            int cnt[8];
            int s = 0;
#pragma unroll
            for (int i = 0; i < 8; i++) { cnt[i] = hist[b0 - i]; s += cnt[i]; }
            int pre = s;
            for (int o = 1; o < 32; o <<= 1) {
                int n = __shfl_up_sync(0xffffffffu, pre, o);
                if (lane >= o) pre += n;
            }
            int excl = pre - s;       // count in bins above this lane's group
            int rem = sh_remain;
            if (excl < rem && rem <= excl + s) {
                int acc = excl;
#pragma unroll
                for (int i = 0; i < 8; i++) {
                    if (acc + cnt[i] >= rem) {
                        uint32_t oldp = sh_prefix;
                        sh_prefix = (oldp << 8) | (uint32_t)(b0 - i);
                        sh_remain = rem - acc;
                        break;
                    }
                    acc += cnt[i];
                }
            }
        }
        __syncthreads();
    }
    if (tid == 0) {
        uint32_t su = sh_prefix;
        uint32_t tb = (su & 0x80000000u) ? (su ^ 0x80000000u) : ~su;
        sh_thr = __uint_as_float(tb);
    }
    __syncthreads();
    const float thr = sh_thr;
    const float hiW = thr + EPS_W, loW = thr - EPS_W;

    // ---- classification counts + candidate gather
    {
        int my_above = 0;
#pragma unroll
        for (int j = 0; j < 4; ++j) {
            int t = p0 + j;
            float p = s_cum[t];
            if (p > hiW) my_above++;
            else if (p >= loW) {
                int pos = atomicAdd(&sh_ncand, 1);
                if (pos < MAXC) cand_idx[pos] = t;
            }
        }
        for (int o = 16; o; o >>= 1) my_above += __shfl_xor_sync(0xffffffffu, my_above, o);
        if (lane == 0) atomicAdd(&sh_above, my_above);
    }
    __syncthreads();
    const int ncand = sh_ncand;
    const bool refine = (ncand <= MAXC);

    // ---- exact recompute of candidate perts (warp per candidate)
    if (refine) {
        const float b2v = b2[0];
        for (int c = wid; c < ncand; c += 32) {
            int t = cand_idx[c];
            float ex;
            if (s_attn[t] == 0.f) {
                ex = s_cum[t];
            } else {
                const float4* e4 = (const float4*)(emb + ((size_t)row*TT + t)*DD);
                float4 va = e4[lane*2], vb = e4[lane*2+1];
                float s  = va.x+va.y+va.z+va.w+vb.x+vb.y+vb.z+vb.w;
                float s2 = va.x*va.x+va.y*va.y+va.z*va.z+va.w*va.w
                         + vb.x*vb.x+vb.y*vb.y+vb.z*vb.z+vb.w*vb.w;
#pragma unroll
                for (int o = 16; o; o >>= 1) {
                    s  += __shfl_xor_sync(0xffffffffu, s, o);
                    s2 += __shfl_xor_sync(0xffffffffu, s2, o);
                }
                float mu = s * (1.f/256.f);
                float rstd = rsqrtf(s2 * (1.f/256.f) - mu*mu + 1e-5f);
                float xv[8] = {va.x,va.y,va.z,va.w,vb.x,vb.y,vb.z,vb.w};
                float* xw = s_xn + wid*256 + lane*8;
#pragma unroll
                for (int p = 0; p < 8; ++p) {
                    int d = lane*8 + p;
                    xw[p] = (xv[p] - mu) * rstd * gamma_[d] + beta_[d];
                }
                __syncwarp();
                float sc = 0.f;
                for (int h = lane; h < HH; h += 32) {
                    const float4* wr = (const float4*)(g_w1t32 + (size_t)h*DD);
                    const float4* xq = (const float4*)(s_xn + wid*256);
                    float dot = 0.f;
#pragma unroll 8
                    for (int u = 0; u < 64; ++u) {
                        float4 a = wr[u], bq = xq[u];
                        dot += a.x*bq.x + a.y*bq.y + a.z*bq.z + a.w*bq.w;
                    }
                    float v = dot + g_b1p[h];
                    sc += gelu_w2(v, g_w2p[h]);
                }
#pragma unroll
                for (int o = 16; o; o >>= 1) sc += __shfl_xor_sync(0xffffffffu, sc, o);
                ex = sc + b2v + gumbel_of((uint32_t)(row*TT + t));
                __syncwarp();
            }
            if (lane == 0) cand_pert[c] = ex;
        }
    }
    __syncthreads();

    if (refine && tid == 0) {
        int need = ki - sh_above;
        for (int c = 0; c < ncand; ++c) {
            int rank = 0;
            float pc = cand_pert[c];
            for (int c2 = 0; c2 < ncand; ++c2)
                if (cand_pert[c2] > pc) rank++;
            cand_sel[c] = (rank < need) ? 1 : 0;
        }
    }
    __syncthreads();

    // ---- g output
#pragma unroll
    for (int j = 0; j < 4; ++j) {
        int t = p0 + j;
        float p = s_cum[t];
        float a0 = s_attn[t];
        float gv;
        if (refine) {
            if (p > hiW) gv = a0;
            else if (p >= loW) {
                gv = 0.f;
                for (int c = 0; c < ncand; ++c)
                    if (cand_idx[c] == t) { gv = cand_sel[c] ? a0 : 0.f; break; }
            } else gv = 0.f;
        } else {
            gv = (p >= thr) ? a0 : 0.f;
        }
        out[BT + row*TT + t] = gv;
        s_g[t] = gv;
    }
    __syncthreads();

    // ---- TV
    float num = 0.f, den = 0.f;
    for (int t = tid; t < TT - 1; t += 1024) {
        float valid = s_attn[t] * s_attn[t+1];
        num += fabsf(s_g[t+1] - s_g[t]) * valid;
        den += valid;
    }
    for (int o = 16; o; o >>= 1) {
        num += __shfl_xor_sync(0xffffffffu, num, o);
        den += __shfl_xor_sync(0xffffffffu, den, o);
    }
    if (lane == 0) { red[wid] = num; red2[wid] = den; }
    __syncthreads();
    if (tid == 0) {
        float a = 0.f, b = 0.f;
        for (int w = 0; w < 32; w++) { a += red[w]; b += red2[w]; }
        g_tv[row] = a / fmaxf(b, 1.f);
    }
}

__global__ void kernelC(float* __restrict__ out)
{
    __shared__ float r[64];
    r[threadIdx.x] = g_tv[threadIdx.x];
    __syncthreads();
    if (threadIdx.x == 0) {
        float s = 0.f;
        for (int i = 0; i < 64; i++) s += r[i];
        out[2*BT] = 0.1f * (s / 64.f);
    }
}

extern "C" void kernel_launch(void* const* d_in, const int* in_sizes, int n_in,
                              void* d_out, int out_size)
{
    const float* emb   = (const float*)d_in[0];
    const float* attn  = (const float*)d_in[1];
    const float* gamma = (const float*)d_in[2];
    const float* beta  = (const float*)d_in[3];
    const float* W1    = (const float*)d_in[4];
    const float* b1    = (const float*)d_in[5];
    const float* W2    = (const float*)d_in[6];
    const float* b2    = (const float*)d_in[7];
    float* out = (float*)d_out;

    cudaFuncSetAttribute(kernelA, cudaFuncAttributeMaxDynamicSharedMemorySize, SMEM_A_TOT);
    cudaFuncSetAttribute(kernelB, cudaFuncAttributeMaxDynamicSharedMemorySize, SMEM_B);

    kernelW<<<NP, 256>>>(W1, b1, W2);
    kernelA<<<BT/64, 256, SMEM_A_TOT>>>(emb, attn, gamma, beta, b2);
    kernelB<<<BB, 1024, SMEM_B>>>(attn, emb, gamma, beta, b2, out);
    kernelC<<<1, 64>>>(out);
}